// round 1
// baseline (speedup 1.0000x reference)
#include <cuda_runtime.h>
#include <math.h>
#include <stdint.h>

// Problem constants
#define Sx   256
#define Dx   128
#define Hx   8
#define DKx  16
#define NKx  16
#define BSx  4
#define NEGV (-1e32f)

// ---------------- scratch (device globals; no allocation allowed) ----------------
__device__ float d_Q1[BSx * Sx * Dx];            // block1 Q (== K, kq_same)
__device__ float d_V1[BSx * Sx * Dx];            // block1 V
__device__ float d_cat1[BSx * Sx * Dx];          // block1 attn concat
__device__ float d_p[BSx * Sx * Dx];             // block1 layer output
__device__ float d_q4[NKx * Dx];                 // block4 Q (per knowledge vector)
__device__ float d_k4[BSx * Sx * Dx];            // block4 K
__device__ float d_v4[BSx * Sx * Dx];            // block4 V
__device__ float d_sc4[BSx * NKx * Hx * Sx];     // block4 base score rows
__device__ float d_cat4[BSx * NKx * Sx * Dx];    // block4 attn concat
__device__ float d_WT[7][Dx * Dx];               // transposed weights

// ---------------- helpers ----------------
__device__ __forceinline__ float warp_max(float v) {
#pragma unroll
    for (int o = 16; o; o >>= 1) v = fmaxf(v, __shfl_xor_sync(0xffffffffu, v, o));
    return v;
}
__device__ __forceinline__ float warp_sum(float v) {
#pragma unroll
    for (int o = 16; o; o >>= 1) v += __shfl_xor_sync(0xffffffffu, v, o);
    return v;
}
__device__ __forceinline__ float block_sum128(float v, float* red) {
    v = warp_sum(v);
    int w = threadIdx.x >> 5;
    __syncthreads();
    if ((threadIdx.x & 31) == 0) red[w] = v;
    __syncthreads();
    return red[0] + red[1] + red[2] + red[3];
}

// ---------------- 128x128 transpose ----------------
__global__ void transpose128(const float* __restrict__ W, float* __restrict__ Wt) {
    __shared__ float t[16][17];
    int bx = blockIdx.x * 16, by = blockIdx.y * 16;
    int x = threadIdx.x, y = threadIdx.y;
    t[y][x] = W[(by + y) * Dx + bx + x];
    __syncthreads();
    Wt[(bx + y) * Dx + by + x] = t[x][y];
}

// ---------------- C[row, :] = A[row, :] @ W^T + b  (Wt pre-transposed) ----------------
__global__ void gemm_bias_t(const float* __restrict__ A, const float* __restrict__ Wt,
                            const float* __restrict__ bias, float* __restrict__ C) {
    __shared__ float xs[Dx];
    int row = blockIdx.x, o = threadIdx.x;
    xs[o] = A[(size_t)row * Dx + o];
    __syncthreads();
    float acc = bias[o];
#pragma unroll 16
    for (int i = 0; i < Dx; i++) acc = fmaf(xs[i], Wt[i * Dx + o], acc);
    C[(size_t)row * Dx + o] = acc;
}

// ---------------- block1 attention: warp-per-row ----------------
// grid (Sx/8, Hx, BSx), 256 threads. K == Q (kq_same).
__global__ void attn1_kernel(const float* __restrict__ QK, const float* __restrict__ Vg,
                             const float* __restrict__ gamma,
                             float* __restrict__ q_scores, float* __restrict__ cat1) {
    __shared__ float Kd[DKx * Sx];   // [d][j] : conflict-free lane-varying-j reads
    __shared__ float Vsh[Sx * DKx];  // [j][d]
    __shared__ float Psh[8][Sx];
    const int b = blockIdx.z, h = blockIdx.y;
    const int tid = threadIdx.x, lane = tid & 31, warp = tid >> 5;

    // Load K: thread t owns row t, scattered STS (conflict-free across lanes)
    {
        const float* base = QK + ((size_t)b * Sx) * Dx + h * DKx;
        const float4* r = (const float4*)(base + (size_t)tid * Dx);
        float4 a0 = r[0], a1 = r[1], a2 = r[2], a3 = r[3];
        Kd[0*Sx+tid]=a0.x; Kd[1*Sx+tid]=a0.y; Kd[2*Sx+tid]=a0.z; Kd[3*Sx+tid]=a0.w;
        Kd[4*Sx+tid]=a1.x; Kd[5*Sx+tid]=a1.y; Kd[6*Sx+tid]=a1.z; Kd[7*Sx+tid]=a1.w;
        Kd[8*Sx+tid]=a2.x; Kd[9*Sx+tid]=a2.y; Kd[10*Sx+tid]=a2.z; Kd[11*Sx+tid]=a2.w;
        Kd[12*Sx+tid]=a3.x; Kd[13*Sx+tid]=a3.y; Kd[14*Sx+tid]=a3.z; Kd[15*Sx+tid]=a3.w;
    }
    {
        const float* base = Vg + ((size_t)b * Sx) * Dx + h * DKx;
        for (int idx = tid; idx < Sx * DKx; idx += 256) {
            int j = idx >> 4, d = idx & 15;
            Vsh[idx] = base[(size_t)j * Dx + d];
        }
    }
    __syncthreads();

    const float g = -fabsf(gamma[h]);
    const int i = blockIdx.x * 8 + warp;

    float q[16];
#pragma unroll
    for (int d = 0; d < 16; d++) q[d] = Kd[d * Sx + i];

    float sc[8], ex[8];
    float mx = NEGV;
#pragma unroll
    for (int u = 0; u < 8; u++) {
        int j = u * 32 + lane;
        float s = 0.f;
#pragma unroll
        for (int d = 0; d < 16; d++) s = fmaf(q[d], Kd[d * Sx + j], s);
        s *= 0.25f;
        sc[u] = s;
        float m = (j <= i) ? s : NEGV;
        ex[u] = m;
        mx = fmaxf(mx, m);
    }
    mx = warp_max(mx);
    float sum = 0.f;
#pragma unroll
    for (int u = 0; u < 8; u++) { ex[u] = __expf(ex[u] - mx); sum += ex[u]; }
    sum = warp_sum(sum);
    float inv = 1.0f / sum;

    // inclusive cumsum over j of normalized s_
    float cum[8]; float carry = 0.f;
#pragma unroll
    for (int u = 0; u < 8; u++) {
        float x = ex[u] * inv;
#pragma unroll
        for (int off = 1; off < 32; off <<= 1) {
            float nv = __shfl_up_sync(0xffffffffu, x, off);
            if (lane >= off) x += nv;
        }
        float seg = __shfl_sync(0xffffffffu, x, 31);
        cum[u] = x + carry;
        carry += seg;
    }
    const float total = carry;

    float mx2 = NEGV;
#pragma unroll
    for (int u = 0; u < 8; u++) {
        int j = u * 32 + lane;
        float pos = fabsf((float)(j - i));
        float dist = sqrtf(fmaxf((total - cum[u]) * pos, 0.f));
        float eff = __expf(g * dist);
        eff = fminf(fmaxf(eff, 1e-5f), 1e5f);
        float s2 = sc[u] * eff;
        s2 = (j <= i) ? s2 : NEGV;
        ex[u] = s2;
        mx2 = fmaxf(mx2, s2);
    }
    mx2 = warp_max(mx2);
    float sum2 = 0.f;
#pragma unroll
    for (int u = 0; u < 8; u++) { ex[u] = __expf(ex[u] - mx2); sum2 += ex[u]; }
    sum2 = warp_sum(sum2);
    float inv2 = 1.0f / sum2;

    float* qs = q_scores + (((size_t)(b * Hx + h)) * Sx + i) * Sx;
#pragma unroll
    for (int u = 0; u < 8; u++) {
        int j = u * 32 + lane;
        float p = (j <= i) ? ex[u] * inv2 : 0.f;
        Psh[warp][j] = p;
        qs[j] = p;
    }
    __syncwarp();

    // out = P @ V ; half-warp even/odd j split keeps Vsh conflict-free
    float acc = 0.f;
    int d0 = lane & 15, half = lane >> 4;
    for (int jj = 0; jj < 128; jj++) {
        int j = jj * 2 + half;
        acc = fmaf(Psh[warp][j], Vsh[j * DKx + d0], acc);
    }
    acc += __shfl_down_sync(0xffffffffu, acc, 16);
    if (lane < 16)
        cat1[(((size_t)b * Sx) + i) * Dx + h * DKx + lane] = acc;
}

// ---------------- block4 base scores (i-independent) ----------------
// grid (BSx*NKx, Hx), 256 threads (one j each)
__global__ void sc4_kernel(const float* __restrict__ Q4, const float* __restrict__ K4,
                           float* __restrict__ SC) {
    int bn = blockIdx.x, h = blockIdx.y;
    int b = bn >> 4, n = bn & 15;
    int j = threadIdx.x;
    const float* q = Q4 + n * Dx + h * DKx;
    const float* k = K4 + (((size_t)b * Sx) + j) * Dx + h * DKx;
    float s = 0.f;
#pragma unroll
    for (int d = 0; d < 16; d++) s = fmaf(q[d], k[d], s);
    SC[((size_t)bn * Hx + h) * Sx + j] = s * 0.25f;
}

// ---------------- block4 attention: warp-per-row, 2 rows per warp ----------------
// grid (Sx/16, Hx, BSx*NKx), 256 threads. Strict mask (j < i), maxout=true.
__global__ void attn4_kernel(const float* __restrict__ SC, const float* __restrict__ V4,
                             const float* __restrict__ gamma,
                             float* __restrict__ k_scores, float* __restrict__ cat4) {
    __shared__ float scsh[Sx];
    __shared__ float Vsh[Sx * DKx];   // [j][d]
    __shared__ float Psh[8][2][Sx];
    const int bn = blockIdx.z, h = blockIdx.y;
    const int b = bn >> 4;
    const int n = bn & 15;
    const int tid = threadIdx.x, lane = tid & 31, warp = tid >> 5;

    {
        const float* base = V4 + ((size_t)b * Sx) * Dx + h * DKx;
        for (int idx = tid; idx < Sx * DKx; idx += 256) {
            int j = idx >> 4, d = idx & 15;
            Vsh[idx] = base[(size_t)j * Dx + d];
        }
        scsh[tid] = SC[((size_t)bn * Hx + h) * Sx + tid];
    }
    __syncthreads();

    const float g = -fabsf(gamma[h]);
    float sc[8];
#pragma unroll
    for (int u = 0; u < 8; u++) sc[u] = scsh[u * 32 + lane];

    const int i_base = blockIdx.x * 16 + warp * 2;

    for (int r = 0; r < 2; r++) {
        const int i = i_base + r;
        float ex[8];
        float mx = NEGV;
#pragma unroll
        for (int u = 0; u < 8; u++) {
            int j = u * 32 + lane;
            float m = (j < i) ? sc[u] : NEGV;
            ex[u] = m;
            mx = fmaxf(mx, m);
        }
        mx = warp_max(mx);
        float sum = 0.f;
#pragma unroll
        for (int u = 0; u < 8; u++) { ex[u] = __expf(ex[u] - mx); sum += ex[u]; }
        sum = warp_sum(sum);
        float inv = 1.0f / sum;

        float cum[8]; float carry = 0.f;
#pragma unroll
        for (int u = 0; u < 8; u++) {
            float x = ex[u] * inv;
#pragma unroll
            for (int off = 1; off < 32; off <<= 1) {
                float nv = __shfl_up_sync(0xffffffffu, x, off);
                if (lane >= off) x += nv;
            }
            float seg = __shfl_sync(0xffffffffu, x, 31);
            cum[u] = x + carry;
            carry += seg;
        }
        const float total = carry;

        float mx2 = NEGV;
#pragma unroll
        for (int u = 0; u < 8; u++) {
            int j = u * 32 + lane;
            float pos = fabsf((float)(j - i));
            float dist = sqrtf(fmaxf((total - cum[u]) * pos, 0.f));
            float eff = __expf(g * dist);
            eff = fminf(fmaxf(eff, 1e-5f), 1e5f);
            float s2 = sc[u] * eff;
            s2 = (j < i) ? s2 : NEGV;
            ex[u] = s2;
            mx2 = fmaxf(mx2, s2);
        }
        mx2 = warp_max(mx2);
        float sum2 = 0.f;
#pragma unroll
        for (int u = 0; u < 8; u++) { ex[u] = __expf(ex[u] - mx2); sum2 += ex[u]; }
        sum2 = warp_sum(sum2);
        float inv2 = 1.0f / sum2;

        // zero outside mask; maxout
        float pmax = 0.f;
#pragma unroll
        for (int u = 0; u < 8; u++) {
            int j = u * 32 + lane;
            float p = (j < i) ? ex[u] * inv2 : 0.f;
            ex[u] = p;
            pmax = fmaxf(pmax, p);
        }
        pmax = warp_max(pmax);
        float scale = fminf(1.0f / pmax, 5.0f);   // pmax==0 -> inf -> 5

        float* ks = k_scores + (((((size_t)(b * Hx + h)) * Sx + i) * NKx + n)) * Sx;
#pragma unroll
        for (int u = 0; u < 8; u++) {
            int j = u * 32 + lane;
            float p = ex[u] * scale;
            Psh[warp][r][j] = p;
            ks[j] = p;
        }
    }
    __syncwarp();

    // out for both rows, V read once
    float acc0 = 0.f, acc1 = 0.f;
    int d0 = lane & 15, half = lane >> 4;
    for (int jj = 0; jj < 128; jj++) {
        int j = jj * 2 + half;
        float v = Vsh[j * DKx + d0];
        acc0 = fmaf(Psh[warp][0][j], v, acc0);
        acc1 = fmaf(Psh[warp][1][j], v, acc1);
    }
    acc0 += __shfl_down_sync(0xffffffffu, acc0, 16);
    acc1 += __shfl_down_sync(0xffffffffu, acc1, 16);
    if (lane < 16) {
        cat4[(((size_t)bn * Sx) + i_base + 0) * Dx + h * DKx + lane] = acc0;
        cat4[(((size_t)bn * Sx) + i_base + 1) * Dx + h * DKx + lane] = acc1;
    }
}

// ---------------- O-proj + residual + LayerNorm (block1) ----------------
__global__ void oproj_ln1_kernel(const float* __restrict__ X, const float* __restrict__ WoT,
                                 const float* __restrict__ bo, const float* __restrict__ res,
                                 const float* __restrict__ g, const float* __restrict__ be,
                                 float* __restrict__ out) {
    __shared__ float xs[Dx];
    __shared__ float red[4];
    int row = blockIdx.x, o = threadIdx.x;
    xs[o] = X[(size_t)row * Dx + o];
    __syncthreads();
    float acc = bo[o];
#pragma unroll 16
    for (int i = 0; i < Dx; i++) acc = fmaf(xs[i], WoT[i * Dx + o], acc);
    float hv = res[(size_t)row * Dx + o] + acc;
    float m = block_sum128(hv, red) * (1.f / 128.f);
    float dv = hv - m;
    float var = block_sum128(dv * dv, red) * (1.f / 128.f);
    out[(size_t)row * Dx + o] = dv * rsqrtf(var + 1e-5f) * g[o] + be[o];
}

// ---------------- O-proj + residual(know) + LayerNorm + transpose-out (block4) ----------------
__global__ void oproj_ln4_kernel(const float* __restrict__ X, const float* __restrict__ WoT,
                                 const float* __restrict__ bo, const float* __restrict__ know,
                                 const float* __restrict__ g, const float* __restrict__ be,
                                 float* __restrict__ z) {
    __shared__ float xs[Dx];
    __shared__ float red[4];
    int row = blockIdx.x, o = threadIdx.x;        // row in (b*NK+n)*S + s order
    int bn = row >> 8, s = row & 255;
    int b = bn >> 4, n = bn & 15;
    xs[o] = X[(size_t)row * Dx + o];
    __syncthreads();
    float acc = bo[o];
#pragma unroll 16
    for (int i = 0; i < Dx; i++) acc = fmaf(xs[i], WoT[i * Dx + o], acc);
    float hv = know[n * Dx + o] + acc;
    float m = block_sum128(hv, red) * (1.f / 128.f);
    float dv = hv - m;
    float var = block_sum128(dv * dv, red) * (1.f / 128.f);
    z[((((size_t)b * Sx) + s) * NKx + n) * Dx + o] = dv * rsqrtf(var + 1e-5f) * g[o] + be[o];
}

// ---------------- launch ----------------
extern "C" void kernel_launch(void* const* d_in, const int* in_sizes, int n_in,
                              void* d_out, int out_size) {
    (void)in_sizes; (void)n_in; (void)out_size;
    const float* q_emb   = (const float*)d_in[0];
    const float* s_emb   = (const float*)d_in[1];
    // d_in[2] = lens (unused in eval math)
    const float* b1_Wq   = (const float*)d_in[3];
    const float* b1_bq   = (const float*)d_in[4];
    const float* b1_Wv   = (const float*)d_in[5];
    const float* b1_bv   = (const float*)d_in[6];
    const float* b1_Wo   = (const float*)d_in[7];
    const float* b1_bo   = (const float*)d_in[8];
    const float* b1_gam  = (const float*)d_in[9];
    const float* b1_lng  = (const float*)d_in[10];
    const float* b1_lnb  = (const float*)d_in[11];
    const float* b4_Wq   = (const float*)d_in[12];
    const float* b4_bq   = (const float*)d_in[13];
    const float* b4_Wk   = (const float*)d_in[14];
    const float* b4_bk   = (const float*)d_in[15];
    const float* b4_Wv   = (const float*)d_in[16];
    const float* b4_bv   = (const float*)d_in[17];
    const float* b4_Wo   = (const float*)d_in[18];
    const float* b4_bo   = (const float*)d_in[19];
    const float* b4_gam  = (const float*)d_in[20];
    const float* b4_lng  = (const float*)d_in[21];
    const float* b4_lnb  = (const float*)d_in[22];
    const float* know    = (const float*)d_in[23];

    float* z_out  = (float*)d_out;
    float* qs_out = z_out + (size_t)BSx * Sx * NKx * Dx;        // + 2,097,152
    float* ks_out = qs_out + (size_t)BSx * Hx * Sx * Sx;        // + 2,097,152

    float *Q1, *V1, *cat1, *p, *q4, *k4, *v4, *sc4, *cat4, *WT;
    cudaGetSymbolAddress((void**)&Q1,   d_Q1);
    cudaGetSymbolAddress((void**)&V1,   d_V1);
    cudaGetSymbolAddress((void**)&cat1, d_cat1);
    cudaGetSymbolAddress((void**)&p,    d_p);
    cudaGetSymbolAddress((void**)&q4,   d_q4);
    cudaGetSymbolAddress((void**)&k4,   d_k4);
    cudaGetSymbolAddress((void**)&v4,   d_v4);
    cudaGetSymbolAddress((void**)&sc4,  d_sc4);
    cudaGetSymbolAddress((void**)&cat4, d_cat4);
    cudaGetSymbolAddress((void**)&WT,   d_WT);
    float* WT_1q = WT + 0 * Dx * Dx;
    float* WT_1v = WT + 1 * Dx * Dx;
    float* WT_1o = WT + 2 * Dx * Dx;
    float* WT_4q = WT + 3 * Dx * Dx;
    float* WT_4k = WT + 4 * Dx * Dx;
    float* WT_4v = WT + 5 * Dx * Dx;
    float* WT_4o = WT + 6 * Dx * Dx;

    dim3 tb(16, 16), tg(8, 8);
    transpose128<<<tg, tb>>>(b1_Wq, WT_1q);
    transpose128<<<tg, tb>>>(b1_Wv, WT_1v);
    transpose128<<<tg, tb>>>(b1_Wo, WT_1o);
    transpose128<<<tg, tb>>>(b4_Wq, WT_4q);
    transpose128<<<tg, tb>>>(b4_Wk, WT_4k);
    transpose128<<<tg, tb>>>(b4_Wv, WT_4v);
    transpose128<<<tg, tb>>>(b4_Wo, WT_4o);

    const int M1 = BSx * Sx;              // 1024
    gemm_bias_t<<<M1, Dx>>>(q_emb, WT_1q, b1_bq, Q1);
    gemm_bias_t<<<M1, Dx>>>(s_emb, WT_1v, b1_bv, V1);

    attn1_kernel<<<dim3(Sx / 8, Hx, BSx), 256>>>(Q1, V1, b1_gam, qs_out, cat1);
    oproj_ln1_kernel<<<M1, Dx>>>(cat1, WT_1o, b1_bo, q_emb, b1_lng, b1_lnb, p);

    gemm_bias_t<<<NKx, Dx>>>(know, WT_4q, b4_bq, q4);
    gemm_bias_t<<<M1, Dx>>>(q_emb, WT_4k, b4_bk, k4);
    gemm_bias_t<<<M1, Dx>>>(p,     WT_4v, b4_bv, v4);

    sc4_kernel<<<dim3(BSx * NKx, Hx), 256>>>(q4, k4, sc4);
    attn4_kernel<<<dim3(Sx / 16, Hx, BSx * NKx), 256>>>(sc4, v4, b4_gam, ks_out, cat4);

    oproj_ln4_kernel<<<BSx * NKx * Sx, Dx>>>(cat4, WT_4o, b4_bo, know, b4_lng, b4_lnb, z_out);
}

// round 2
// speedup vs baseline: 1.2736x; 1.2736x over previous
#include <cuda_runtime.h>
#include <math.h>
#include <stdint.h>

#define Sx   256
#define Dx   128
#define Hx   8
#define DKx  16
#define NKx  16
#define BSx  4
#define NEGV (-1e32f)

// ---------------- scratch ----------------
__device__ float d_Q1[BSx * Sx * Dx];
__device__ float d_V1[BSx * Sx * Dx];
__device__ float d_cat1[BSx * Sx * Dx];
__device__ float d_p[BSx * Sx * Dx];
__device__ float d_q4[NKx * Dx];
__device__ float d_k4[BSx * Sx * Dx];
__device__ float d_v4[BSx * Sx * Dx];
__device__ float d_cat4[BSx * NKx * Sx * Dx];
__device__ float d_WT[7][Dx * Dx];

// ---------------- helpers ----------------
__device__ __forceinline__ float warp_max(float v) {
#pragma unroll
    for (int o = 16; o; o >>= 1) v = fmaxf(v, __shfl_xor_sync(0xffffffffu, v, o));
    return v;
}
__device__ __forceinline__ float warp_sum(float v) {
#pragma unroll
    for (int o = 16; o; o >>= 1) v += __shfl_xor_sync(0xffffffffu, v, o);
    return v;
}
__device__ __forceinline__ float rcp_ap(float x) {
    float r; asm("rcp.approx.f32 %0, %1;" : "=f"(r) : "f"(x)); return r;
}
__device__ __forceinline__ float sqrt_ap(float x) {
    float r; asm("sqrt.approx.f32 %0, %1;" : "=f"(r) : "f"(x)); return r;
}
__device__ __forceinline__ void fma4(float4& a, float x, const float4& w) {
    a.x = fmaf(x, w.x, a.x); a.y = fmaf(x, w.y, a.y);
    a.z = fmaf(x, w.z, a.z); a.w = fmaf(x, w.w, a.w);
}

// ---------------- transpose all 7 weights ----------------
__global__ void transpose_all(const float* __restrict__ s0, const float* __restrict__ s1,
                              const float* __restrict__ s2, const float* __restrict__ s3,
                              const float* __restrict__ s4, const float* __restrict__ s5,
                              const float* __restrict__ s6, float* __restrict__ dst) {
    const float* srcs[7] = {s0, s1, s2, s3, s4, s5, s6};
    __shared__ float t[16][17];
    const float* W = srcs[blockIdx.z];
    float* Wt = dst + (size_t)blockIdx.z * Dx * Dx;
    int bx = blockIdx.x * 16, by = blockIdx.y * 16;
    int x = threadIdx.x, y = threadIdx.y;
    t[y][x] = W[(by + y) * Dx + bx + x];
    __syncthreads();
    Wt[(bx + y) * Dx + by + x] = t[x][y];
}

// ---------------- warp computes 4 rows of A @ Wt + bias ----------------
__device__ __forceinline__ void gemm_warp4(const float* __restrict__ A,
                                           const float* __restrict__ Wt,
                                           int r0, int lane, float4 ar[4]) {
    const float4* W4 = (const float4*)Wt;
    const float4* A4 = (const float4*)A;
    float4 z = {0.f, 0.f, 0.f, 0.f};
#pragma unroll
    for (int r = 0; r < 4; r++) ar[r] = z;
#pragma unroll 4
    for (int c = 0; c < 32; c++) {
        float4 xr[4];
#pragma unroll
        for (int r = 0; r < 4; r++) xr[r] = A4[(size_t)(r0 + r) * 32 + c];
        float4 w[4];
#pragma unroll
        for (int k = 0; k < 4; k++) w[k] = W4[c * 128 + k * 32 + lane];
#pragma unroll
        for (int r = 0; r < 4; r++) {
            fma4(ar[r], xr[r].x, w[0]);
            fma4(ar[r], xr[r].y, w[1]);
            fma4(ar[r], xr[r].z, w[2]);
            fma4(ar[r], xr[r].w, w[3]);
        }
    }
}

// ---------------- batched projections: Q1, V1, K4, Q4 ----------------
__global__ void proj_batch(const float* __restrict__ q_emb, const float* __restrict__ s_emb,
                           const float* __restrict__ know, const float* __restrict__ WT,
                           const float* __restrict__ bq1, const float* __restrict__ bv1,
                           const float* __restrict__ bk4, const float* __restrict__ bq4,
                           float* __restrict__ Q1, float* __restrict__ V1,
                           float* __restrict__ K4, float* __restrict__ Q4) {
    const float* A; const float* Wt; const float* bias; float* C; int M;
    switch (blockIdx.y) {
        case 0:  A = q_emb; Wt = WT + 0 * 16384; bias = bq1; C = Q1; M = 1024; break;
        case 1:  A = s_emb; Wt = WT + 1 * 16384; bias = bv1; C = V1; M = 1024; break;
        case 2:  A = q_emb; Wt = WT + 4 * 16384; bias = bk4; C = K4; M = 1024; break;
        default: A = know;  Wt = WT + 3 * 16384; bias = bq4; C = Q4; M = 16;   break;
    }
    int warp = threadIdx.x >> 5, lane = threadIdx.x & 31;
    int r0 = blockIdx.x * 32 + warp * 4;
    if (r0 >= M) return;
    float4 ar[4];
    gemm_warp4(A, Wt, r0, lane, ar);
    float4 b4 = ((const float4*)bias)[lane];
    float4* C4 = (float4*)C;
#pragma unroll
    for (int r = 0; r < 4; r++) {
        float4 o = {ar[r].x + b4.x, ar[r].y + b4.y, ar[r].z + b4.z, ar[r].w + b4.w};
        C4[(size_t)(r0 + r) * 32 + lane] = o;
    }
}

// ---------------- single projection (v4 = p @ Wv4^T + b) ----------------
__global__ void proj_single(const float* __restrict__ A, const float* __restrict__ Wt,
                            const float* __restrict__ bias, float* __restrict__ C) {
    int warp = threadIdx.x >> 5, lane = threadIdx.x & 31;
    int r0 = blockIdx.x * 32 + warp * 4;
    float4 ar[4];
    gemm_warp4(A, Wt, r0, lane, ar);
    float4 b4 = ((const float4*)bias)[lane];
    float4* C4 = (float4*)C;
#pragma unroll
    for (int r = 0; r < 4; r++) {
        float4 o = {ar[r].x + b4.x, ar[r].y + b4.y, ar[r].z + b4.z, ar[r].w + b4.w};
        C4[(size_t)(r0 + r) * 32 + lane] = o;
    }
}

// ---------------- LN over a float4-per-lane row ----------------
__device__ __forceinline__ float4 ln_row(float4 hv, const float4& g4, const float4& b4) {
    float s = hv.x + hv.y + hv.z + hv.w;
    s = warp_sum(s);
    float mean = s * 0.0078125f;
    float4 dv = {hv.x - mean, hv.y - mean, hv.z - mean, hv.w - mean};
    float vs = dv.x * dv.x + dv.y * dv.y + dv.z * dv.z + dv.w * dv.w;
    vs = warp_sum(vs);
    float rstd = rsqrtf(vs * 0.0078125f + 1e-5f);
    float4 o = {dv.x * rstd * g4.x + b4.x, dv.y * rstd * g4.y + b4.y,
                dv.z * rstd * g4.z + b4.z, dv.w * rstd * g4.w + b4.w};
    return o;
}

// ---------------- O-proj + residual + LN (block1) ----------------
__global__ void oproj_ln1_k(const float* __restrict__ X, const float* __restrict__ WoT,
                            const float* __restrict__ bo, const float* __restrict__ res,
                            const float* __restrict__ lng, const float* __restrict__ lnb,
                            float* __restrict__ out) {
    int warp = threadIdx.x >> 5, lane = threadIdx.x & 31;
    int r0 = blockIdx.x * 32 + warp * 4;
    float4 ar[4];
    gemm_warp4(X, WoT, r0, lane, ar);
    float4 bb = ((const float4*)bo)[lane];
    float4 g4 = ((const float4*)lng)[lane];
    float4 b4 = ((const float4*)lnb)[lane];
    const float4* R4 = (const float4*)res;
    float4* O4 = (float4*)out;
#pragma unroll
    for (int r = 0; r < 4; r++) {
        float4 rv = R4[(size_t)(r0 + r) * 32 + lane];
        float4 hv = {ar[r].x + bb.x + rv.x, ar[r].y + bb.y + rv.y,
                     ar[r].z + bb.z + rv.z, ar[r].w + bb.w + rv.w};
        O4[(size_t)(r0 + r) * 32 + lane] = ln_row(hv, g4, b4);
    }
}

// ---------------- O-proj + residual(know) + LN + scatter (block4) ----------------
__global__ void oproj_ln4_k(const float* __restrict__ X, const float* __restrict__ WoT,
                            const float* __restrict__ bo, const float* __restrict__ know,
                            const float* __restrict__ lng, const float* __restrict__ lnb,
                            float* __restrict__ z) {
    int warp = threadIdx.x >> 5, lane = threadIdx.x & 31;
    int r0 = blockIdx.x * 32 + warp * 4;
    float4 ar[4];
    gemm_warp4(X, WoT, r0, lane, ar);
    float4 bb = ((const float4*)bo)[lane];
    float4 g4 = ((const float4*)lng)[lane];
    float4 b4 = ((const float4*)lnb)[lane];
    const float4* K4p = (const float4*)know;
    float4* Z4 = (float4*)z;
#pragma unroll
    for (int r = 0; r < 4; r++) {
        int row = r0 + r;                 // row = (b*NK+n)*S + s
        int bn = row >> 8, s = row & 255;
        int b = bn >> 4, n = bn & 15;
        float4 rv = K4p[n * 32 + lane];
        float4 hv = {ar[r].x + bb.x + rv.x, ar[r].y + bb.y + rv.y,
                     ar[r].z + bb.z + rv.z, ar[r].w + bb.w + rv.w};
        Z4[(((size_t)(b * Sx + s) * NKx) + n) * 32 + lane] = ln_row(hv, g4, b4);
    }
}

// ---------------- block1 attention: warp-per-row, triangular bounds ----------------
__global__ void attn1_kernel(const float* __restrict__ QK, const float* __restrict__ Vg,
                             const float* __restrict__ gamma,
                             float* __restrict__ q_scores, float* __restrict__ cat1) {
    __shared__ float Kd[DKx * Sx];   // [d][j]
    __shared__ float Vsh[Sx * DKx];  // [j][d]
    __shared__ float Psh[8][Sx];
    const int b = blockIdx.z, h = blockIdx.y;
    const int tid = threadIdx.x, lane = tid & 31, warp = tid >> 5;

    {
        const float* base = QK + ((size_t)b * Sx) * Dx + h * DKx;
        const float4* r = (const float4*)(base + (size_t)tid * Dx);
        float4 a0 = r[0], a1 = r[1], a2 = r[2], a3 = r[3];
        Kd[0*Sx+tid]=a0.x; Kd[1*Sx+tid]=a0.y; Kd[2*Sx+tid]=a0.z; Kd[3*Sx+tid]=a0.w;
        Kd[4*Sx+tid]=a1.x; Kd[5*Sx+tid]=a1.y; Kd[6*Sx+tid]=a1.z; Kd[7*Sx+tid]=a1.w;
        Kd[8*Sx+tid]=a2.x; Kd[9*Sx+tid]=a2.y; Kd[10*Sx+tid]=a2.z; Kd[11*Sx+tid]=a2.w;
        Kd[12*Sx+tid]=a3.x; Kd[13*Sx+tid]=a3.y; Kd[14*Sx+tid]=a3.z; Kd[15*Sx+tid]=a3.w;
    }
    {
        const float* base = Vg + ((size_t)b * Sx) * Dx + h * DKx;
        for (int idx = tid; idx < Sx * DKx; idx += 256) {
            int j = idx >> 4, d = idx & 15;
            Vsh[idx] = base[(size_t)j * Dx + d];
        }
    }
    __syncthreads();

    const float g = -fabsf(gamma[h]);
    const int i = blockIdx.x * 8 + warp;
    const int uMax = i >> 5;

    float q[16];
#pragma unroll
    for (int d = 0; d < 16; d++) q[d] = Kd[d * Sx + i];

    float sc[8], ex[8];
    float mx = NEGV;
#pragma unroll
    for (int u = 0; u < 8; u++) {
        if (u <= uMax) {
            int j = u * 32 + lane;
            float s = 0.f;
#pragma unroll
            for (int d = 0; d < 16; d++) s = fmaf(q[d], Kd[d * Sx + j], s);
            s *= 0.25f;
            sc[u] = s;
            float m = (j <= i) ? s : NEGV;
            ex[u] = m;
            mx = fmaxf(mx, m);
        } else { ex[u] = NEGV; sc[u] = 0.f; }
    }
    mx = warp_max(mx);
    float sum = 0.f;
#pragma unroll
    for (int u = 0; u < 8; u++) if (u <= uMax) { ex[u] = __expf(ex[u] - mx); sum += ex[u]; }
    sum = warp_sum(sum);
    float inv = rcp_ap(sum);

    float cum[8]; float carry = 0.f;
#pragma unroll
    for (int u = 0; u < 8; u++) {
        if (u <= uMax) {
            float x = ex[u] * inv;
#pragma unroll
            for (int off = 1; off < 32; off <<= 1) {
                float nv = __shfl_up_sync(0xffffffffu, x, off);
                if (lane >= off) x += nv;
            }
            float seg = __shfl_sync(0xffffffffu, x, 31);
            cum[u] = x + carry;
            carry += seg;
        } else cum[u] = 0.f;
    }
    const float total = carry;
    const float fi = (float)i;

    float mx2 = NEGV;
#pragma unroll
    for (int u = 0; u < 8; u++) {
        if (u <= uMax) {
            int j = u * 32 + lane;
            float pos = fabsf((float)j - fi);
            float dist = sqrt_ap(fmaxf((total - cum[u]) * pos, 0.f));
            float eff = __expf(g * dist);
            eff = fminf(fmaxf(eff, 1e-5f), 1e5f);
            float s2 = sc[u] * eff;
            s2 = (j <= i) ? s2 : NEGV;
            ex[u] = s2;
            mx2 = fmaxf(mx2, s2);
        }
    }
    mx2 = warp_max(mx2);
    float sum2 = 0.f;
#pragma unroll
    for (int u = 0; u < 8; u++) if (u <= uMax) { ex[u] = __expf(ex[u] - mx2); sum2 += ex[u]; }
    sum2 = warp_sum(sum2);
    float inv2 = rcp_ap(sum2);

    float* qs = q_scores + (((size_t)(b * Hx + h)) * Sx + i) * Sx;
#pragma unroll
    for (int u = 0; u < 8; u++) {
        int j = u * 32 + lane;
        float p = (u <= uMax && j <= i) ? ex[u] * inv2 : 0.f;
        Psh[warp][j] = p;
        qs[j] = p;
    }
    __syncwarp();

    float acc = 0.f;
    int d0 = lane & 15, half = lane >> 4;
    for (int j = half; j <= i; j += 2)
        acc = fmaf(Psh[warp][j], Vsh[j * DKx + d0], acc);
    acc += __shfl_down_sync(0xffffffffu, acc, 16);
    if (lane < 16)
        cat1[(((size_t)b * Sx) + i) * Dx + h * DKx + lane] = acc;
}

// ---------------- block4 attention: scan-free (prefix-sum trick), fused sc ----------------
// grid (64 bn, 8 h), 256 threads, 8 warps; warp handles rows i ≡ warp (mod 8).
__global__ void attn4_kernel(const float* __restrict__ q4g, const float* __restrict__ k4g,
                             const float* __restrict__ v4g, const float* __restrict__ gamma,
                             float* __restrict__ ks_out, float* __restrict__ cat4) {
    __shared__ float Vsh[Sx * DKx];     // 16KB
    __shared__ float scsh[Sx];
    __shared__ float Csh[Sx];
    __shared__ float Psh[8][2][Sx];     // 16KB
    __shared__ float redA[8], redB[8];

    const int bn = blockIdx.x, h = blockIdx.y;
    const int b = bn >> 4, n = bn & 15;
    const int tid = threadIdx.x, lane = tid & 31, warp = tid >> 5;

    {   // V slice
        const float* vb = v4g + ((size_t)b * Sx) * Dx + h * DKx;
        for (int idx = tid; idx < Sx * DKx; idx += 256) {
            int j = idx >> 4, d = idx & 15;
            Vsh[idx] = vb[(size_t)j * Dx + d];
        }
    }
    {   // base score row + block max + prefix sums
        const float* qp = q4g + n * Dx + h * DKx;
        const float* kp = k4g + ((size_t)b * Sx + tid) * Dx + h * DKx;
        float s = 0.f;
#pragma unroll
        for (int d = 0; d < 16; d++) s = fmaf(qp[d], kp[d], s);
        s *= 0.25f;
        scsh[tid] = s;
        float m = warp_max(s);
        if (lane == 0) redA[warp] = m;
        __syncthreads();
        float M = redA[0];
#pragma unroll
        for (int w = 1; w < 8; w++) M = fmaxf(M, redA[w]);
        float e = __expf(s - M);
        float x = e;
#pragma unroll
        for (int off = 1; off < 32; off <<= 1) {
            float nv = __shfl_up_sync(0xffffffffu, x, off);
            if (lane >= off) x += nv;
        }
        if (lane == 31) redB[warp] = x;
        __syncthreads();
        float carry = 0.f;
#pragma unroll
        for (int w = 0; w < 7; w++) if (w < warp) carry += redB[w];
        Csh[tid] = x + carry;
    }
    __syncthreads();

    const float g = -fabsf(gamma[h]);
    float scu[8];
#pragma unroll
    for (int u = 0; u < 8; u++) scu[u] = scsh[u * 32 + lane];

    const int d0 = lane & 15, half = lane >> 4;

    for (int gb = 0; gb < 16; ++gb) {
        const int i1 = warp + 8 * (2 * gb + 1);   // larger row of the pair
        const int nUb = (i1 - 1) >> 5;            // last unit needed for PV

        for (int k = 0; k < 2; ++k) {
            const int i = warp + 8 * (2 * gb + k);
            const int uMax = (i - 1) >> 5;        // -1 when i==0
            float invC = 0.f;
            if (i > 0) invC = rcp_ap(Csh[i - 1]);
            const float fi = (float)i;

            float ex[8];
            float mx = NEGV;
#pragma unroll
            for (int u = 0; u < 8; u++) {
                if (u <= uMax) {
                    int j = u * 32 + lane;
                    float Cu = Csh[j];
                    float t = (1.f - Cu * invC) * fabsf((float)j - fi);
                    float dist = sqrt_ap(fmaxf(t, 0.f));
                    float eff = __expf(g * dist);
                    eff = fminf(fmaxf(eff, 1e-5f), 1e5f);
                    float s2 = scu[u] * eff;
                    s2 = (j < i) ? s2 : NEGV;
                    ex[u] = s2;
                    mx = fmaxf(mx, s2);
                } else ex[u] = NEGV;
            }
            mx = warp_max(mx);
            float sum = 0.f;
#pragma unroll
            for (int u = 0; u < 8; u++)
                if (u <= uMax) { ex[u] = __expf(ex[u] - mx); sum += ex[u]; }
            sum = warp_sum(sum);
            float inv2 = rcp_ap(sum);

            float pmax = 0.f;
#pragma unroll
            for (int u = 0; u < 8; u++) {
                if (u <= uMax) {
                    int j = u * 32 + lane;
                    float pv = (j < i) ? ex[u] * inv2 : 0.f;
                    ex[u] = pv;
                    pmax = fmaxf(pmax, pv);
                } else ex[u] = 0.f;
            }
            pmax = warp_max(pmax);
            float scale = fminf(rcp_ap(pmax), 5.f);

            float* ks = ks_out + ((((size_t)(b * Hx + h) * Sx + i) * NKx + n) << 8);
#pragma unroll
            for (int u = 0; u < 8; u++) {
                int j = u * 32 + lane;
                float pv = ex[u] * scale;
                ks[j] = pv;
                if (u <= nUb) Psh[warp][k][j] = pv;
            }
        }
        __syncwarp();

        float a0 = 0.f, a1 = 0.f;
        for (int j = half; j < i1; j += 2) {
            float v = Vsh[j * DKx + d0];
            a0 = fmaf(Psh[warp][0][j], v, a0);
            a1 = fmaf(Psh[warp][1][j], v, a1);
        }
        a0 += __shfl_down_sync(0xffffffffu, a0, 16);
        a1 += __shfl_down_sync(0xffffffffu, a1, 16);
        if (lane < 16) {
            int i0 = i1 - 8;
            cat4[((size_t)bn * Sx + i0) * Dx + h * DKx + d0] = a0;
            cat4[((size_t)bn * Sx + i1) * Dx + h * DKx + d0] = a1;
        }
        __syncwarp();
    }
}

// ---------------- launch ----------------
extern "C" void kernel_launch(void* const* d_in, const int* in_sizes, int n_in,
                              void* d_out, int out_size) {
    (void)in_sizes; (void)n_in; (void)out_size;
    const float* q_emb  = (const float*)d_in[0];
    const float* s_emb  = (const float*)d_in[1];
    const float* b1_Wq  = (const float*)d_in[3];
    const float* b1_bq  = (const float*)d_in[4];
    const float* b1_Wv  = (const float*)d_in[5];
    const float* b1_bv  = (const float*)d_in[6];
    const float* b1_Wo  = (const float*)d_in[7];
    const float* b1_bo  = (const float*)d_in[8];
    const float* b1_gam = (const float*)d_in[9];
    const float* b1_lng = (const float*)d_in[10];
    const float* b1_lnb = (const float*)d_in[11];
    const float* b4_Wq  = (const float*)d_in[12];
    const float* b4_bq  = (const float*)d_in[13];
    const float* b4_Wk  = (const float*)d_in[14];
    const float* b4_bk  = (const float*)d_in[15];
    const float* b4_Wv  = (const float*)d_in[16];
    const float* b4_bv  = (const float*)d_in[17];
    const float* b4_Wo  = (const float*)d_in[18];
    const float* b4_bo  = (const float*)d_in[19];
    const float* b4_gam = (const float*)d_in[20];
    const float* b4_lng = (const float*)d_in[21];
    const float* b4_lnb = (const float*)d_in[22];
    const float* know   = (const float*)d_in[23];

    float* z_out  = (float*)d_out;
    float* qs_out = z_out + (size_t)BSx * Sx * NKx * Dx;
    float* ks_out = qs_out + (size_t)BSx * Hx * Sx * Sx;

    float *Q1, *V1, *cat1, *p, *q4, *k4, *v4, *cat4, *WT;
    cudaGetSymbolAddress((void**)&Q1,   d_Q1);
    cudaGetSymbolAddress((void**)&V1,   d_V1);
    cudaGetSymbolAddress((void**)&cat1, d_cat1);
    cudaGetSymbolAddress((void**)&p,    d_p);
    cudaGetSymbolAddress((void**)&q4,   d_q4);
    cudaGetSymbolAddress((void**)&k4,   d_k4);
    cudaGetSymbolAddress((void**)&v4,   d_v4);
    cudaGetSymbolAddress((void**)&cat4, d_cat4);
    cudaGetSymbolAddress((void**)&WT,   d_WT);

    // WT slots: 0=b1_Wq 1=b1_Wv 2=b1_Wo 3=b4_Wq 4=b4_Wk 5=b4_Wv 6=b4_Wo
    transpose_all<<<dim3(8, 8, 7), dim3(16, 16)>>>(b1_Wq, b1_Wv, b1_Wo, b4_Wq, b4_Wk, b4_Wv, b4_Wo, WT);

    proj_batch<<<dim3(32, 4), 256>>>(q_emb, s_emb, know, WT,
                                     b1_bq, b1_bv, b4_bk, b4_bq,
                                     Q1, V1, k4, q4);

    attn1_kernel<<<dim3(Sx / 8, Hx, BSx), 256>>>(Q1, V1, b1_gam, qs_out, cat1);

    oproj_ln1_k<<<32, 256>>>(cat1, WT + 2 * 16384, b1_bo, q_emb, b1_lng, b1_lnb, p);

    proj_single<<<32, 256>>>(p, WT + 5 * 16384, b4_bv, v4);

    attn4_kernel<<<dim3(BSx * NKx, Hx), 256>>>(q4, k4, v4, b4_gam, ks_out, cat4);

    oproj_ln4_k<<<512, 256>>>(cat4, WT + 6 * 16384, b4_bo, know, b4_lng, b4_lnb, z_out);
}

// round 3
// speedup vs baseline: 1.3583x; 1.0665x over previous
#include <cuda_runtime.h>
#include <math.h>
#include <stdint.h>

#define Sx   256
#define Dx   128
#define Hx   8
#define DKx  16
#define NKx  16
#define BSx  4
#define NEGV (-1e32f)

// ---------------- scratch ----------------
__device__ float d_Q1[BSx * Sx * Dx];
__device__ float d_V1[BSx * Sx * Dx];
__device__ float d_cat1[BSx * Sx * Dx];
__device__ float d_q4[NKx * Dx];
__device__ float d_k4[BSx * Sx * Dx];
__device__ float d_v4[BSx * Sx * Dx];
__device__ float d_cat4[BSx * NKx * Sx * Dx];
__device__ float d_WT[7][Dx * Dx];

// ---------------- helpers ----------------
__device__ __forceinline__ float warp_max(float v) {
#pragma unroll
    for (int o = 16; o; o >>= 1) v = fmaxf(v, __shfl_xor_sync(0xffffffffu, v, o));
    return v;
}
__device__ __forceinline__ float warp_sum(float v) {
#pragma unroll
    for (int o = 16; o; o >>= 1) v += __shfl_xor_sync(0xffffffffu, v, o);
    return v;
}
__device__ __forceinline__ float rcp_ap(float x) {
    float r; asm("rcp.approx.f32 %0, %1;" : "=f"(r) : "f"(x)); return r;
}
__device__ __forceinline__ float sqrt_ap(float x) {
    float r; asm("sqrt.approx.f32 %0, %1;" : "=f"(r) : "f"(x)); return r;
}
__device__ __forceinline__ void fma4(float4& a, float x, const float4& w) {
    a.x = fmaf(x, w.x, a.x); a.y = fmaf(x, w.y, a.y);
    a.z = fmaf(x, w.z, a.z); a.w = fmaf(x, w.w, a.w);
}
__device__ __forceinline__ float4 add4(float4 a, float4 b) {
    return make_float4(a.x + b.x, a.y + b.y, a.z + b.z, a.w + b.w);
}

// ---------------- transpose all 7 weights ----------------
__global__ void transpose_all(const float* __restrict__ s0, const float* __restrict__ s1,
                              const float* __restrict__ s2, const float* __restrict__ s3,
                              const float* __restrict__ s4, const float* __restrict__ s5,
                              const float* __restrict__ s6, float* __restrict__ dst) {
    const float* srcs[7] = {s0, s1, s2, s3, s4, s5, s6};
    __shared__ float t[16][17];
    const float* W = srcs[blockIdx.z];
    float* Wt = dst + (size_t)blockIdx.z * Dx * Dx;
    int bx = blockIdx.x * 16, by = blockIdx.y * 16;
    int x = threadIdx.x, y = threadIdx.y;
    t[y][x] = W[(by + y) * Dx + bx + x];
    __syncthreads();
    Wt[(bx + y) * Dx + by + x] = t[x][y];
}

// ---------------- warp GEMM: row held in registers (a), output float4/lane ----------------
__device__ __forceinline__ float4 gemm_reg(float4 a, const float* __restrict__ Wt, int lane) {
    const float4* W4 = (const float4*)Wt;
    float4 acc = make_float4(0.f, 0.f, 0.f, 0.f);
#pragma unroll 4
    for (int c = 0; c < 32; c++) {
        float x0 = __shfl_sync(0xffffffffu, a.x, c);
        float x1 = __shfl_sync(0xffffffffu, a.y, c);
        float x2 = __shfl_sync(0xffffffffu, a.z, c);
        float x3 = __shfl_sync(0xffffffffu, a.w, c);
        float4 w0 = W4[(4 * c + 0) * 32 + lane];
        float4 w1 = W4[(4 * c + 1) * 32 + lane];
        float4 w2 = W4[(4 * c + 2) * 32 + lane];
        float4 w3 = W4[(4 * c + 3) * 32 + lane];
        fma4(acc, x0, w0); fma4(acc, x1, w1); fma4(acc, x2, w2); fma4(acc, x3, w3);
    }
    return acc;
}

// two rows sharing the W stream
__device__ __forceinline__ void gemm_reg2(float4 a0, float4 a1, const float* __restrict__ Wt,
                                          int lane, float4& acc0, float4& acc1) {
    const float4* W4 = (const float4*)Wt;
    acc0 = make_float4(0.f, 0.f, 0.f, 0.f);
    acc1 = make_float4(0.f, 0.f, 0.f, 0.f);
#pragma unroll 2
    for (int c = 0; c < 32; c++) {
        float p0 = __shfl_sync(0xffffffffu, a0.x, c);
        float p1 = __shfl_sync(0xffffffffu, a0.y, c);
        float p2 = __shfl_sync(0xffffffffu, a0.z, c);
        float p3 = __shfl_sync(0xffffffffu, a0.w, c);
        float q0 = __shfl_sync(0xffffffffu, a1.x, c);
        float q1 = __shfl_sync(0xffffffffu, a1.y, c);
        float q2 = __shfl_sync(0xffffffffu, a1.z, c);
        float q3 = __shfl_sync(0xffffffffu, a1.w, c);
        float4 w0 = W4[(4 * c + 0) * 32 + lane];
        float4 w1 = W4[(4 * c + 1) * 32 + lane];
        float4 w2 = W4[(4 * c + 2) * 32 + lane];
        float4 w3 = W4[(4 * c + 3) * 32 + lane];
        fma4(acc0, p0, w0); fma4(acc0, p1, w1); fma4(acc0, p2, w2); fma4(acc0, p3, w3);
        fma4(acc1, q0, w0); fma4(acc1, q1, w1); fma4(acc1, q2, w2); fma4(acc1, q3, w3);
    }
}

// ---------------- LN over a float4-per-lane row ----------------
__device__ __forceinline__ float4 ln_row(float4 hv, const float4& g4, const float4& b4) {
    float s = hv.x + hv.y + hv.z + hv.w;
    s = warp_sum(s);
    float mean = s * 0.0078125f;
    float4 dv = {hv.x - mean, hv.y - mean, hv.z - mean, hv.w - mean};
    float vs = dv.x * dv.x + dv.y * dv.y + dv.z * dv.z + dv.w * dv.w;
    vs = warp_sum(vs);
    float rstd = rsqrtf(vs * 0.0078125f + 1e-5f);
    float4 o = {dv.x * rstd * g4.x + b4.x, dv.y * rstd * g4.y + b4.y,
                dv.z * rstd * g4.z + b4.z, dv.w * rstd * g4.w + b4.w};
    return o;
}

// ---------------- batched projections: Q1, V1, K4, Q4 (warp per row) ----------------
__global__ void proj_batch(const float* __restrict__ q_emb, const float* __restrict__ s_emb,
                           const float* __restrict__ know, const float* __restrict__ WT,
                           const float* __restrict__ bq1, const float* __restrict__ bv1,
                           const float* __restrict__ bk4, const float* __restrict__ bq4,
                           float* __restrict__ Q1, float* __restrict__ V1,
                           float* __restrict__ K4, float* __restrict__ Q4) {
    const float* A; const float* Wt; const float* bias; float* C; int M;
    switch (blockIdx.y) {
        case 0:  A = q_emb; Wt = WT + 0 * 16384; bias = bq1; C = Q1; M = 1024; break;
        case 1:  A = s_emb; Wt = WT + 1 * 16384; bias = bv1; C = V1; M = 1024; break;
        case 2:  A = q_emb; Wt = WT + 4 * 16384; bias = bk4; C = K4; M = 1024; break;
        default: A = know;  Wt = WT + 3 * 16384; bias = bq4; C = Q4; M = 16;   break;
    }
    int warp = threadIdx.x >> 5, lane = threadIdx.x & 31;
    int row = blockIdx.x * 8 + warp;
    if (row >= M) return;
    float4 a = ((const float4*)A)[(size_t)row * 32 + lane];
    float4 acc = gemm_reg(a, Wt, lane);
    float4 b4 = ((const float4*)bias)[lane];
    ((float4*)C)[(size_t)row * 32 + lane] = add4(acc, b4);
}

// ---------------- O-proj + residual + LN (block1) fused with V4 projection ----------------
// p row never hits memory: v4 = LN(q_emb + cat1@Wo^T + bo) @ Wv4^T + bv4
__global__ void oproj_ln1_v4(const float* __restrict__ X, const float* __restrict__ WoT,
                             const float* __restrict__ bo, const float* __restrict__ res,
                             const float* __restrict__ lng, const float* __restrict__ lnb,
                             const float* __restrict__ WvT, const float* __restrict__ bv,
                             float* __restrict__ v4) {
    int warp = threadIdx.x >> 5, lane = threadIdx.x & 31;
    int row = blockIdx.x * 8 + warp;
    float4 a = ((const float4*)X)[(size_t)row * 32 + lane];
    float4 acc = gemm_reg(a, WoT, lane);
    float4 bb = ((const float4*)bo)[lane];
    float4 rv = ((const float4*)res)[(size_t)row * 32 + lane];
    float4 hv = {acc.x + bb.x + rv.x, acc.y + bb.y + rv.y,
                 acc.z + bb.z + rv.z, acc.w + bb.w + rv.w};
    float4 g4 = ((const float4*)lng)[lane];
    float4 b4 = ((const float4*)lnb)[lane];
    float4 p4 = ln_row(hv, g4, b4);
    // second GEMM straight from registers
    float4 acc2 = gemm_reg(p4, WvT, lane);
    float4 bv4 = ((const float4*)bv)[lane];
    ((float4*)v4)[(size_t)row * 32 + lane] = add4(acc2, bv4);
}

// ---------------- O-proj + residual(know) + LN + scatter (block4), 2 rows/warp ----------------
__global__ void oproj_ln4_k(const float* __restrict__ X, const float* __restrict__ WoT,
                            const float* __restrict__ bo, const float* __restrict__ know,
                            const float* __restrict__ lng, const float* __restrict__ lnb,
                            float* __restrict__ z) {
    int warp = threadIdx.x >> 5, lane = threadIdx.x & 31;
    int row0 = blockIdx.x * 16 + warp * 2;      // rows row0, row0+1
    float4 a0 = ((const float4*)X)[(size_t)row0 * 32 + lane];
    float4 a1 = ((const float4*)X)[(size_t)(row0 + 1) * 32 + lane];
    float4 acc0, acc1;
    gemm_reg2(a0, a1, WoT, lane, acc0, acc1);
    float4 bb = ((const float4*)bo)[lane];
    float4 g4 = ((const float4*)lng)[lane];
    float4 b4 = ((const float4*)lnb)[lane];
    const float4* K4p = (const float4*)know;
    float4* Z4 = (float4*)z;
#pragma unroll
    for (int r = 0; r < 2; r++) {
        int row = row0 + r;                      // (b*NK+n)*S + s
        int bn = row >> 8, s = row & 255;
        int b = bn >> 4, n = bn & 15;
        float4 rv = K4p[n * 32 + lane];
        float4 ac = (r == 0) ? acc0 : acc1;
        float4 hv = {ac.x + bb.x + rv.x, ac.y + bb.y + rv.y,
                     ac.z + bb.z + rv.z, ac.w + bb.w + rv.w};
        Z4[(((size_t)(b * Sx + s) * NKx) + n) * 32 + lane] = ln_row(hv, g4, b4);
    }
}

// ---------------- block1 attention: warp-per-row, triangular bounds ----------------
__global__ void attn1_kernel(const float* __restrict__ QK, const float* __restrict__ Vg,
                             const float* __restrict__ gamma,
                             float* __restrict__ q_scores, float* __restrict__ cat1) {
    __shared__ float Kd[DKx * Sx];   // [d][j]
    __shared__ float Vsh[Sx * DKx];  // [j][d]
    __shared__ float Psh[8][Sx];
    const int b = blockIdx.z, h = blockIdx.y;
    const int tid = threadIdx.x, lane = tid & 31, warp = tid >> 5;

    {
        const float* base = QK + ((size_t)b * Sx) * Dx + h * DKx;
        const float4* r = (const float4*)(base + (size_t)tid * Dx);
        float4 a0 = r[0], a1 = r[1], a2 = r[2], a3 = r[3];
        Kd[0*Sx+tid]=a0.x; Kd[1*Sx+tid]=a0.y; Kd[2*Sx+tid]=a0.z; Kd[3*Sx+tid]=a0.w;
        Kd[4*Sx+tid]=a1.x; Kd[5*Sx+tid]=a1.y; Kd[6*Sx+tid]=a1.z; Kd[7*Sx+tid]=a1.w;
        Kd[8*Sx+tid]=a2.x; Kd[9*Sx+tid]=a2.y; Kd[10*Sx+tid]=a2.z; Kd[11*Sx+tid]=a2.w;
        Kd[12*Sx+tid]=a3.x; Kd[13*Sx+tid]=a3.y; Kd[14*Sx+tid]=a3.z; Kd[15*Sx+tid]=a3.w;
    }
    {
        const float* base = Vg + ((size_t)b * Sx) * Dx + h * DKx;
        for (int idx = tid; idx < Sx * DKx; idx += 256) {
            int j = idx >> 4, d = idx & 15;
            Vsh[idx] = base[(size_t)j * Dx + d];
        }
    }
    __syncthreads();

    const float g = -fabsf(gamma[h]);
    const int i = blockIdx.x * 8 + warp;
    const int uMax = i >> 5;

    float q[16];
#pragma unroll
    for (int d = 0; d < 16; d++) q[d] = Kd[d * Sx + i];

    float sc[8], ex[8];
    float mx = NEGV;
#pragma unroll
    for (int u = 0; u < 8; u++) {
        if (u <= uMax) {
            int j = u * 32 + lane;
            float s = 0.f;
#pragma unroll
            for (int d = 0; d < 16; d++) s = fmaf(q[d], Kd[d * Sx + j], s);
            s *= 0.25f;
            sc[u] = s;
            float m = (j <= i) ? s : NEGV;
            ex[u] = m;
            mx = fmaxf(mx, m);
        } else { ex[u] = NEGV; sc[u] = 0.f; }
    }
    mx = warp_max(mx);
    float sum = 0.f;
#pragma unroll
    for (int u = 0; u < 8; u++) if (u <= uMax) { ex[u] = __expf(ex[u] - mx); sum += ex[u]; }
    sum = warp_sum(sum);
    float inv = rcp_ap(sum);

    float cum[8]; float carry = 0.f;
#pragma unroll
    for (int u = 0; u < 8; u++) {
        if (u <= uMax) {
            float x = ex[u] * inv;
#pragma unroll
            for (int off = 1; off < 32; off <<= 1) {
                float nv = __shfl_up_sync(0xffffffffu, x, off);
                if (lane >= off) x += nv;
            }
            float seg = __shfl_sync(0xffffffffu, x, 31);
            cum[u] = x + carry;
            carry += seg;
        } else cum[u] = 0.f;
    }
    const float total = carry;
    const float fi = (float)i;

    float mx2 = NEGV;
#pragma unroll
    for (int u = 0; u < 8; u++) {
        if (u <= uMax) {
            int j = u * 32 + lane;
            float pos = fabsf((float)j - fi);
            float dist = sqrt_ap(fmaxf((total - cum[u]) * pos, 0.f));
            float eff = __expf(g * dist);
            eff = fminf(fmaxf(eff, 1e-5f), 1e5f);
            float s2 = sc[u] * eff;
            s2 = (j <= i) ? s2 : NEGV;
            ex[u] = s2;
            mx2 = fmaxf(mx2, s2);
        }
    }
    mx2 = warp_max(mx2);
    float sum2 = 0.f;
#pragma unroll
    for (int u = 0; u < 8; u++) if (u <= uMax) { ex[u] = __expf(ex[u] - mx2); sum2 += ex[u]; }
    sum2 = warp_sum(sum2);
    float inv2 = rcp_ap(sum2);

    float* qs = q_scores + (((size_t)(b * Hx + h)) * Sx + i) * Sx;
#pragma unroll
    for (int u = 0; u < 8; u++) {
        int j = u * 32 + lane;
        float p = (u <= uMax && j <= i) ? ex[u] * inv2 : 0.f;
        Psh[warp][j] = p;
        qs[j] = p;
    }
    __syncwarp();

    float acc = 0.f;
    int d0 = lane & 15, half = lane >> 4;
    for (int j = half; j <= i; j += 2)
        acc = fmaf(Psh[warp][j], Vsh[j * DKx + d0], acc);
    acc += __shfl_down_sync(0xffffffffu, acc, 16);
    if (lane < 16)
        cat1[(((size_t)b * Sx) + i) * Dx + h * DKx + lane] = acc;
}

// ---------------- block4 attention: scan-free (prefix-sum trick), fused sc ----------------
__global__ void attn4_kernel(const float* __restrict__ q4g, const float* __restrict__ k4g,
                             const float* __restrict__ v4g, const float* __restrict__ gamma,
                             float* __restrict__ ks_out, float* __restrict__ cat4) {
    __shared__ float Vsh[Sx * DKx];
    __shared__ float scsh[Sx];
    __shared__ float Csh[Sx];
    __shared__ float Psh[8][2][Sx];
    __shared__ float redA[8], redB[8];

    const int bn = blockIdx.x, h = blockIdx.y;
    const int b = bn >> 4, n = bn & 15;
    const int tid = threadIdx.x, lane = tid & 31, warp = tid >> 5;

    {
        const float* vb = v4g + ((size_t)b * Sx) * Dx + h * DKx;
        for (int idx = tid; idx < Sx * DKx; idx += 256) {
            int j = idx >> 4, d = idx & 15;
            Vsh[idx] = vb[(size_t)j * Dx + d];
        }
    }
    {
        const float* qp = q4g + n * Dx + h * DKx;
        const float* kp = k4g + ((size_t)b * Sx + tid) * Dx + h * DKx;
        float s = 0.f;
#pragma unroll
        for (int d = 0; d < 16; d++) s = fmaf(qp[d], kp[d], s);
        s *= 0.25f;
        scsh[tid] = s;
        float m = warp_max(s);
        if (lane == 0) redA[warp] = m;
        __syncthreads();
        float M = redA[0];
#pragma unroll
        for (int w = 1; w < 8; w++) M = fmaxf(M, redA[w]);
        float e = __expf(s - M);
        float x = e;
#pragma unroll
        for (int off = 1; off < 32; off <<= 1) {
            float nv = __shfl_up_sync(0xffffffffu, x, off);
            if (lane >= off) x += nv;
        }
        if (lane == 31) redB[warp] = x;
        __syncthreads();
        float carry = 0.f;
#pragma unroll
        for (int w = 0; w < 7; w++) if (w < warp) carry += redB[w];
        Csh[tid] = x + carry;
    }
    __syncthreads();

    const float g = -fabsf(gamma[h]);
    float scu[8];
#pragma unroll
    for (int u = 0; u < 8; u++) scu[u] = scsh[u * 32 + lane];

    const int d0 = lane & 15, half = lane >> 4;

    for (int gb = 0; gb < 16; ++gb) {
        const int i1 = warp + 8 * (2 * gb + 1);
        const int nUb = (i1 - 1) >> 5;

        for (int k = 0; k < 2; ++k) {
            const int i = warp + 8 * (2 * gb + k);
            const int uMax = (i - 1) >> 5;
            float invC = 0.f;
            if (i > 0) invC = rcp_ap(Csh[i - 1]);
            const float fi = (float)i;

            float ex[8];
            float mx = NEGV;
#pragma unroll
            for (int u = 0; u < 8; u++) {
                if (u <= uMax) {
                    int j = u * 32 + lane;
                    float Cu = Csh[j];
                    float t = (1.f - Cu * invC) * fabsf((float)j - fi);
                    float dist = sqrt_ap(fmaxf(t, 0.f));
                    float eff = __expf(g * dist);
                    eff = fminf(fmaxf(eff, 1e-5f), 1e5f);
                    float s2 = scu[u] * eff;
                    s2 = (j < i) ? s2 : NEGV;
                    ex[u] = s2;
                    mx = fmaxf(mx, s2);
                } else ex[u] = NEGV;
            }
            mx = warp_max(mx);
            float sum = 0.f;
#pragma unroll
            for (int u = 0; u < 8; u++)
                if (u <= uMax) { ex[u] = __expf(ex[u] - mx); sum += ex[u]; }
            sum = warp_sum(sum);
            float inv2 = rcp_ap(sum);

            float pmax = 0.f;
#pragma unroll
            for (int u = 0; u < 8; u++) {
                if (u <= uMax) {
                    int j = u * 32 + lane;
                    float pv = (j < i) ? ex[u] * inv2 : 0.f;
                    ex[u] = pv;
                    pmax = fmaxf(pmax, pv);
                } else ex[u] = 0.f;
            }
            pmax = warp_max(pmax);
            float scale = fminf(rcp_ap(pmax), 5.f);

            float* ks = ks_out + ((((size_t)(b * Hx + h) * Sx + i) * NKx + n) << 8);
#pragma unroll
            for (int u = 0; u < 8; u++) {
                int j = u * 32 + lane;
                float pv = ex[u] * scale;
                ks[j] = pv;
                if (u <= nUb) Psh[warp][k][j] = pv;
            }
        }
        __syncwarp();

        float a0 = 0.f, a1 = 0.f;
        for (int j = half; j < i1; j += 2) {
            float v = Vsh[j * DKx + d0];
            a0 = fmaf(Psh[warp][0][j], v, a0);
            a1 = fmaf(Psh[warp][1][j], v, a1);
        }
        a0 += __shfl_down_sync(0xffffffffu, a0, 16);
        a1 += __shfl_down_sync(0xffffffffu, a1, 16);
        if (lane < 16) {
            int i0 = i1 - 8;
            cat4[((size_t)bn * Sx + i0) * Dx + h * DKx + d0] = a0;
            cat4[((size_t)bn * Sx + i1) * Dx + h * DKx + d0] = a1;
        }
        __syncwarp();
    }
}

// ---------------- launch ----------------
extern "C" void kernel_launch(void* const* d_in, const int* in_sizes, int n_in,
                              void* d_out, int out_size) {
    (void)in_sizes; (void)n_in; (void)out_size;
    const float* q_emb  = (const float*)d_in[0];
    const float* s_emb  = (const float*)d_in[1];
    const float* b1_Wq  = (const float*)d_in[3];
    const float* b1_bq  = (const float*)d_in[4];
    const float* b1_Wv  = (const float*)d_in[5];
    const float* b1_bv  = (const float*)d_in[6];
    const float* b1_Wo  = (const float*)d_in[7];
    const float* b1_bo  = (const float*)d_in[8];
    const float* b1_gam = (const float*)d_in[9];
    const float* b1_lng = (const float*)d_in[10];
    const float* b1_lnb = (const float*)d_in[11];
    const float* b4_Wq  = (const float*)d_in[12];
    const float* b4_bq  = (const float*)d_in[13];
    const float* b4_Wk  = (const float*)d_in[14];
    const float* b4_bk  = (const float*)d_in[15];
    const float* b4_Wv  = (const float*)d_in[16];
    const float* b4_bv  = (const float*)d_in[17];
    const float* b4_Wo  = (const float*)d_in[18];
    const float* b4_bo  = (const float*)d_in[19];
    const float* b4_gam = (const float*)d_in[20];
    const float* b4_lng = (const float*)d_in[21];
    const float* b4_lnb = (const float*)d_in[22];
    const float* know   = (const float*)d_in[23];

    float* z_out  = (float*)d_out;
    float* qs_out = z_out + (size_t)BSx * Sx * NKx * Dx;
    float* ks_out = qs_out + (size_t)BSx * Hx * Sx * Sx;

    float *Q1, *V1, *cat1, *q4, *k4, *v4, *cat4, *WT;
    cudaGetSymbolAddress((void**)&Q1,   d_Q1);
    cudaGetSymbolAddress((void**)&V1,   d_V1);
    cudaGetSymbolAddress((void**)&cat1, d_cat1);
    cudaGetSymbolAddress((void**)&q4,   d_q4);
    cudaGetSymbolAddress((void**)&k4,   d_k4);
    cudaGetSymbolAddress((void**)&v4,   d_v4);
    cudaGetSymbolAddress((void**)&cat4, d_cat4);
    cudaGetSymbolAddress((void**)&WT,   d_WT);

    // WT slots: 0=b1_Wq 1=b1_Wv 2=b1_Wo 3=b4_Wq 4=b4_Wk 5=b4_Wv 6=b4_Wo
    transpose_all<<<dim3(8, 8, 7), dim3(16, 16)>>>(b1_Wq, b1_Wv, b1_Wo, b4_Wq, b4_Wk, b4_Wv, b4_Wo, WT);

    proj_batch<<<dim3(128, 4), 256>>>(q_emb, s_emb, know, WT,
                                      b1_bq, b1_bv, b4_bk, b4_bq,
                                      Q1, V1, k4, q4);

    attn1_kernel<<<dim3(Sx / 8, Hx, BSx), 256>>>(Q1, V1, b1_gam, qs_out, cat1);

    oproj_ln1_v4<<<128, 256>>>(cat1, WT + 2 * 16384, b1_bo, q_emb, b1_lng, b1_lnb,
                               WT + 5 * 16384, b4_bv, v4);

    attn4_kernel<<<dim3(BSx * NKx, Hx), 256>>>(q4, k4, v4, b4_gam, ks_out, cat4);

    oproj_ln4_k<<<1024, 256>>>(cat4, WT + 6 * 16384, b4_bo, know, b4_lng, b4_lnb, z_out);
}

// round 4
// speedup vs baseline: 1.5828x; 1.1652x over previous
#include <cuda_runtime.h>
#include <math.h>
#include <stdint.h>

#define Sx   256
#define Dx   128
#define Hx   8
#define DKx  16
#define NKx  16
#define BSx  4

typedef unsigned long long u64;

// ---------------- scratch ----------------
__device__ float d_Q1[BSx * Sx * Dx];
__device__ float d_V1[BSx * Sx * Dx];
__device__ float d_cat1[BSx * Sx * Dx];
__device__ float d_q4[NKx * Dx];
__device__ float d_k4[BSx * Sx * Dx];
__device__ float d_v4[BSx * Sx * Dx];
__device__ float d_cat4[BSx * NKx * Sx * Dx];
__device__ float d_WT[7][Dx * Dx];

// ---------------- helpers ----------------
__device__ __forceinline__ float warp_max(float v) {
#pragma unroll
    for (int o = 16; o; o >>= 1) v = fmaxf(v, __shfl_xor_sync(0xffffffffu, v, o));
    return v;
}
__device__ __forceinline__ float warp_sum(float v) {
#pragma unroll
    for (int o = 16; o; o >>= 1) v += __shfl_xor_sync(0xffffffffu, v, o);
    return v;
}
__device__ __forceinline__ float rcp_ap(float x) {
    float r; asm("rcp.approx.f32 %0, %1;" : "=f"(r) : "f"(x)); return r;
}
__device__ __forceinline__ float sqrt_ap(float x) {
    float r; asm("sqrt.approx.f32 %0, %1;" : "=f"(r) : "f"(x)); return r;
}
__device__ __forceinline__ float ex2_ap(float x) {
    float r; asm("ex2.approx.f32 %0, %1;" : "=f"(r) : "f"(x)); return r;
}
__device__ __forceinline__ u64 pk2(float x) {
    u64 r; asm("mov.b64 %0, {%1, %1};" : "=l"(r) : "f"(x)); return r;
}
__device__ __forceinline__ void ffma2(u64& d, u64 a, u64 b) {
    asm("fma.rn.f32x2 %0, %1, %2, %0;" : "+l"(d) : "l"(a), "l"(b));
}
__device__ __forceinline__ float2 up2(u64 v) {
    float2 f; asm("mov.b64 {%0, %1}, %2;" : "=f"(f.x), "=f"(f.y) : "l"(v)); return f;
}
__device__ __forceinline__ float4 unpack_acc(u64 lo, u64 hi) {
    float2 a = up2(lo), b = up2(hi);
    return make_float4(a.x, a.y, b.x, b.y);
}

#define LN2I 1.442695041f

// ---------------- transpose all 7 weights ----------------
__global__ void transpose_all(const float* __restrict__ s0, const float* __restrict__ s1,
                              const float* __restrict__ s2, const float* __restrict__ s3,
                              const float* __restrict__ s4, const float* __restrict__ s5,
                              const float* __restrict__ s6, float* __restrict__ dst) {
    const float* srcs[7] = {s0, s1, s2, s3, s4, s5, s6};
    __shared__ float t[16][17];
    const float* W = srcs[blockIdx.z];
    float* Wt = dst + (size_t)blockIdx.z * Dx * Dx;
    int bx = blockIdx.x * 16, by = blockIdx.y * 16;
    int x = threadIdx.x, y = threadIdx.y;
    t[y][x] = W[(by + y) * Dx + bx + x];
    __syncthreads();
    Wt[(bx + y) * Dx + by + x] = t[x][y];
}

// ---------------- warp GEMM: R rows, X via uniform LDG.128, FFMA2 accumulate ----------------
template<int R>
__device__ __forceinline__ void gemm_px(const float4* X4,   // row0 base; rows are 32 float4 apart
                                        const float* __restrict__ Wt, int lane,
                                        u64 aL[R], u64 aH[R]) {
#pragma unroll
    for (int r = 0; r < R; r++) { aL[r] = 0ull; aH[r] = 0ull; }
    const ulonglong2* W2 = (const ulonglong2*)Wt;
#pragma unroll 4
    for (int c = 0; c < 32; c++) {
        float4 xv[R];
#pragma unroll
        for (int r = 0; r < R; r++) xv[r] = X4[r * 32 + c];
        ulonglong2 w0 = W2[(4 * c + 0) * 32 + lane];
        ulonglong2 w1 = W2[(4 * c + 1) * 32 + lane];
        ulonglong2 w2 = W2[(4 * c + 2) * 32 + lane];
        ulonglong2 w3 = W2[(4 * c + 3) * 32 + lane];
#pragma unroll
        for (int r = 0; r < R; r++) {
            u64 p0 = pk2(xv[r].x), p1 = pk2(xv[r].y), p2 = pk2(xv[r].z), p3 = pk2(xv[r].w);
            ffma2(aL[r], p0, w0.x); ffma2(aH[r], p0, w0.y);
            ffma2(aL[r], p1, w1.x); ffma2(aH[r], p1, w1.y);
            ffma2(aL[r], p2, w2.x); ffma2(aH[r], p2, w2.y);
            ffma2(aL[r], p3, w3.x); ffma2(aH[r], p3, w3.y);
        }
    }
}

// ---------------- LN over a float4-per-lane row ----------------
__device__ __forceinline__ float4 ln_row(float4 hv, const float4& g4, const float4& b4) {
    float s = hv.x + hv.y + hv.z + hv.w;
    s = warp_sum(s);
    float mean = s * 0.0078125f;
    float4 dv = {hv.x - mean, hv.y - mean, hv.z - mean, hv.w - mean};
    float vs = dv.x * dv.x + dv.y * dv.y + dv.z * dv.z + dv.w * dv.w;
    vs = warp_sum(vs);
    float rstd = rsqrtf(vs * 0.0078125f + 1e-5f);
    float4 o = {dv.x * rstd * g4.x + b4.x, dv.y * rstd * g4.y + b4.y,
                dv.z * rstd * g4.z + b4.z, dv.w * rstd * g4.w + b4.w};
    return o;
}

// ---------------- batched projections: Q1, V1, K4, Q4 (2 rows/warp) ----------------
__global__ void proj_batch(const float* __restrict__ q_emb, const float* __restrict__ s_emb,
                           const float* __restrict__ know, const float* __restrict__ WT,
                           const float* __restrict__ bq1, const float* __restrict__ bv1,
                           const float* __restrict__ bk4, const float* __restrict__ bq4,
                           float* __restrict__ Q1, float* __restrict__ V1,
                           float* __restrict__ K4, float* __restrict__ Q4) {
    const float* A; const float* Wt; const float* bias; float* C; int M;
    switch (blockIdx.y) {
        case 0:  A = q_emb; Wt = WT + 0 * 16384; bias = bq1; C = Q1; M = 1024; break;
        case 1:  A = s_emb; Wt = WT + 1 * 16384; bias = bv1; C = V1; M = 1024; break;
        case 2:  A = q_emb; Wt = WT + 4 * 16384; bias = bk4; C = K4; M = 1024; break;
        default: A = know;  Wt = WT + 3 * 16384; bias = bq4; C = Q4; M = 16;   break;
    }
    int warp = threadIdx.x >> 5, lane = threadIdx.x & 31;
    int row0 = blockIdx.x * 16 + warp * 2;
    if (row0 >= M) return;
    u64 aL[2], aH[2];
    gemm_px<2>((const float4*)A + (size_t)row0 * 32, Wt, lane, aL, aH);
    float4 b4 = ((const float4*)bias)[lane];
    float4* C4 = (float4*)C;
#pragma unroll
    for (int r = 0; r < 2; r++) {
        float4 acc = unpack_acc(aL[r], aH[r]);
        C4[(size_t)(row0 + r) * 32 + lane] =
            make_float4(acc.x + b4.x, acc.y + b4.y, acc.z + b4.z, acc.w + b4.w);
    }
}

// ---------------- O-proj + residual + LN (block1) fused with V4 projection ----------------
__global__ void oproj_ln1_v4(const float* __restrict__ X, const float* __restrict__ WoT,
                             const float* __restrict__ bo, const float* __restrict__ res,
                             const float* __restrict__ lng, const float* __restrict__ lnb,
                             const float* __restrict__ WvT, const float* __restrict__ bv,
                             float* __restrict__ v4) {
    __shared__ float psm[8][2][Dx];
    int warp = threadIdx.x >> 5, lane = threadIdx.x & 31;
    int row0 = blockIdx.x * 16 + warp * 2;
    u64 aL[2], aH[2];
    gemm_px<2>((const float4*)X + (size_t)row0 * 32, WoT, lane, aL, aH);
    float4 bb = ((const float4*)bo)[lane];
    float4 g4 = ((const float4*)lng)[lane];
    float4 b4 = ((const float4*)lnb)[lane];
#pragma unroll
    for (int r = 0; r < 2; r++) {
        float4 acc = unpack_acc(aL[r], aH[r]);
        float4 rv = ((const float4*)res)[(size_t)(row0 + r) * 32 + lane];
        float4 hv = {acc.x + bb.x + rv.x, acc.y + bb.y + rv.y,
                     acc.z + bb.z + rv.z, acc.w + bb.w + rv.w};
        ((float4*)psm[warp][r])[lane] = ln_row(hv, g4, b4);
    }
    __syncwarp();
    u64 cL[2], cH[2];
    gemm_px<2>((const float4*)psm[warp][0], WvT, lane, cL, cH);
    float4 bv4 = ((const float4*)bv)[lane];
    float4* V4 = (float4*)v4;
#pragma unroll
    for (int r = 0; r < 2; r++) {
        float4 acc = unpack_acc(cL[r], cH[r]);
        V4[(size_t)(row0 + r) * 32 + lane] =
            make_float4(acc.x + bv4.x, acc.y + bv4.y, acc.z + bv4.z, acc.w + bv4.w);
    }
}

// ---------------- O-proj + residual(know) + LN + scatter (block4), 4 rows/warp ----------------
__global__ void oproj_ln4_k(const float* __restrict__ X, const float* __restrict__ WoT,
                            const float* __restrict__ bo, const float* __restrict__ know,
                            const float* __restrict__ lng, const float* __restrict__ lnb,
                            float* __restrict__ z) {
    int warp = threadIdx.x >> 5, lane = threadIdx.x & 31;
    int row0 = blockIdx.x * 32 + warp * 4;
    u64 aL[4], aH[4];
    gemm_px<4>((const float4*)X + (size_t)row0 * 32, WoT, lane, aL, aH);
    float4 bb = ((const float4*)bo)[lane];
    float4 g4 = ((const float4*)lng)[lane];
    float4 b4 = ((const float4*)lnb)[lane];
    const float4* K4p = (const float4*)know;
    float4* Z4 = (float4*)z;
#pragma unroll
    for (int r = 0; r < 4; r++) {
        int row = row0 + r;                      // (b*NK+n)*S + s
        int bn = row >> 8, s = row & 255;
        int b = bn >> 4, n = bn & 15;
        float4 rv = K4p[n * 32 + lane];
        float4 acc = unpack_acc(aL[r], aH[r]);
        float4 hv = {acc.x + bb.x + rv.x, acc.y + bb.y + rv.y,
                     acc.z + bb.z + rv.z, acc.w + bb.w + rv.w};
        Z4[(((size_t)(b * Sx + s) * NKx) + n) * 32 + lane] = ln_row(hv, g4, b4);
    }
}

// ---------------- block1 attention: warp-per-row, no-max softmax ----------------
__global__ void attn1_kernel(const float* __restrict__ QK, const float* __restrict__ Vg,
                             const float* __restrict__ gamma,
                             float* __restrict__ q_scores, float* __restrict__ cat1) {
    __shared__ float Kd[DKx * Sx];   // [d][j]
    __shared__ float Vsh[Sx * DKx];  // [j][d]
    __shared__ float Psh[8][Sx];
    const int b = blockIdx.z, h = blockIdx.y;
    const int tid = threadIdx.x, lane = tid & 31, warp = tid >> 5;

    {
        const float* base = QK + ((size_t)b * Sx) * Dx + h * DKx;
        const float4* r = (const float4*)(base + (size_t)tid * Dx);
        float4 a0 = r[0], a1 = r[1], a2 = r[2], a3 = r[3];
        Kd[0*Sx+tid]=a0.x; Kd[1*Sx+tid]=a0.y; Kd[2*Sx+tid]=a0.z; Kd[3*Sx+tid]=a0.w;
        Kd[4*Sx+tid]=a1.x; Kd[5*Sx+tid]=a1.y; Kd[6*Sx+tid]=a1.z; Kd[7*Sx+tid]=a1.w;
        Kd[8*Sx+tid]=a2.x; Kd[9*Sx+tid]=a2.y; Kd[10*Sx+tid]=a2.z; Kd[11*Sx+tid]=a2.w;
        Kd[12*Sx+tid]=a3.x; Kd[13*Sx+tid]=a3.y; Kd[14*Sx+tid]=a3.z; Kd[15*Sx+tid]=a3.w;
    }
    {
        const float* base = Vg + ((size_t)b * Sx) * Dx + h * DKx;
        for (int idx = tid; idx < Sx * DKx; idx += 256) {
            int j = idx >> 4, d = idx & 15;
            Vsh[idx] = base[(size_t)j * Dx + d];
        }
    }
    __syncthreads();

    const float g2 = -fabsf(gamma[h]) * LN2I;
    const int i = blockIdx.x * 8 + warp;
    const int uMax = i >> 5;

    float q[16];
#pragma unroll
    for (int d = 0; d < 16; d++) q[d] = Kd[d * Sx + i];

    float sc2[8], ex[8];
    float sum = 0.f;
#pragma unroll
    for (int u = 0; u < 8; u++) {
        if (u <= uMax) {
            int j = u * 32 + lane;
            float s = 0.f;
#pragma unroll
            for (int d = 0; d < 16; d++) s = fmaf(q[d], Kd[d * Sx + j], s);
            sc2[u] = s * (0.25f * LN2I);
            float e = (j <= i) ? ex2_ap(sc2[u]) : 0.f;
            ex[u] = e;
            sum += e;
        } else { ex[u] = 0.f; sc2[u] = 0.f; }
    }
    sum = warp_sum(sum);
    float inv = rcp_ap(sum);

    float cum[8]; float carry = 0.f;
#pragma unroll
    for (int u = 0; u < 8; u++) {
        if (u <= uMax) {
            float x = ex[u] * inv;
#pragma unroll
            for (int off = 1; off < 32; off <<= 1) {
                float nv = __shfl_up_sync(0xffffffffu, x, off);
                if (lane >= off) x += nv;
            }
            float seg = __shfl_sync(0xffffffffu, x, 31);
            cum[u] = x + carry;
            carry += seg;
        } else cum[u] = 0.f;
    }
    const float total = carry;
    const float fi = (float)i;

    float sum2 = 0.f;
#pragma unroll
    for (int u = 0; u < 8; u++) {
        if (u <= uMax) {
            int j = u * 32 + lane;
            float pos = fabsf((float)j - fi);
            float dist = sqrt_ap(fmaxf((total - cum[u]) * pos, 0.f));
            float eff = fmaxf(ex2_ap(g2 * dist), 1e-5f);
            float e2 = (j <= i) ? ex2_ap(sc2[u] * eff) : 0.f;
            ex[u] = e2;
            sum2 += e2;
        }
    }
    sum2 = warp_sum(sum2);
    float inv2 = rcp_ap(sum2);

#pragma unroll
    for (int u = 0; u < 8; u++)
        Psh[warp][u * 32 + lane] = (u <= uMax) ? ex[u] * inv2 : 0.f;
    __syncwarp();

    {   // q_scores via float4
        const float4* P4 = (const float4*)Psh[warp];
        float4* qs4 = (float4*)(q_scores + (((size_t)(b * Hx + h)) * Sx + i) * Sx);
        qs4[lane] = P4[lane];
        qs4[32 + lane] = P4[32 + lane];
    }

    float acc = 0.f;
    int d0 = lane & 15, half = lane >> 4;
    for (int j = half; j <= i; j += 2)
        acc = fmaf(Psh[warp][j], Vsh[j * DKx + d0], acc);
    acc += __shfl_down_sync(0xffffffffu, acc, 16);
    if (lane < 16)
        cat1[(((size_t)b * Sx) + i) * Dx + h * DKx + lane] = acc;
}

// ---------------- block4 attention: scan-free, no-max softmax2, fused maxout ----------------
__global__ void attn4_kernel(const float* __restrict__ q4g, const float* __restrict__ k4g,
                             const float* __restrict__ v4g, const float* __restrict__ gamma,
                             float* __restrict__ ks_out, float* __restrict__ cat4) {
    __shared__ float Vsh[Sx * DKx];
    __shared__ float sc2sh[Sx];
    __shared__ float Csh[Sx];
    __shared__ float Psh[8][2][Sx];
    __shared__ float redA[8], redB[8];

    const int bn = blockIdx.x, h = blockIdx.y;
    const int b = bn >> 4, n = bn & 15;
    const int tid = threadIdx.x, lane = tid & 31, warp = tid >> 5;

    {
        const float* vb = v4g + ((size_t)b * Sx) * Dx + h * DKx;
        for (int idx = tid; idx < Sx * DKx; idx += 256) {
            int j = idx >> 4, d = idx & 15;
            Vsh[idx] = vb[(size_t)j * Dx + d];
        }
    }
    {   // base score row (log2-scaled) + block max + prefix sums of exp
        const float* qp = q4g + n * Dx + h * DKx;
        const float* kp = k4g + ((size_t)b * Sx + tid) * Dx + h * DKx;
        float s = 0.f;
#pragma unroll
        for (int d = 0; d < 16; d++) s = fmaf(qp[d], kp[d], s);
        float v = s * (0.25f * LN2I);
        sc2sh[tid] = v;
        float m = warp_max(v);
        if (lane == 0) redA[warp] = m;
        __syncthreads();
        float M = redA[0];
#pragma unroll
        for (int w = 1; w < 8; w++) M = fmaxf(M, redA[w]);
        float x = ex2_ap(v - M);
#pragma unroll
        for (int off = 1; off < 32; off <<= 1) {
            float nv = __shfl_up_sync(0xffffffffu, x, off);
            if (lane >= off) x += nv;
        }
        if (lane == 31) redB[warp] = x;
        __syncthreads();
        float carry = 0.f;
#pragma unroll
        for (int w = 0; w < 7; w++) if (w < warp) carry += redB[w];
        Csh[tid] = x + carry;
    }
    __syncthreads();

    const float g2 = -fabsf(gamma[h]) * LN2I;
    float sc2[8];
#pragma unroll
    for (int u = 0; u < 8; u++) sc2[u] = sc2sh[u * 32 + lane];

    const int d0 = lane & 15, half = lane >> 4;

    for (int gb = 0; gb < 16; ++gb) {
        const int i1 = warp + 8 * (2 * gb + 1);

        for (int k = 0; k < 2; ++k) {
            const int i = i1 - 8 + 8 * k;
            const int uMax = (i - 1) >> 5;
            const float invC = (i > 0) ? rcp_ap(Csh[i - 1]) : 0.f;
            const float fi = (float)i;

            float e[8], sum = 0.f, emax = 0.f;
#pragma unroll
            for (int u = 0; u < 8; u++) {
                if (u <= uMax) {
                    int j = u * 32 + lane;
                    float t = fmaf(-Csh[j], invC, 1.0f);
                    float pos = fabsf((float)j - fi);
                    float dist = sqrt_ap(fmaxf(t * pos, 0.f));
                    float eff = fmaxf(ex2_ap(g2 * dist), 1e-5f);
                    float ev = (j < i) ? ex2_ap(sc2[u] * eff) : 0.f;
                    e[u] = ev;
                    sum += ev;
                    emax = fmaxf(emax, ev);
                } else e[u] = 0.f;
            }
            sum = warp_sum(sum);
            emax = warp_max(emax);
            float mult = fminf(rcp_ap(fmaxf(emax, 1e-30f)),
                               5.f * rcp_ap(fmaxf(sum, 1e-30f)));
#pragma unroll
            for (int u = 0; u < 8; u++)
                Psh[warp][k][u * 32 + lane] = e[u] * mult;
            __syncwarp();

            const float4* P4 = (const float4*)Psh[warp][k];
            float4* ks4 = (float4*)(ks_out + ((((size_t)(b * Hx + h) * Sx + i) * NKx + n) << 8));
            ks4[lane] = P4[lane];
            ks4[32 + lane] = P4[32 + lane];
        }

        float a0 = 0.f, a1 = 0.f;
        for (int j = half; j < i1; j += 2) {
            float v = Vsh[j * DKx + d0];
            a0 = fmaf(Psh[warp][0][j], v, a0);
            a1 = fmaf(Psh[warp][1][j], v, a1);
        }
        a0 += __shfl_down_sync(0xffffffffu, a0, 16);
        a1 += __shfl_down_sync(0xffffffffu, a1, 16);
        if (lane < 16) {
            int i0 = i1 - 8;
            cat4[((size_t)bn * Sx + i0) * Dx + h * DKx + d0] = a0;
            cat4[((size_t)bn * Sx + i1) * Dx + h * DKx + d0] = a1;
        }
        __syncwarp();
    }
}

// ---------------- launch ----------------
extern "C" void kernel_launch(void* const* d_in, const int* in_sizes, int n_in,
                              void* d_out, int out_size) {
    (void)in_sizes; (void)n_in; (void)out_size;
    const float* q_emb  = (const float*)d_in[0];
    const float* s_emb  = (const float*)d_in[1];
    const float* b1_Wq  = (const float*)d_in[3];
    const float* b1_bq  = (const float*)d_in[4];
    const float* b1_Wv  = (const float*)d_in[5];
    const float* b1_bv  = (const float*)d_in[6];
    const float* b1_Wo  = (const float*)d_in[7];
    const float* b1_bo  = (const float*)d_in[8];
    const float* b1_gam = (const float*)d_in[9];
    const float* b1_lng = (const float*)d_in[10];
    const float* b1_lnb = (const float*)d_in[11];
    const float* b4_Wq  = (const float*)d_in[12];
    const float* b4_bq  = (const float*)d_in[13];
    const float* b4_Wk  = (const float*)d_in[14];
    const float* b4_bk  = (const float*)d_in[15];
    const float* b4_Wv  = (const float*)d_in[16];
    const float* b4_bv  = (const float*)d_in[17];
    const float* b4_Wo  = (const float*)d_in[18];
    const float* b4_bo  = (const float*)d_in[19];
    const float* b4_gam = (const float*)d_in[20];
    const float* b4_lng = (const float*)d_in[21];
    const float* b4_lnb = (const float*)d_in[22];
    const float* know   = (const float*)d_in[23];

    float* z_out  = (float*)d_out;
    float* qs_out = z_out + (size_t)BSx * Sx * NKx * Dx;
    float* ks_out = qs_out + (size_t)BSx * Hx * Sx * Sx;

    float *Q1, *V1, *cat1, *q4, *k4, *v4, *cat4, *WT;
    cudaGetSymbolAddress((void**)&Q1,   d_Q1);
    cudaGetSymbolAddress((void**)&V1,   d_V1);
    cudaGetSymbolAddress((void**)&cat1, d_cat1);
    cudaGetSymbolAddress((void**)&q4,   d_q4);
    cudaGetSymbolAddress((void**)&k4,   d_k4);
    cudaGetSymbolAddress((void**)&v4,   d_v4);
    cudaGetSymbolAddress((void**)&cat4, d_cat4);
    cudaGetSymbolAddress((void**)&WT,   d_WT);

    // WT slots: 0=b1_Wq 1=b1_Wv 2=b1_Wo 3=b4_Wq 4=b4_Wk 5=b4_Wv 6=b4_Wo
    transpose_all<<<dim3(8, 8, 7), dim3(16, 16)>>>(b1_Wq, b1_Wv, b1_Wo, b4_Wq, b4_Wk, b4_Wv, b4_Wo, WT);

    proj_batch<<<dim3(64, 4), 256>>>(q_emb, s_emb, know, WT,
                                     b1_bq, b1_bv, b4_bk, b4_bq,
                                     Q1, V1, k4, q4);

    attn1_kernel<<<dim3(Sx / 8, Hx, BSx), 256>>>(Q1, V1, b1_gam, qs_out, cat1);

    oproj_ln1_v4<<<64, 256>>>(cat1, WT + 2 * 16384, b1_bo, q_emb, b1_lng, b1_lnb,
                              WT + 5 * 16384, b4_bv, v4);

    attn4_kernel<<<dim3(BSx * NKx, Hx), 256>>>(q4, k4, v4, b4_gam, ks_out, cat4);

    oproj_ln4_k<<<512, 256>>>(cat4, WT + 6 * 16384, b4_bo, know, b4_lng, b4_lnb, z_out);
}

// round 6
// speedup vs baseline: 1.8570x; 1.1733x over previous
#include <cuda_runtime.h>
#include <math.h>
#include <stdint.h>

#define Sx   256
#define Dx   128
#define Hx   8
#define DKx  16
#define NKx  16
#define BSx  4

typedef unsigned long long u64;

// ---------------- scratch ----------------
__device__ float d_Q1[BSx * Sx * Dx];
__device__ float d_V1[BSx * Sx * Dx];
__device__ float d_cat1[BSx * Sx * Dx];
__device__ float d_q4[NKx * Dx];
__device__ float d_k4[BSx * Sx * Dx];
__device__ float d_v4[BSx * Sx * Dx];
__device__ float d_cat4[BSx * NKx * Sx * Dx];
__device__ float d_WT[7][Dx * Dx];

// ---------------- helpers ----------------
__device__ __forceinline__ float warp_max(float v) {
#pragma unroll
    for (int o = 16; o; o >>= 1) v = fmaxf(v, __shfl_xor_sync(0xffffffffu, v, o));
    return v;
}
__device__ __forceinline__ float warp_sum(float v) {
#pragma unroll
    for (int o = 16; o; o >>= 1) v += __shfl_xor_sync(0xffffffffu, v, o);
    return v;
}
__device__ __forceinline__ float rcp_ap(float x) {
    float r; asm("rcp.approx.f32 %0, %1;" : "=f"(r) : "f"(x)); return r;
}
__device__ __forceinline__ float sqrt_ap(float x) {
    float r; asm("sqrt.approx.f32 %0, %1;" : "=f"(r) : "f"(x)); return r;
}
__device__ __forceinline__ float ex2_ap(float x) {
    float r; asm("ex2.approx.f32 %0, %1;" : "=f"(r) : "f"(x)); return r;
}
__device__ __forceinline__ u64 pk2(float x) {
    u64 r; asm("mov.b64 %0, {%1, %1};" : "=l"(r) : "f"(x)); return r;
}
__device__ __forceinline__ void ffma2(u64& d, u64 a, u64 b) {
    asm("fma.rn.f32x2 %0, %1, %2, %0;" : "+l"(d) : "l"(a), "l"(b));
}
__device__ __forceinline__ float2 up2(u64 v) {
    float2 f; asm("mov.b64 {%0, %1}, %2;" : "=f"(f.x), "=f"(f.y) : "l"(v)); return f;
}
__device__ __forceinline__ float4 unpack_acc(u64 lo, u64 hi) {
    float2 a = up2(lo), b = up2(hi);
    return make_float4(a.x, a.y, b.x, b.y);
}
__device__ __forceinline__ float4 add4(float4 a, float4 b) {
    return make_float4(a.x + b.x, a.y + b.y, a.z + b.z, a.w + b.w);
}

#define LN2I 1.442695041f

// ---------------- transpose all 7 weights ----------------
__global__ void transpose_all(const float* __restrict__ s0, const float* __restrict__ s1,
                              const float* __restrict__ s2, const float* __restrict__ s3,
                              const float* __restrict__ s4, const float* __restrict__ s5,
                              const float* __restrict__ s6, float* __restrict__ dst) {
    const float* srcs[7] = {s0, s1, s2, s3, s4, s5, s6};
    __shared__ float t[16][17];
    const float* W = srcs[blockIdx.z];
    float* Wt = dst + (size_t)blockIdx.z * Dx * Dx;
    int bx = blockIdx.x * 16, by = blockIdx.y * 16;
    int x = threadIdx.x, y = threadIdx.y;
    t[y][x] = W[(by + y) * Dx + bx + x];
    __syncthreads();
    Wt[(bx + y) * Dx + by + x] = t[x][y];
}

// ---------------- K-chunk partial for 4 rows: chunk kp (32 K-values) ----------------
// X4: base of row group (rows stride 32 float4). out[r] = partial for row r, cols 4*lane..4*lane+3
__device__ __forceinline__ void gemm_part_r4(const float4* __restrict__ X4,
                                             const float* __restrict__ Wt,
                                             int kp, int lane, float4 out[4]) {
    u64 aL[4] = {0ull, 0ull, 0ull, 0ull}, aH[4] = {0ull, 0ull, 0ull, 0ull};
    const ulonglong2* W2 = (const ulonglong2*)(Wt + kp * 32 * Dx);
#pragma unroll
    for (int c = 0; c < 8; c++) {
        ulonglong2 w0 = W2[(4 * c + 0) * 32 + lane];
        ulonglong2 w1 = W2[(4 * c + 1) * 32 + lane];
        ulonglong2 w2 = W2[(4 * c + 2) * 32 + lane];
        ulonglong2 w3 = W2[(4 * c + 3) * 32 + lane];
#pragma unroll
        for (int r = 0; r < 4; r++) {
            float4 xv = X4[r * 32 + kp * 8 + c];
            u64 p0 = pk2(xv.x), p1 = pk2(xv.y), p2 = pk2(xv.z), p3 = pk2(xv.w);
            ffma2(aL[r], p0, w0.x); ffma2(aH[r], p0, w0.y);
            ffma2(aL[r], p1, w1.x); ffma2(aH[r], p1, w1.y);
            ffma2(aL[r], p2, w2.x); ffma2(aH[r], p2, w2.y);
            ffma2(aL[r], p3, w3.x); ffma2(aH[r], p3, w3.y);
        }
    }
#pragma unroll
    for (int r = 0; r < 4; r++) out[r] = unpack_acc(aL[r], aH[r]);
}

// ---------------- LN over a float4-per-lane row (warp-collective) ----------------
__device__ __forceinline__ float4 ln_row(float4 hv, const float4& g4, const float4& b4) {
    float s = hv.x + hv.y + hv.z + hv.w;
    s = warp_sum(s);
    float mean = s * 0.0078125f;
    float4 dv = {hv.x - mean, hv.y - mean, hv.z - mean, hv.w - mean};
    float vs = dv.x * dv.x + dv.y * dv.y + dv.z * dv.z + dv.w * dv.w;
    vs = warp_sum(vs);
    float rstd = rsqrtf(vs * 0.0078125f + 1e-5f);
    float4 o = {dv.x * rstd * g4.x + b4.x, dv.y * rstd * g4.y + b4.y,
                dv.z * rstd * g4.z + b4.z, dv.w * rstd * g4.w + b4.w};
    return o;
}

// ---------------- projections: Q1, V1, K4, Q4 — 16 rows/block, 512 thr ----------------
__global__ void proj_batch(const float* __restrict__ q_emb, const float* __restrict__ s_emb,
                           const float* __restrict__ know, const float* __restrict__ WT,
                           const float* __restrict__ bq1, const float* __restrict__ bv1,
                           const float* __restrict__ bk4, const float* __restrict__ bq4,
                           float* __restrict__ Q1, float* __restrict__ V1,
                           float* __restrict__ K4, float* __restrict__ Q4) {
    const float* A; const float* Wt; const float* bias; float* C; int M;
    switch (blockIdx.y) {
        case 0:  A = q_emb; Wt = WT + 0 * 16384; bias = bq1; C = Q1; M = 1024; break;
        case 1:  A = s_emb; Wt = WT + 1 * 16384; bias = bv1; C = V1; M = 1024; break;
        case 2:  A = q_emb; Wt = WT + 4 * 16384; bias = bk4; C = K4; M = 1024; break;
        default: A = know;  Wt = WT + 3 * 16384; bias = bq4; C = Q4; M = 16;   break;
    }
    int row0 = blockIdx.x * 16;
    if (row0 >= M) return;
    __shared__ float4 Ps[16][4][32];
    int lane = threadIdx.x & 31, warp = threadIdx.x >> 5;
    int rg = warp >> 2, kp = warp & 3;
    float4 out[4];
    gemm_part_r4((const float4*)A + (size_t)(row0 + rg * 4) * 32, Wt, kp, lane, out);
#pragma unroll
    for (int r = 0; r < 4; r++) Ps[rg * 4 + r][kp][lane] = out[r];
    __syncthreads();
    float4 s = add4(add4(Ps[warp][0][lane], Ps[warp][1][lane]),
                    add4(Ps[warp][2][lane], Ps[warp][3][lane]));
    float4 b4 = ((const float4*)bias)[lane];
    ((float4*)C)[(size_t)(row0 + warp) * 32 + lane] = add4(s, b4);
}

// ---------------- block1 O-proj + residual + LN fused with V4 projection ----------------
__global__ void oproj_ln1_v4(const float* __restrict__ X, const float* __restrict__ WoT,
                             const float* __restrict__ bo, const float* __restrict__ res,
                             const float* __restrict__ lng, const float* __restrict__ lnb,
                             const float* __restrict__ WvT, const float* __restrict__ bv,
                             float* __restrict__ v4) {
    __shared__ float4 Ps[16][4][32];
    __shared__ float4 p_sm[16][32];
    int lane = threadIdx.x & 31, warp = threadIdx.x >> 5;
    int rg = warp >> 2, kp = warp & 3;
    int row0 = blockIdx.x * 16;
    // phase A: O-proj partials
    {
        float4 out[4];
        gemm_part_r4((const float4*)X + (size_t)(row0 + rg * 4) * 32, WoT, kp, lane, out);
#pragma unroll
        for (int r = 0; r < 4; r++) Ps[rg * 4 + r][kp][lane] = out[r];
    }
    __syncthreads();
    // phase B: reduce + bias + residual + LN -> p_sm (one warp per row)
    {
        float4 s = add4(add4(Ps[warp][0][lane], Ps[warp][1][lane]),
                        add4(Ps[warp][2][lane], Ps[warp][3][lane]));
        float4 bb = ((const float4*)bo)[lane];
        float4 rv = ((const float4*)res)[(size_t)(row0 + warp) * 32 + lane];
        float4 hv = {s.x + bb.x + rv.x, s.y + bb.y + rv.y,
                     s.z + bb.z + rv.z, s.w + bb.w + rv.w};
        float4 g4 = ((const float4*)lng)[lane];
        float4 b4 = ((const float4*)lnb)[lane];
        p_sm[warp][lane] = ln_row(hv, g4, b4);
    }
    __syncthreads();
    // phase C: V4 projection partials from p rows in smem
    {
        float4 out[4];
        gemm_part_r4((const float4*)p_sm + rg * 4 * 32, WvT, kp, lane, out);
#pragma unroll
        for (int r = 0; r < 4; r++) Ps[rg * 4 + r][kp][lane] = out[r];
    }
    __syncthreads();
    // phase D: reduce + bias -> v4
    {
        float4 s = add4(add4(Ps[warp][0][lane], Ps[warp][1][lane]),
                        add4(Ps[warp][2][lane], Ps[warp][3][lane]));
        float4 b4 = ((const float4*)bv)[lane];
        ((float4*)v4)[(size_t)(row0 + warp) * 32 + lane] = add4(s, b4);
    }
}

// ---------------- block4 O-proj + residual(know) + LN + scatter ----------------
__global__ void oproj_ln4_k(const float* __restrict__ X, const float* __restrict__ WoT,
                            const float* __restrict__ bo, const float* __restrict__ know,
                            const float* __restrict__ lng, const float* __restrict__ lnb,
                            float* __restrict__ z) {
    __shared__ float4 Ps[16][4][32];
    int lane = threadIdx.x & 31, warp = threadIdx.x >> 5;
    int rg = warp >> 2, kp = warp & 3;
    int row0 = blockIdx.x * 16;
    {
        float4 out[4];
        gemm_part_r4((const float4*)X + (size_t)(row0 + rg * 4) * 32, WoT, kp, lane, out);
#pragma unroll
        for (int r = 0; r < 4; r++) Ps[rg * 4 + r][kp][lane] = out[r];
    }
    __syncthreads();
    {
        int row = row0 + warp;                   // (b*NK+n)*S + s
        int bn = row >> 8, s = row & 255;
        int b = bn >> 4, n = bn & 15;
        float4 sm = add4(add4(Ps[warp][0][lane], Ps[warp][1][lane]),
                         add4(Ps[warp][2][lane], Ps[warp][3][lane]));
        float4 bb = ((const float4*)bo)[lane];
        float4 rv = ((const float4*)know)[n * 32 + lane];
        float4 hv = {sm.x + bb.x + rv.x, sm.y + bb.y + rv.y,
                     sm.z + bb.z + rv.z, sm.w + bb.w + rv.w};
        float4 g4 = ((const float4*)lng)[lane];
        float4 b4 = ((const float4*)lnb)[lane];
        ((float4*)z)[(((size_t)(b * Sx + s) * NKx) + n) * 32 + lane] = ln_row(hv, g4, b4);
    }
}

// ---------------- block1 attention: warp-per-row, no-max softmax ----------------
__global__ void attn1_kernel(const float* __restrict__ QK, const float* __restrict__ Vg,
                             const float* __restrict__ gamma,
                             float* __restrict__ q_scores, float* __restrict__ cat1) {
    __shared__ float Kd[DKx * Sx];   // [d][j]
    __shared__ float Vsh[Sx * DKx];  // [j][d]
    __shared__ float Psh[8][Sx];
    const int b = blockIdx.z, h = blockIdx.y;
    const int tid = threadIdx.x, lane = tid & 31, warp = tid >> 5;

    {
        const float* base = QK + ((size_t)b * Sx) * Dx + h * DKx;
        const float4* r = (const float4*)(base + (size_t)tid * Dx);
        float4 a0 = r[0], a1 = r[1], a2 = r[2], a3 = r[3];
        Kd[0*Sx+tid]=a0.x; Kd[1*Sx+tid]=a0.y; Kd[2*Sx+tid]=a0.z; Kd[3*Sx+tid]=a0.w;
        Kd[4*Sx+tid]=a1.x; Kd[5*Sx+tid]=a1.y; Kd[6*Sx+tid]=a1.z; Kd[7*Sx+tid]=a1.w;
        Kd[8*Sx+tid]=a2.x; Kd[9*Sx+tid]=a2.y; Kd[10*Sx+tid]=a2.z; Kd[11*Sx+tid]=a2.w;
        Kd[12*Sx+tid]=a3.x; Kd[13*Sx+tid]=a3.y; Kd[14*Sx+tid]=a3.z; Kd[15*Sx+tid]=a3.w;
    }
    {
        const float* base = Vg + ((size_t)b * Sx) * Dx + h * DKx;
        for (int idx = tid; idx < Sx * DKx; idx += 256) {
            int j = idx >> 4, d = idx & 15;
            Vsh[idx] = base[(size_t)j * Dx + d];
        }
    }
    __syncthreads();

    const float g2 = -fabsf(gamma[h]) * LN2I;
    const int i = blockIdx.x * 8 + warp;
    const int uMax = i >> 5;

    float q[16];
#pragma unroll
    for (int d = 0; d < 16; d++) q[d] = Kd[d * Sx + i];

    float sc2[8], ex[8];
    float sum = 0.f;
#pragma unroll
    for (int u = 0; u < 8; u++) {
        if (u <= uMax) {
            int j = u * 32 + lane;
            float s = 0.f;
#pragma unroll
            for (int d = 0; d < 16; d++) s = fmaf(q[d], Kd[d * Sx + j], s);
            sc2[u] = s * (0.25f * LN2I);
            float e = (j <= i) ? ex2_ap(sc2[u]) : 0.f;
            ex[u] = e;
            sum += e;
        } else { ex[u] = 0.f; sc2[u] = 0.f; }
    }
    sum = warp_sum(sum);
    float inv = rcp_ap(sum);

    float cum[8]; float carry = 0.f;
#pragma unroll
    for (int u = 0; u < 8; u++) {
        if (u <= uMax) {
            float x = ex[u] * inv;
#pragma unroll
            for (int off = 1; off < 32; off <<= 1) {
                float nv = __shfl_up_sync(0xffffffffu, x, off);
                if (lane >= off) x += nv;
            }
            float seg = __shfl_sync(0xffffffffu, x, 31);
            cum[u] = x + carry;
            carry += seg;
        } else cum[u] = 0.f;
    }
    const float total = carry;
    const float fi = (float)i;

    float sum2 = 0.f;
#pragma unroll
    for (int u = 0; u < 8; u++) {
        if (u <= uMax) {
            int j = u * 32 + lane;
            float pos = fabsf((float)j - fi);
            float dist = sqrt_ap(fmaxf((total - cum[u]) * pos, 0.f));
            float eff = fmaxf(ex2_ap(g2 * dist), 1e-5f);
            float e2 = (j <= i) ? ex2_ap(sc2[u] * eff) : 0.f;
            ex[u] = e2;
            sum2 += e2;
        }
    }
    sum2 = warp_sum(sum2);
    float inv2 = rcp_ap(sum2);

#pragma unroll
    for (int u = 0; u < 8; u++)
        Psh[warp][u * 32 + lane] = (u <= uMax) ? ex[u] * inv2 : 0.f;
    __syncwarp();

    {
        const float4* P4 = (const float4*)Psh[warp];
        float4* qs4 = (float4*)(q_scores + (((size_t)(b * Hx + h)) * Sx + i) * Sx);
        qs4[lane] = P4[lane];
        qs4[32 + lane] = P4[32 + lane];
    }

    float acc = 0.f;
    int d0 = lane & 15, half = lane >> 4;
    for (int j = half; j <= i; j += 2)
        acc = fmaf(Psh[warp][j], Vsh[j * DKx + d0], acc);
    acc += __shfl_down_sync(0xffffffffu, acc, 16);
    if (lane < 16)
        cat1[(((size_t)b * Sx) + i) * Dx + h * DKx + lane] = acc;
}

// ---------------- block4 attention: scan-free, no-max softmax2, fused maxout ----------------
__global__ void attn4_kernel(const float* __restrict__ q4g, const float* __restrict__ k4g,
                             const float* __restrict__ v4g, const float* __restrict__ gamma,
                             float* __restrict__ ks_out, float* __restrict__ cat4) {
    __shared__ float Vsh[Sx * DKx];
    __shared__ float sc2sh[Sx];
    __shared__ float Csh[Sx];
    __shared__ float Psh[8][2][Sx];
    __shared__ float redA[8], redB[8];

    const int bn = blockIdx.x, h = blockIdx.y;
    const int b = bn >> 4, n = bn & 15;
    const int tid = threadIdx.x, lane = tid & 31, warp = tid >> 5;

    {
        const float* vb = v4g + ((size_t)b * Sx) * Dx + h * DKx;
        for (int idx = tid; idx < Sx * DKx; idx += 256) {
            int j = idx >> 4, d = idx & 15;
            Vsh[idx] = vb[(size_t)j * Dx + d];
        }
    }
    {
        const float* qp = q4g + n * Dx + h * DKx;
        const float* kp = k4g + ((size_t)b * Sx + tid) * Dx + h * DKx;
        float s = 0.f;
#pragma unroll
        for (int d = 0; d < 16; d++) s = fmaf(qp[d], kp[d], s);
        float v = s * (0.25f * LN2I);
        sc2sh[tid] = v;
        float m = warp_max(v);
        if (lane == 0) redA[warp] = m;
        __syncthreads();
        float M = redA[0];
#pragma unroll
        for (int w = 1; w < 8; w++) M = fmaxf(M, redA[w]);
        float x = ex2_ap(v - M);
#pragma unroll
        for (int off = 1; off < 32; off <<= 1) {
            float nv = __shfl_up_sync(0xffffffffu, x, off);
            if (lane >= off) x += nv;
        }
        if (lane == 31) redB[warp] = x;
        __syncthreads();
        float carry = 0.f;
#pragma unroll
        for (int w = 0; w < 7; w++) if (w < warp) carry += redB[w];
        Csh[tid] = x + carry;
    }
    __syncthreads();

    const float g2 = -fabsf(gamma[h]) * LN2I;
    float sc2[8];
#pragma unroll
    for (int u = 0; u < 8; u++) sc2[u] = sc2sh[u * 32 + lane];

    const int d0 = lane & 15, half = lane >> 4;

    for (int gb = 0; gb < 16; ++gb) {
        const int i1 = warp + 8 * (2 * gb + 1);

        for (int k = 0; k < 2; ++k) {
            const int i = i1 - 8 + 8 * k;
            const int uMax = (i - 1) >> 5;
            const float invC = (i > 0) ? rcp_ap(Csh[i - 1]) : 0.f;
            const float fi = (float)i;

            float e[8], sum = 0.f, emax = 0.f;
#pragma unroll
            for (int u = 0; u < 8; u++) {
                if (u <= uMax) {
                    int j = u * 32 + lane;
                    float t = fmaf(-Csh[j], invC, 1.0f);
                    float pos = fabsf((float)j - fi);
                    float dist = sqrt_ap(fmaxf(t * pos, 0.f));
                    float eff = fmaxf(ex2_ap(g2 * dist), 1e-5f);
                    float ev = (j < i) ? ex2_ap(sc2[u] * eff) : 0.f;
                    e[u] = ev;
                    sum += ev;
                    emax = fmaxf(emax, ev);
                } else e[u] = 0.f;
            }
            sum = warp_sum(sum);
            emax = warp_max(emax);
            float mult = fminf(rcp_ap(fmaxf(emax, 1e-30f)),
                               5.f * rcp_ap(fmaxf(sum, 1e-30f)));
#pragma unroll
            for (int u = 0; u < 8; u++)
                Psh[warp][k][u * 32 + lane] = e[u] * mult;
            __syncwarp();

            const float4* P4 = (const float4*)Psh[warp][k];
            float4* ks4 = (float4*)(ks_out + ((((size_t)(b * Hx + h) * Sx + i) * NKx + n) << 8));
            ks4[lane] = P4[lane];
            ks4[32 + lane] = P4[32 + lane];
        }

        float a0 = 0.f, a1 = 0.f;
        for (int j = half; j < i1; j += 2) {
            float v = Vsh[j * DKx + d0];
            a0 = fmaf(Psh[warp][0][j], v, a0);
            a1 = fmaf(Psh[warp][1][j], v, a1);
        }
        a0 += __shfl_down_sync(0xffffffffu, a0, 16);
        a1 += __shfl_down_sync(0xffffffffu, a1, 16);
        if (lane < 16) {
            int i0 = i1 - 8;
            cat4[((size_t)bn * Sx + i0) * Dx + h * DKx + d0] = a0;
            cat4[((size_t)bn * Sx + i1) * Dx + h * DKx + d0] = a1;
        }
        __syncwarp();
    }
}

// ---------------- launch ----------------
extern "C" void kernel_launch(void* const* d_in, const int* in_sizes, int n_in,
                              void* d_out, int out_size) {
    (void)in_sizes; (void)n_in; (void)out_size;
    const float* q_emb  = (const float*)d_in[0];
    const float* s_emb  = (const float*)d_in[1];
    const float* b1_Wq  = (const float*)d_in[3];
    const float* b1_bq  = (const float*)d_in[4];
    const float* b1_Wv  = (const float*)d_in[5];
    const float* b1_bv  = (const float*)d_in[6];
    const float* b1_Wo  = (const float*)d_in[7];
    const float* b1_bo  = (const float*)d_in[8];
    const float* b1_gam = (const float*)d_in[9];
    const float* b1_lng = (const float*)d_in[10];
    const float* b1_lnb = (const float*)d_in[11];
    const float* b4_Wq  = (const float*)d_in[12];
    const float* b4_bq  = (const float*)d_in[13];
    const float* b4_Wk  = (const float*)d_in[14];
    const float* b4_bk  = (const float*)d_in[15];
    const float* b4_Wv  = (const float*)d_in[16];
    const float* b4_bv  = (const float*)d_in[17];
    const float* b4_Wo  = (const float*)d_in[18];
    const float* b4_bo  = (const float*)d_in[19];
    const float* b4_gam = (const float*)d_in[20];
    const float* b4_lng = (const float*)d_in[21];
    const float* b4_lnb = (const float*)d_in[22];
    const float* know   = (const float*)d_in[23];

    float* z_out  = (float*)d_out;
    float* qs_out = z_out + (size_t)BSx * Sx * NKx * Dx;
    float* ks_out = qs_out + (size_t)BSx * Hx * Sx * Sx;

    float *Q1, *V1, *cat1, *q4, *k4, *v4, *cat4, *WT;
    cudaGetSymbolAddress((void**)&Q1,   d_Q1);
    cudaGetSymbolAddress((void**)&V1,   d_V1);
    cudaGetSymbolAddress((void**)&cat1, d_cat1);
    cudaGetSymbolAddress((void**)&q4,   d_q4);
    cudaGetSymbolAddress((void**)&k4,   d_k4);
    cudaGetSymbolAddress((void**)&v4,   d_v4);
    cudaGetSymbolAddress((void**)&cat4, d_cat4);
    cudaGetSymbolAddress((void**)&WT,   d_WT);

    // WT slots: 0=b1_Wq 1=b1_Wv 2=b1_Wo 3=b4_Wq 4=b4_Wk 5=b4_Wv 6=b4_Wo
    transpose_all<<<dim3(8, 8, 7), dim3(16, 16)>>>(b1_Wq, b1_Wv, b1_Wo, b4_Wq, b4_Wk, b4_Wv, b4_Wo, WT);

    proj_batch<<<dim3(64, 4), 512>>>(q_emb, s_emb, know, WT,
                                     b1_bq, b1_bv, b4_bk, b4_bq,
                                     Q1, V1, k4, q4);

    attn1_kernel<<<dim3(Sx / 8, Hx, BSx), 256>>>(Q1, V1, b1_gam, qs_out, cat1);

    oproj_ln1_v4<<<64, 512>>>(cat1, WT + 2 * 16384, b1_bo, q_emb, b1_lng, b1_lnb,
                              WT + 5 * 16384, b4_bv, v4);

    attn4_kernel<<<dim3(BSx * NKx, Hx), 256>>>(q4, k4, v4, b4_gam, ks_out, cat4);

    oproj_ln4_k<<<1024, 512>>>(cat4, WT + 6 * 16384, b4_bo, know, b4_lng, b4_lnb, z_out);
}

// round 7
// speedup vs baseline: 2.0141x; 1.0846x over previous
#include <cuda_runtime.h>
#include <math.h>
#include <stdint.h>

#define Sx   256
#define Dx   128
#define Hx   8
#define DKx  16
#define NKx  16
#define BSx  4

typedef unsigned long long u64;

// ---------------- scratch ----------------
__device__ float d_Q1[BSx * Sx * Dx];
__device__ float d_V1[BSx * Sx * Dx];
__device__ float d_cat1[BSx * Sx * Dx];
__device__ float d_q4[NKx * Dx];
__device__ float d_k4[BSx * Sx * Dx];
__device__ float d_v4[BSx * Sx * Dx];
__device__ float d_cat4[BSx * NKx * Sx * Dx];
__device__ float d_WT[7][Dx * Dx];

// ---------------- helpers ----------------
__device__ __forceinline__ float warp_max(float v) {
#pragma unroll
    for (int o = 16; o; o >>= 1) v = fmaxf(v, __shfl_xor_sync(0xffffffffu, v, o));
    return v;
}
__device__ __forceinline__ float warp_sum(float v) {
#pragma unroll
    for (int o = 16; o; o >>= 1) v += __shfl_xor_sync(0xffffffffu, v, o);
    return v;
}
__device__ __forceinline__ float rcp_ap(float x) {
    float r; asm("rcp.approx.f32 %0, %1;" : "=f"(r) : "f"(x)); return r;
}
__device__ __forceinline__ float sqrt_ap(float x) {
    float r; asm("sqrt.approx.f32 %0, %1;" : "=f"(r) : "f"(x)); return r;
}
__device__ __forceinline__ float ex2_ap(float x) {
    float r; asm("ex2.approx.f32 %0, %1;" : "=f"(r) : "f"(x)); return r;
}
__device__ __forceinline__ u64 pk2(float x) {
    u64 r; asm("mov.b64 %0, {%1, %1};" : "=l"(r) : "f"(x)); return r;
}
__device__ __forceinline__ void ffma2(u64& d, u64 a, u64 b) {
    asm("fma.rn.f32x2 %0, %1, %2, %0;" : "+l"(d) : "l"(a), "l"(b));
}
__device__ __forceinline__ u64 addf2(u64 a, u64 b) {
    u64 r; asm("add.rn.f32x2 %0, %1, %2;" : "=l"(r) : "l"(a), "l"(b)); return r;
}
__device__ __forceinline__ float2 up2(u64 v) {
    float2 f; asm("mov.b64 {%0, %1}, %2;" : "=f"(f.x), "=f"(f.y) : "l"(v)); return f;
}
__device__ __forceinline__ float4 unpack_acc(u64 lo, u64 hi) {
    float2 a = up2(lo), b = up2(hi);
    return make_float4(a.x, a.y, b.x, b.y);
}
__device__ __forceinline__ float4 add4(float4 a, float4 b) {
    return make_float4(a.x + b.x, a.y + b.y, a.z + b.z, a.w + b.w);
}

#define LN2I 1.442695041f

// ---------------- transpose all 7 weights ----------------
__global__ void transpose_all(const float* __restrict__ s0, const float* __restrict__ s1,
                              const float* __restrict__ s2, const float* __restrict__ s3,
                              const float* __restrict__ s4, const float* __restrict__ s5,
                              const float* __restrict__ s6, float* __restrict__ dst) {
    const float* srcs[7] = {s0, s1, s2, s3, s4, s5, s6};
    __shared__ float t[16][17];
    const float* W = srcs[blockIdx.z];
    float* Wt = dst + (size_t)blockIdx.z * Dx * Dx;
    int bx = blockIdx.x * 16, by = blockIdx.y * 16;
    int x = threadIdx.x, y = threadIdx.y;
    t[y][x] = W[(by + y) * Dx + bx + x];
    __syncthreads();
    Wt[(bx + y) * Dx + by + x] = t[x][y];
}

// ---------------- K-chunk partial for 4 rows ----------------
__device__ __forceinline__ void gemm_part_r4(const float4* __restrict__ X4,
                                             const float* __restrict__ Wt,
                                             int kp, int lane, float4 out[4]) {
    u64 aL[4] = {0ull, 0ull, 0ull, 0ull}, aH[4] = {0ull, 0ull, 0ull, 0ull};
    const ulonglong2* W2 = (const ulonglong2*)(Wt + kp * 32 * Dx);
#pragma unroll
    for (int c = 0; c < 8; c++) {
        ulonglong2 w0 = W2[(4 * c + 0) * 32 + lane];
        ulonglong2 w1 = W2[(4 * c + 1) * 32 + lane];
        ulonglong2 w2 = W2[(4 * c + 2) * 32 + lane];
        ulonglong2 w3 = W2[(4 * c + 3) * 32 + lane];
#pragma unroll
        for (int r = 0; r < 4; r++) {
            float4 xv = X4[r * 32 + kp * 8 + c];
            u64 p0 = pk2(xv.x), p1 = pk2(xv.y), p2 = pk2(xv.z), p3 = pk2(xv.w);
            ffma2(aL[r], p0, w0.x); ffma2(aH[r], p0, w0.y);
            ffma2(aL[r], p1, w1.x); ffma2(aH[r], p1, w1.y);
            ffma2(aL[r], p2, w2.x); ffma2(aH[r], p2, w2.y);
            ffma2(aL[r], p3, w3.x); ffma2(aH[r], p3, w3.y);
        }
    }
#pragma unroll
    for (int r = 0; r < 4; r++) out[r] = unpack_acc(aL[r], aH[r]);
}

// ---------------- K-chunk partial for 8 rows ----------------
__device__ __forceinline__ void gemm_part_r8(const float4* __restrict__ X4,
                                             const float* __restrict__ Wt,
                                             int kp, int lane, float4 out[8]) {
    u64 aL[8], aH[8];
#pragma unroll
    for (int r = 0; r < 8; r++) { aL[r] = 0ull; aH[r] = 0ull; }
    const ulonglong2* W2 = (const ulonglong2*)(Wt + kp * 32 * Dx);
#pragma unroll
    for (int c = 0; c < 8; c++) {
        ulonglong2 w0 = W2[(4 * c + 0) * 32 + lane];
        ulonglong2 w1 = W2[(4 * c + 1) * 32 + lane];
        ulonglong2 w2 = W2[(4 * c + 2) * 32 + lane];
        ulonglong2 w3 = W2[(4 * c + 3) * 32 + lane];
#pragma unroll
        for (int r = 0; r < 8; r++) {
            float4 xv = X4[r * 32 + kp * 8 + c];
            u64 p0 = pk2(xv.x), p1 = pk2(xv.y), p2 = pk2(xv.z), p3 = pk2(xv.w);
            ffma2(aL[r], p0, w0.x); ffma2(aH[r], p0, w0.y);
            ffma2(aL[r], p1, w1.x); ffma2(aH[r], p1, w1.y);
            ffma2(aL[r], p2, w2.x); ffma2(aH[r], p2, w2.y);
            ffma2(aL[r], p3, w3.x); ffma2(aH[r], p3, w3.y);
        }
    }
#pragma unroll
    for (int r = 0; r < 8; r++) out[r] = unpack_acc(aL[r], aH[r]);
}

// ---------------- LN over a float4-per-lane row (warp-collective) ----------------
__device__ __forceinline__ float4 ln_row(float4 hv, const float4& g4, const float4& b4) {
    float s = hv.x + hv.y + hv.z + hv.w;
    s = warp_sum(s);
    float mean = s * 0.0078125f;
    float4 dv = {hv.x - mean, hv.y - mean, hv.z - mean, hv.w - mean};
    float vs = dv.x * dv.x + dv.y * dv.y + dv.z * dv.z + dv.w * dv.w;
    vs = warp_sum(vs);
    float rstd = rsqrtf(vs * 0.0078125f + 1e-5f);
    float4 o = {dv.x * rstd * g4.x + b4.x, dv.y * rstd * g4.y + b4.y,
                dv.z * rstd * g4.z + b4.z, dv.w * rstd * g4.w + b4.w};
    return o;
}

// ---------------- projections: Q1, V1, K4, Q4 — 16 rows/block, 512 thr ----------------
__global__ void proj_batch(const float* __restrict__ q_emb, const float* __restrict__ s_emb,
                           const float* __restrict__ know, const float* __restrict__ WT,
                           const float* __restrict__ bq1, const float* __restrict__ bv1,
                           const float* __restrict__ bk4, const float* __restrict__ bq4,
                           float* __restrict__ Q1, float* __restrict__ V1,
                           float* __restrict__ K4, float* __restrict__ Q4) {
    const float* A; const float* Wt; const float* bias; float* C; int M;
    switch (blockIdx.y) {
        case 0:  A = q_emb; Wt = WT + 0 * 16384; bias = bq1; C = Q1; M = 1024; break;
        case 1:  A = s_emb; Wt = WT + 1 * 16384; bias = bv1; C = V1; M = 1024; break;
        case 2:  A = q_emb; Wt = WT + 4 * 16384; bias = bk4; C = K4; M = 1024; break;
        default: A = know;  Wt = WT + 3 * 16384; bias = bq4; C = Q4; M = 16;   break;
    }
    int row0 = blockIdx.x * 16;
    if (row0 >= M) return;
    __shared__ float4 Ps[16][4][32];
    int lane = threadIdx.x & 31, warp = threadIdx.x >> 5;
    int rg = warp >> 2, kp = warp & 3;
    float4 out[4];
    gemm_part_r4((const float4*)A + (size_t)(row0 + rg * 4) * 32, Wt, kp, lane, out);
#pragma unroll
    for (int r = 0; r < 4; r++) Ps[rg * 4 + r][kp][lane] = out[r];
    __syncthreads();
    float4 s = add4(add4(Ps[warp][0][lane], Ps[warp][1][lane]),
                    add4(Ps[warp][2][lane], Ps[warp][3][lane]));
    float4 b4 = ((const float4*)bias)[lane];
    ((float4*)C)[(size_t)(row0 + warp) * 32 + lane] = add4(s, b4);
}

// ---------------- block1 O-proj + residual + LN fused with V4 projection ----------------
__global__ void oproj_ln1_v4(const float* __restrict__ X, const float* __restrict__ WoT,
                             const float* __restrict__ bo, const float* __restrict__ res,
                             const float* __restrict__ lng, const float* __restrict__ lnb,
                             const float* __restrict__ WvT, const float* __restrict__ bv,
                             float* __restrict__ v4) {
    __shared__ float4 Ps[16][4][32];
    __shared__ float4 p_sm[16][32];
    int lane = threadIdx.x & 31, warp = threadIdx.x >> 5;
    int rg = warp >> 2, kp = warp & 3;
    int row0 = blockIdx.x * 16;
    {
        float4 out[4];
        gemm_part_r4((const float4*)X + (size_t)(row0 + rg * 4) * 32, WoT, kp, lane, out);
#pragma unroll
        for (int r = 0; r < 4; r++) Ps[rg * 4 + r][kp][lane] = out[r];
    }
    __syncthreads();
    {
        float4 s = add4(add4(Ps[warp][0][lane], Ps[warp][1][lane]),
                        add4(Ps[warp][2][lane], Ps[warp][3][lane]));
        float4 bb = ((const float4*)bo)[lane];
        float4 rv = ((const float4*)res)[(size_t)(row0 + warp) * 32 + lane];
        float4 hv = {s.x + bb.x + rv.x, s.y + bb.y + rv.y,
                     s.z + bb.z + rv.z, s.w + bb.w + rv.w};
        float4 g4 = ((const float4*)lng)[lane];
        float4 b4 = ((const float4*)lnb)[lane];
        p_sm[warp][lane] = ln_row(hv, g4, b4);
    }
    __syncthreads();
    {
        float4 out[4];
        gemm_part_r4((const float4*)p_sm + rg * 4 * 32, WvT, kp, lane, out);
#pragma unroll
        for (int r = 0; r < 4; r++) Ps[rg * 4 + r][kp][lane] = out[r];
    }
    __syncthreads();
    {
        float4 s = add4(add4(Ps[warp][0][lane], Ps[warp][1][lane]),
                        add4(Ps[warp][2][lane], Ps[warp][3][lane]));
        float4 b4 = ((const float4*)bv)[lane];
        ((float4*)v4)[(size_t)(row0 + warp) * 32 + lane] = add4(s, b4);
    }
}

// ---------------- block4 O-proj + residual(know) + LN + scatter: 8 rows/warp ----------------
__global__ void __launch_bounds__(256) oproj_ln4_k(
        const float* __restrict__ X, const float* __restrict__ WoT,
        const float* __restrict__ bo, const float* __restrict__ know,
        const float* __restrict__ lng, const float* __restrict__ lnb,
        float* __restrict__ z) {
    __shared__ float4 Ps[16][4][32];     // 32KB
    int lane = threadIdx.x & 31, warp = threadIdx.x >> 5;   // 8 warps
    int rg = warp >> 2, kp = warp & 3;                      // rg 0..1
    int row0 = blockIdx.x * 16;
    {
        float4 out[8];
        gemm_part_r8((const float4*)X + (size_t)(row0 + rg * 8) * 32, WoT, kp, lane, out);
#pragma unroll
        for (int r = 0; r < 8; r++) Ps[rg * 8 + r][kp][lane] = out[r];
    }
    __syncthreads();
#pragma unroll
    for (int rr = 0; rr < 2; rr++) {
        int lrow = warp * 2 + rr;
        int row = row0 + lrow;                   // (b*NK+n)*S + s
        int bn = row >> 8, s = row & 255;
        int b = bn >> 4, n = bn & 15;
        float4 sm = add4(add4(Ps[lrow][0][lane], Ps[lrow][1][lane]),
                         add4(Ps[lrow][2][lane], Ps[lrow][3][lane]));
        float4 bb = ((const float4*)bo)[lane];
        float4 rv = ((const float4*)know)[n * 32 + lane];
        float4 hv = {sm.x + bb.x + rv.x, sm.y + bb.y + rv.y,
                     sm.z + bb.z + rv.z, sm.w + bb.w + rv.w};
        float4 g4 = ((const float4*)lng)[lane];
        float4 b4 = ((const float4*)lnb)[lane];
        ((float4*)z)[(((size_t)(b * Sx + s) * NKx) + n) * 32 + lane] = ln_row(hv, g4, b4);
    }
}

// ---------------- block1 attention: warp-per-row, packed PV ----------------
__global__ void attn1_kernel(const float* __restrict__ QK, const float* __restrict__ Vg,
                             const float* __restrict__ gamma,
                             float* __restrict__ q_scores, float* __restrict__ cat1) {
    __shared__ float Kd[DKx * Sx];   // [d][j]
    __shared__ float Vsh[Sx * DKx];  // [j][d]
    __shared__ float Psh[8][Sx];
    const int b = blockIdx.z, h = blockIdx.y;
    const int tid = threadIdx.x, lane = tid & 31, warp = tid >> 5;

    {
        const float* base = QK + ((size_t)b * Sx) * Dx + h * DKx;
        const float4* r = (const float4*)(base + (size_t)tid * Dx);
        float4 a0 = r[0], a1 = r[1], a2 = r[2], a3 = r[3];
        Kd[0*Sx+tid]=a0.x; Kd[1*Sx+tid]=a0.y; Kd[2*Sx+tid]=a0.z; Kd[3*Sx+tid]=a0.w;
        Kd[4*Sx+tid]=a1.x; Kd[5*Sx+tid]=a1.y; Kd[6*Sx+tid]=a1.z; Kd[7*Sx+tid]=a1.w;
        Kd[8*Sx+tid]=a2.x; Kd[9*Sx+tid]=a2.y; Kd[10*Sx+tid]=a2.z; Kd[11*Sx+tid]=a2.w;
        Kd[12*Sx+tid]=a3.x; Kd[13*Sx+tid]=a3.y; Kd[14*Sx+tid]=a3.z; Kd[15*Sx+tid]=a3.w;
    }
    {
        const float* base = Vg + ((size_t)b * Sx) * Dx + h * DKx;
        for (int idx = tid; idx < Sx * DKx; idx += 256) {
            int j = idx >> 4, d = idx & 15;
            Vsh[idx] = base[(size_t)j * Dx + d];
        }
    }
    __syncthreads();

    const float g2 = -fabsf(gamma[h]) * LN2I;
    const int i = blockIdx.x * 8 + warp;
    const int uMax = i >> 5;

    float q[16];
#pragma unroll
    for (int d = 0; d < 16; d++) q[d] = Kd[d * Sx + i];

    float sc2[8], ex[8];
    float sum = 0.f;
#pragma unroll
    for (int u = 0; u < 8; u++) {
        if (u <= uMax) {
            int j = u * 32 + lane;
            float s = 0.f;
#pragma unroll
            for (int d = 0; d < 16; d++) s = fmaf(q[d], Kd[d * Sx + j], s);
            sc2[u] = s * (0.25f * LN2I);
            float e = (j <= i) ? ex2_ap(sc2[u]) : 0.f;
            ex[u] = e;
            sum += e;
        } else { ex[u] = 0.f; sc2[u] = 0.f; }
    }
    sum = warp_sum(sum);
    float inv = rcp_ap(sum);

    float cum[8]; float carry = 0.f;
#pragma unroll
    for (int u = 0; u < 8; u++) {
        if (u <= uMax) {
            float x = ex[u] * inv;
#pragma unroll
            for (int off = 1; off < 32; off <<= 1) {
                float nv = __shfl_up_sync(0xffffffffu, x, off);
                if (lane >= off) x += nv;
            }
            float seg = __shfl_sync(0xffffffffu, x, 31);
            cum[u] = x + carry;
            carry += seg;
        } else cum[u] = 0.f;
    }
    const float total = carry;
    const float fi = (float)i;

    float sum2 = 0.f;
#pragma unroll
    for (int u = 0; u < 8; u++) {
        if (u <= uMax) {
            int j = u * 32 + lane;
            float pos = fabsf((float)j - fi);
            float dist = sqrt_ap(fmaxf((total - cum[u]) * pos, 0.f));
            float eff = ex2_ap(g2 * dist);
            float e2 = (j <= i) ? ex2_ap(sc2[u] * eff) : 0.f;
            ex[u] = e2;
            sum2 += e2;
        }
    }
    sum2 = warp_sum(sum2);
    float inv2 = rcp_ap(sum2);

#pragma unroll
    for (int u = 0; u < 8; u++)
        Psh[warp][u * 32 + lane] = (u <= uMax) ? ex[u] * inv2 : 0.f;
    __syncwarp();

    {
        const float4* P4 = (const float4*)Psh[warp];
        float4* qs4 = (float4*)(q_scores + (((size_t)(b * Hx + h)) * Sx + i) * Sx);
        qs4[lane] = P4[lane];
        qs4[32 + lane] = P4[32 + lane];
    }

    // packed PV: lane = jq(0..3) x dp(0..7)
    const int jq = lane >> 3, dp = lane & 7;
    u64 acc = 0ull;
    const int njj = (i + 4) >> 2;       // covers j <= i; beyond is zeros
    const float* Pr = Psh[warp];
    for (int jj = 0; jj < njj; jj++) {
        int j = jj * 4 + jq;
        u64 v2 = *(const u64*)(Vsh + j * DKx + dp * 2);
        u64 p = pk2(Pr[j]);
        ffma2(acc, p, v2);
    }
    acc = addf2(acc, __shfl_xor_sync(0xffffffffu, acc, 8));
    acc = addf2(acc, __shfl_xor_sync(0xffffffffu, acc, 16));
    if (lane < 8) {
        float2 r = up2(acc);
        *(float2*)(cat1 + (((size_t)b * Sx) + i) * Dx + h * DKx + dp * 2) = r;
    }
}

// ---------------- block4 attention: scan-free, packed PV ----------------
__global__ void attn4_kernel(const float* __restrict__ q4g, const float* __restrict__ k4g,
                             const float* __restrict__ v4g, const float* __restrict__ gamma,
                             float* __restrict__ ks_out, float* __restrict__ cat4) {
    __shared__ float Vsh[Sx * DKx];
    __shared__ float sc2sh[Sx];
    __shared__ float Csh[Sx];
    __shared__ float Psh[8][2][Sx];
    __shared__ float redA[8], redB[8];

    const int bn = blockIdx.x, h = blockIdx.y;
    const int b = bn >> 4, n = bn & 15;
    const int tid = threadIdx.x, lane = tid & 31, warp = tid >> 5;

    {
        const float* vb = v4g + ((size_t)b * Sx) * Dx + h * DKx;
        for (int idx = tid; idx < Sx * DKx; idx += 256) {
            int j = idx >> 4, d = idx & 15;
            Vsh[idx] = vb[(size_t)j * Dx + d];
        }
    }
    {
        const float* qp = q4g + n * Dx + h * DKx;
        const float* kp = k4g + ((size_t)b * Sx + tid) * Dx + h * DKx;
        float s = 0.f;
#pragma unroll
        for (int d = 0; d < 16; d++) s = fmaf(qp[d], kp[d], s);
        float v = s * (0.25f * LN2I);
        sc2sh[tid] = v;
        float m = warp_max(v);
        if (lane == 0) redA[warp] = m;
        __syncthreads();
        float M = redA[0];
#pragma unroll
        for (int w = 1; w < 8; w++) M = fmaxf(M, redA[w]);
        float x = ex2_ap(v - M);
#pragma unroll
        for (int off = 1; off < 32; off <<= 1) {
            float nv = __shfl_up_sync(0xffffffffu, x, off);
            if (lane >= off) x += nv;
        }
        if (lane == 31) redB[warp] = x;
        __syncthreads();
        float carry = 0.f;
#pragma unroll
        for (int w = 0; w < 7; w++) if (w < warp) carry += redB[w];
        Csh[tid] = x + carry;
    }
    __syncthreads();

    const float g2 = -fabsf(gamma[h]) * LN2I;
    float sc2[8];
#pragma unroll
    for (int u = 0; u < 8; u++) sc2[u] = sc2sh[u * 32 + lane];

    const int jq = lane >> 3, dp = lane & 7;

    for (int gb = 0; gb < 16; ++gb) {
        const int i1 = warp + 8 * (2 * gb + 1);

        for (int k = 0; k < 2; ++k) {
            const int i = i1 - 8 + 8 * k;
            const int uMax = (i - 1) >> 5;
            const float invC = (i > 0) ? rcp_ap(Csh[i - 1]) : 0.f;
            const float fi = (float)i;

            float e[8], sum = 0.f, emax = 0.f;
#pragma unroll
            for (int u = 0; u < 8; u++) {
                if (u <= uMax) {
                    int j = u * 32 + lane;
                    float t = fmaf(-Csh[j], invC, 1.0f);
                    float pos = fabsf((float)j - fi);
                    float dist = sqrt_ap(fmaxf(t * pos, 0.f));
                    float eff = ex2_ap(g2 * dist);
                    float ev = (j < i) ? ex2_ap(sc2[u] * eff) : 0.f;
                    e[u] = ev;
                    sum += ev;
                    emax = fmaxf(emax, ev);
                } else e[u] = 0.f;
            }
            sum = warp_sum(sum);
            emax = warp_max(emax);
            float mult = fminf(rcp_ap(fmaxf(emax, 1e-30f)),
                               5.f * rcp_ap(fmaxf(sum, 1e-30f)));
#pragma unroll
            for (int u = 0; u < 8; u++)
                Psh[warp][k][u * 32 + lane] = e[u] * mult;
            __syncwarp();

            const float4* P4 = (const float4*)Psh[warp][k];
            float4* ks4 = (float4*)(ks_out + ((((size_t)(b * Hx + h) * Sx + i) * NKx + n) << 8));
            ks4[lane] = P4[lane];
            ks4[32 + lane] = P4[32 + lane];
        }

        // packed PV for both rows; V LDS shared
        u64 a0 = 0ull, a1 = 0ull;
        const int njj = (i1 + 3) >> 2;    // P beyond i is zero
        const float* Pr0 = Psh[warp][0];
        const float* Pr1 = Psh[warp][1];
        for (int jj = 0; jj < njj; jj++) {
            int j = jj * 4 + jq;
            u64 v2 = *(const u64*)(Vsh + j * DKx + dp * 2);
            u64 p0 = pk2(Pr0[j]);
            u64 p1 = pk2(Pr1[j]);
            ffma2(a0, p0, v2);
            ffma2(a1, p1, v2);
        }
        a0 = addf2(a0, __shfl_xor_sync(0xffffffffu, a0, 8));
        a0 = addf2(a0, __shfl_xor_sync(0xffffffffu, a0, 16));
        a1 = addf2(a1, __shfl_xor_sync(0xffffffffu, a1, 8));
        a1 = addf2(a1, __shfl_xor_sync(0xffffffffu, a1, 16));
        if (lane < 8) {
            int i0 = i1 - 8;
            float2 r0 = up2(a0), r1 = up2(a1);
            *(float2*)(cat4 + ((size_t)bn * Sx + i0) * Dx + h * DKx + dp * 2) = r0;
            *(float2*)(cat4 + ((size_t)bn * Sx + i1) * Dx + h * DKx + dp * 2) = r1;
        }
        __syncwarp();
    }
}

// ---------------- launch ----------------
extern "C" void kernel_launch(void* const* d_in, const int* in_sizes, int n_in,
                              void* d_out, int out_size) {
    (void)in_sizes; (void)n_in; (void)out_size;
    const float* q_emb  = (const float*)d_in[0];
    const float* s_emb  = (const float*)d_in[1];
    const float* b1_Wq  = (const float*)d_in[3];
    const float* b1_bq  = (const float*)d_in[4];
    const float* b1_Wv  = (const float*)d_in[5];
    const float* b1_bv  = (const float*)d_in[6];
    const float* b1_Wo  = (const float*)d_in[7];
    const float* b1_bo  = (const float*)d_in[8];
    const float* b1_gam = (const float*)d_in[9];
    const float* b1_lng = (const float*)d_in[10];
    const float* b1_lnb = (const float*)d_in[11];
    const float* b4_Wq  = (const float*)d_in[12];
    const float* b4_bq  = (const float*)d_in[13];
    const float* b4_Wk  = (const float*)d_in[14];
    const float* b4_bk  = (const float*)d_in[15];
    const float* b4_Wv  = (const float*)d_in[16];
    const float* b4_bv  = (const float*)d_in[17];
    const float* b4_Wo  = (const float*)d_in[18];
    const float* b4_bo  = (const float*)d_in[19];
    const float* b4_gam = (const float*)d_in[20];
    const float* b4_lng = (const float*)d_in[21];
    const float* b4_lnb = (const float*)d_in[22];
    const float* know   = (const float*)d_in[23];

    float* z_out  = (float*)d_out;
    float* qs_out = z_out + (size_t)BSx * Sx * NKx * Dx;
    float* ks_out = qs_out + (size_t)BSx * Hx * Sx * Sx;

    float *Q1, *V1, *cat1, *q4, *k4, *v4, *cat4, *WT;
    cudaGetSymbolAddress((void**)&Q1,   d_Q1);
    cudaGetSymbolAddress((void**)&V1,   d_V1);
    cudaGetSymbolAddress((void**)&cat1, d_cat1);
    cudaGetSymbolAddress((void**)&q4,   d_q4);
    cudaGetSymbolAddress((void**)&k4,   d_k4);
    cudaGetSymbolAddress((void**)&v4,   d_v4);
    cudaGetSymbolAddress((void**)&cat4, d_cat4);
    cudaGetSymbolAddress((void**)&WT,   d_WT);

    // WT slots: 0=b1_Wq 1=b1_Wv 2=b1_Wo 3=b4_Wq 4=b4_Wk 5=b4_Wv 6=b4_Wo
    transpose_all<<<dim3(8, 8, 7), dim3(16, 16)>>>(b1_Wq, b1_Wv, b1_Wo, b4_Wq, b4_Wk, b4_Wv, b4_Wo, WT);

    proj_batch<<<dim3(64, 4), 512>>>(q_emb, s_emb, know, WT,
                                     b1_bq, b1_bv, b4_bk, b4_bq,
                                     Q1, V1, k4, q4);

    attn1_kernel<<<dim3(Sx / 8, Hx, BSx), 256>>>(Q1, V1, b1_gam, qs_out, cat1);

    oproj_ln1_v4<<<64, 512>>>(cat1, WT + 2 * 16384, b1_bo, q_emb, b1_lng, b1_lnb,
                              WT + 5 * 16384, b4_bv, v4);

    attn4_kernel<<<dim3(BSx * NKx, Hx), 256>>>(q4, k4, v4, b4_gam, ks_out, cat4);

    oproj_ln4_k<<<1024, 256>>>(cat4, WT + 6 * 16384, b4_bo, know, b4_lng, b4_lnb, z_out);
}

// round 8
// speedup vs baseline: 2.0266x; 1.0062x over previous
#include <cuda_runtime.h>
#include <math.h>
#include <stdint.h>

#define Sx   256
#define Dx   128
#define Hx   8
#define DKx  16
#define NKx  16
#define BSx  4

typedef unsigned long long u64;

// ---------------- scratch ----------------
__device__ float d_Q1[BSx * Sx * Dx];
__device__ float d_V1[BSx * Sx * Dx];
__device__ float d_cat1[BSx * Sx * Dx];
__device__ float d_q4[NKx * Dx];
__device__ float d_k4[BSx * Sx * Dx];
__device__ float d_v4[BSx * Sx * Dx];
__device__ float d_cat4[BSx * NKx * Sx * Dx];
__device__ float d_WT[7][Dx * Dx];

// ---------------- helpers ----------------
__device__ __forceinline__ float warp_max(float v) {
#pragma unroll
    for (int o = 16; o; o >>= 1) v = fmaxf(v, __shfl_xor_sync(0xffffffffu, v, o));
    return v;
}
__device__ __forceinline__ float warp_sum(float v) {
#pragma unroll
    for (int o = 16; o; o >>= 1) v += __shfl_xor_sync(0xffffffffu, v, o);
    return v;
}
__device__ __forceinline__ float rcp_ap(float x) {
    float r; asm("rcp.approx.f32 %0, %1;" : "=f"(r) : "f"(x)); return r;
}
__device__ __forceinline__ float sqrt_ap(float x) {
    float r; asm("sqrt.approx.f32 %0, %1;" : "=f"(r) : "f"(x)); return r;
}
__device__ __forceinline__ float ex2_ap(float x) {
    float r; asm("ex2.approx.f32 %0, %1;" : "=f"(r) : "f"(x)); return r;
}
__device__ __forceinline__ u64 pk2(float x) {
    u64 r; asm("mov.b64 %0, {%1, %1};" : "=l"(r) : "f"(x)); return r;
}
__device__ __forceinline__ void ffma2(u64& d, u64 a, u64 b) {
    asm("fma.rn.f32x2 %0, %1, %2, %0;" : "+l"(d) : "l"(a), "l"(b));
}
__device__ __forceinline__ u64 addf2(u64 a, u64 b) {
    u64 r; asm("add.rn.f32x2 %0, %1, %2;" : "=l"(r) : "l"(a), "l"(b)); return r;
}
__device__ __forceinline__ float2 up2(u64 v) {
    float2 f; asm("mov.b64 {%0, %1}, %2;" : "=f"(f.x), "=f"(f.y) : "l"(v)); return f;
}
__device__ __forceinline__ float4 unpack_acc(u64 lo, u64 hi) {
    float2 a = up2(lo), b = up2(hi);
    return make_float4(a.x, a.y, b.x, b.y);
}
__device__ __forceinline__ float4 add4(float4 a, float4 b) {
    return make_float4(a.x + b.x, a.y + b.y, a.z + b.z, a.w + b.w);
}

#define LN2I 1.442695041f

// ---------------- transpose all 7 weights ----------------
__global__ void transpose_all(const float* __restrict__ s0, const float* __restrict__ s1,
                              const float* __restrict__ s2, const float* __restrict__ s3,
                              const float* __restrict__ s4, const float* __restrict__ s5,
                              const float* __restrict__ s6, float* __restrict__ dst) {
    const float* srcs[7] = {s0, s1, s2, s3, s4, s5, s6};
    __shared__ float t[16][17];
    const float* W = srcs[blockIdx.z];
    float* Wt = dst + (size_t)blockIdx.z * Dx * Dx;
    int bx = blockIdx.x * 16, by = blockIdx.y * 16;
    int x = threadIdx.x, y = threadIdx.y;
    t[y][x] = W[(by + y) * Dx + bx + x];
    __syncthreads();
    Wt[(bx + y) * Dx + by + x] = t[x][y];
}

// ---------------- K-chunk partial for 4 rows ----------------
__device__ __forceinline__ void gemm_part_r4(const float4* __restrict__ X4,
                                             const float* __restrict__ Wt,
                                             int kp, int lane, float4 out[4]) {
    u64 aL[4] = {0ull, 0ull, 0ull, 0ull}, aH[4] = {0ull, 0ull, 0ull, 0ull};
    const ulonglong2* W2 = (const ulonglong2*)(Wt + kp * 32 * Dx);
#pragma unroll
    for (int c = 0; c < 8; c++) {
        ulonglong2 w0 = W2[(4 * c + 0) * 32 + lane];
        ulonglong2 w1 = W2[(4 * c + 1) * 32 + lane];
        ulonglong2 w2 = W2[(4 * c + 2) * 32 + lane];
        ulonglong2 w3 = W2[(4 * c + 3) * 32 + lane];
#pragma unroll
        for (int r = 0; r < 4; r++) {
            float4 xv = X4[r * 32 + kp * 8 + c];
            u64 p0 = pk2(xv.x), p1 = pk2(xv.y), p2 = pk2(xv.z), p3 = pk2(xv.w);
            ffma2(aL[r], p0, w0.x); ffma2(aH[r], p0, w0.y);
            ffma2(aL[r], p1, w1.x); ffma2(aH[r], p1, w1.y);
            ffma2(aL[r], p2, w2.x); ffma2(aH[r], p2, w2.y);
            ffma2(aL[r], p3, w3.x); ffma2(aH[r], p3, w3.y);
        }
    }
#pragma unroll
    for (int r = 0; r < 4; r++) out[r] = unpack_acc(aL[r], aH[r]);
}

// ---------------- K-chunk partial for 8 rows ----------------
__device__ __forceinline__ void gemm_part_r8(const float4* __restrict__ X4,
                                             const float* __restrict__ Wt,
                                             int kp, int lane, float4 out[8]) {
    u64 aL[8], aH[8];
#pragma unroll
    for (int r = 0; r < 8; r++) { aL[r] = 0ull; aH[r] = 0ull; }
    const ulonglong2* W2 = (const ulonglong2*)(Wt + kp * 32 * Dx);
#pragma unroll
    for (int c = 0; c < 8; c++) {
        ulonglong2 w0 = W2[(4 * c + 0) * 32 + lane];
        ulonglong2 w1 = W2[(4 * c + 1) * 32 + lane];
        ulonglong2 w2 = W2[(4 * c + 2) * 32 + lane];
        ulonglong2 w3 = W2[(4 * c + 3) * 32 + lane];
#pragma unroll
        for (int r = 0; r < 8; r++) {
            float4 xv = X4[r * 32 + kp * 8 + c];
            u64 p0 = pk2(xv.x), p1 = pk2(xv.y), p2 = pk2(xv.z), p3 = pk2(xv.w);
            ffma2(aL[r], p0, w0.x); ffma2(aH[r], p0, w0.y);
            ffma2(aL[r], p1, w1.x); ffma2(aH[r], p1, w1.y);
            ffma2(aL[r], p2, w2.x); ffma2(aH[r], p2, w2.y);
            ffma2(aL[r], p3, w3.x); ffma2(aH[r], p3, w3.y);
        }
    }
#pragma unroll
    for (int r = 0; r < 8; r++) out[r] = unpack_acc(aL[r], aH[r]);
}

// ---------------- LN over a float4-per-lane row (warp-collective) ----------------
__device__ __forceinline__ float4 ln_row(float4 hv, const float4& g4, const float4& b4) {
    float s = hv.x + hv.y + hv.z + hv.w;
    s = warp_sum(s);
    float mean = s * 0.0078125f;
    float4 dv = {hv.x - mean, hv.y - mean, hv.z - mean, hv.w - mean};
    float vs = dv.x * dv.x + dv.y * dv.y + dv.z * dv.z + dv.w * dv.w;
    vs = warp_sum(vs);
    float rstd = rsqrtf(vs * 0.0078125f + 1e-5f);
    float4 o = {dv.x * rstd * g4.x + b4.x, dv.y * rstd * g4.y + b4.y,
                dv.z * rstd * g4.z + b4.z, dv.w * rstd * g4.w + b4.w};
    return o;
}

// ---------------- projections: Q1, V1, K4, Q4 — 16 rows/block, 512 thr ----------------
__global__ void proj_batch(const float* __restrict__ q_emb, const float* __restrict__ s_emb,
                           const float* __restrict__ know, const float* __restrict__ WT,
                           const float* __restrict__ bq1, const float* __restrict__ bv1,
                           const float* __restrict__ bk4, const float* __restrict__ bq4,
                           float* __restrict__ Q1, float* __restrict__ V1,
                           float* __restrict__ K4, float* __restrict__ Q4) {
    const float* A; const float* Wt; const float* bias; float* C; int M;
    switch (blockIdx.y) {
        case 0:  A = q_emb; Wt = WT + 0 * 16384; bias = bq1; C = Q1; M = 1024; break;
        case 1:  A = s_emb; Wt = WT + 1 * 16384; bias = bv1; C = V1; M = 1024; break;
        case 2:  A = q_emb; Wt = WT + 4 * 16384; bias = bk4; C = K4; M = 1024; break;
        default: A = know;  Wt = WT + 3 * 16384; bias = bq4; C = Q4; M = 16;   break;
    }
    int row0 = blockIdx.x * 16;
    if (row0 >= M) return;
    __shared__ float4 Ps[16][4][32];
    int lane = threadIdx.x & 31, warp = threadIdx.x >> 5;
    int rg = warp >> 2, kp = warp & 3;
    float4 out[4];
    gemm_part_r4((const float4*)A + (size_t)(row0 + rg * 4) * 32, Wt, kp, lane, out);
#pragma unroll
    for (int r = 0; r < 4; r++) Ps[rg * 4 + r][kp][lane] = out[r];
    __syncthreads();
    float4 s = add4(add4(Ps[warp][0][lane], Ps[warp][1][lane]),
                    add4(Ps[warp][2][lane], Ps[warp][3][lane]));
    float4 b4 = ((const float4*)bias)[lane];
    ((float4*)C)[(size_t)(row0 + warp) * 32 + lane] = add4(s, b4);
}

// ---------------- block1 O-proj + residual + LN fused with V4 projection ----------------
__global__ void oproj_ln1_v4(const float* __restrict__ X, const float* __restrict__ WoT,
                             const float* __restrict__ bo, const float* __restrict__ res,
                             const float* __restrict__ lng, const float* __restrict__ lnb,
                             const float* __restrict__ WvT, const float* __restrict__ bv,
                             float* __restrict__ v4) {
    __shared__ float4 Ps[16][4][32];
    __shared__ float4 p_sm[16][32];
    int lane = threadIdx.x & 31, warp = threadIdx.x >> 5;
    int rg = warp >> 2, kp = warp & 3;
    int row0 = blockIdx.x * 16;
    {
        float4 out[4];
        gemm_part_r4((const float4*)X + (size_t)(row0 + rg * 4) * 32, WoT, kp, lane, out);
#pragma unroll
        for (int r = 0; r < 4; r++) Ps[rg * 4 + r][kp][lane] = out[r];
    }
    __syncthreads();
    {
        float4 s = add4(add4(Ps[warp][0][lane], Ps[warp][1][lane]),
                        add4(Ps[warp][2][lane], Ps[warp][3][lane]));
        float4 bb = ((const float4*)bo)[lane];
        float4 rv = ((const float4*)res)[(size_t)(row0 + warp) * 32 + lane];
        float4 hv = {s.x + bb.x + rv.x, s.y + bb.y + rv.y,
                     s.z + bb.z + rv.z, s.w + bb.w + rv.w};
        float4 g4 = ((const float4*)lng)[lane];
        float4 b4 = ((const float4*)lnb)[lane];
        p_sm[warp][lane] = ln_row(hv, g4, b4);
    }
    __syncthreads();
    {
        float4 out[4];
        gemm_part_r4((const float4*)p_sm + rg * 4 * 32, WvT, kp, lane, out);
#pragma unroll
        for (int r = 0; r < 4; r++) Ps[rg * 4 + r][kp][lane] = out[r];
    }
    __syncthreads();
    {
        float4 s = add4(add4(Ps[warp][0][lane], Ps[warp][1][lane]),
                        add4(Ps[warp][2][lane], Ps[warp][3][lane]));
        float4 b4 = ((const float4*)bv)[lane];
        ((float4*)v4)[(size_t)(row0 + warp) * 32 + lane] = add4(s, b4);
    }
}

// ---------------- block4 O-proj + residual(know) + LN + scatter: 8 rows/warp ----------------
__global__ void __launch_bounds__(256) oproj_ln4_k(
        const float* __restrict__ X, const float* __restrict__ WoT,
        const float* __restrict__ bo, const float* __restrict__ know,
        const float* __restrict__ lng, const float* __restrict__ lnb,
        float* __restrict__ z) {
    __shared__ float4 Ps[16][4][32];
    int lane = threadIdx.x & 31, warp = threadIdx.x >> 5;
    int rg = warp >> 2, kp = warp & 3;
    int row0 = blockIdx.x * 16;
    {
        float4 out[8];
        gemm_part_r8((const float4*)X + (size_t)(row0 + rg * 8) * 32, WoT, kp, lane, out);
#pragma unroll
        for (int r = 0; r < 8; r++) Ps[rg * 8 + r][kp][lane] = out[r];
    }
    __syncthreads();
#pragma unroll
    for (int rr = 0; rr < 2; rr++) {
        int lrow = warp * 2 + rr;
        int row = row0 + lrow;
        int bn = row >> 8, s = row & 255;
        int b = bn >> 4, n = bn & 15;
        float4 sm = add4(add4(Ps[lrow][0][lane], Ps[lrow][1][lane]),
                         add4(Ps[lrow][2][lane], Ps[lrow][3][lane]));
        float4 bb = ((const float4*)bo)[lane];
        float4 rv = ((const float4*)know)[n * 32 + lane];
        float4 hv = {sm.x + bb.x + rv.x, sm.y + bb.y + rv.y,
                     sm.z + bb.z + rv.z, sm.w + bb.w + rv.w};
        float4 g4 = ((const float4*)lng)[lane];
        float4 b4 = ((const float4*)lnb)[lane];
        ((float4*)z)[(((size_t)(b * Sx + s) * NKx) + n) * 32 + lane] = ln_row(hv, g4, b4);
    }
}

// ---------------- block1 attention: warp-per-row, branch-free, packed PV ----------------
__global__ void attn1_kernel(const float* __restrict__ QK, const float* __restrict__ Vg,
                             const float* __restrict__ gamma,
                             float* __restrict__ q_scores, float* __restrict__ cat1) {
    __shared__ float Kd[DKx * Sx];   // [d][j]
    __shared__ float Vsh[Sx * DKx];  // [j][d]
    __shared__ float Psh[8][Sx];
    const int b = blockIdx.z, h = blockIdx.y;
    const int tid = threadIdx.x, lane = tid & 31, warp = tid >> 5;

    {
        const float* base = QK + ((size_t)b * Sx) * Dx + h * DKx;
        const float4* r = (const float4*)(base + (size_t)tid * Dx);
        float4 a0 = r[0], a1 = r[1], a2 = r[2], a3 = r[3];
        Kd[0*Sx+tid]=a0.x; Kd[1*Sx+tid]=a0.y; Kd[2*Sx+tid]=a0.z; Kd[3*Sx+tid]=a0.w;
        Kd[4*Sx+tid]=a1.x; Kd[5*Sx+tid]=a1.y; Kd[6*Sx+tid]=a1.z; Kd[7*Sx+tid]=a1.w;
        Kd[8*Sx+tid]=a2.x; Kd[9*Sx+tid]=a2.y; Kd[10*Sx+tid]=a2.z; Kd[11*Sx+tid]=a2.w;
        Kd[12*Sx+tid]=a3.x; Kd[13*Sx+tid]=a3.y; Kd[14*Sx+tid]=a3.z; Kd[15*Sx+tid]=a3.w;
    }
    {
        const float* base = Vg + ((size_t)b * Sx) * Dx + h * DKx;
        for (int idx = tid; idx < Sx * DKx; idx += 256) {
            int j = idx >> 4, d = idx & 15;
            Vsh[idx] = base[(size_t)j * Dx + d];
        }
    }
    __syncthreads();

    const float g2 = -fabsf(gamma[h]) * LN2I;
    const int i = blockIdx.x * 8 + warp;

    float q[16];
#pragma unroll
    for (int d = 0; d < 16; d++) q[d] = Kd[d * Sx + i];

    float sc2[8], ex[8];
    float sum = 0.f;
#pragma unroll
    for (int u = 0; u < 8; u++) {
        int j = u * 32 + lane;
        float s = 0.f;
#pragma unroll
        for (int d = 0; d < 16; d++) s = fmaf(q[d], Kd[d * Sx + j], s);
        sc2[u] = s * (0.25f * LN2I);
        float e = (j <= i) ? ex2_ap(sc2[u]) : 0.f;
        ex[u] = e;
        sum += e;
    }
    sum = warp_sum(sum);
    float inv = rcp_ap(sum);

    float cum[8]; float carry = 0.f;
#pragma unroll
    for (int u = 0; u < 8; u++) {
        float x = ex[u] * inv;
#pragma unroll
        for (int off = 1; off < 32; off <<= 1) {
            float nv = __shfl_up_sync(0xffffffffu, x, off);
            x += (lane >= off) ? nv : 0.f;
        }
        float seg = __shfl_sync(0xffffffffu, x, 31);
        cum[u] = x + carry;
        carry += seg;
    }
    const float total = carry;
    const float fi = (float)i;

    float sum2 = 0.f;
#pragma unroll
    for (int u = 0; u < 8; u++) {
        int j = u * 32 + lane;
        float pos = fabsf((float)j - fi);
        float dist = sqrt_ap(fmaxf((total - cum[u]) * pos, 0.f));
        float eff = ex2_ap(g2 * dist);
        float e2 = (j <= i) ? ex2_ap(sc2[u] * eff) : 0.f;
        ex[u] = e2;
        sum2 += e2;
    }
    sum2 = warp_sum(sum2);
    float inv2 = rcp_ap(sum2);

#pragma unroll
    for (int u = 0; u < 8; u++)
        Psh[warp][u * 32 + lane] = ex[u] * inv2;
    __syncwarp();

    {
        const float4* P4 = (const float4*)Psh[warp];
        float4* qs4 = (float4*)(q_scores + (((size_t)(b * Hx + h)) * Sx + i) * Sx);
        qs4[lane] = P4[lane];
        qs4[32 + lane] = P4[32 + lane];
    }

    const int jq = lane >> 3, dp = lane & 7;
    u64 acc = 0ull;
    const int njj = (i + 4) >> 2;
    const float* Pr = Psh[warp];
    for (int jj = 0; jj < njj; jj++) {
        int j = jj * 4 + jq;
        u64 v2 = *(const u64*)(Vsh + j * DKx + dp * 2);
        u64 p = pk2(Pr[j]);
        ffma2(acc, p, v2);
    }
    acc = addf2(acc, __shfl_xor_sync(0xffffffffu, acc, 8));
    acc = addf2(acc, __shfl_xor_sync(0xffffffffu, acc, 16));
    if (lane < 8) {
        float2 r = up2(acc);
        *(float2*)(cat1 + (((size_t)b * Sx) + i) * Dx + h * DKx + dp * 2) = r;
    }
}

// ---------------- block4 attention: scan-free, branch-free inner, packed PV ----------------
__global__ void attn4_kernel(const float* __restrict__ q4g, const float* __restrict__ k4g,
                             const float* __restrict__ v4g, const float* __restrict__ gamma,
                             float* __restrict__ ks_out, float* __restrict__ cat4) {
    __shared__ float Vsh[Sx * DKx];
    __shared__ float sc2sh[Sx];
    __shared__ float Csh[Sx];
    __shared__ float Psh[8][2][Sx];
    __shared__ float redA[8], redB[8];

    const int bn = blockIdx.x, h = blockIdx.y;
    const int b = bn >> 4, n = bn & 15;
    const int tid = threadIdx.x, lane = tid & 31, warp = tid >> 5;

    {
        const float* vb = v4g + ((size_t)b * Sx) * Dx + h * DKx;
        for (int idx = tid; idx < Sx * DKx; idx += 256) {
            int j = idx >> 4, d = idx & 15;
            Vsh[idx] = vb[(size_t)j * Dx + d];
        }
    }
    {
        const float* qp = q4g + n * Dx + h * DKx;
        const float* kp = k4g + ((size_t)b * Sx + tid) * Dx + h * DKx;
        float s = 0.f;
#pragma unroll
        for (int d = 0; d < 16; d++) s = fmaf(qp[d], kp[d], s);
        float v = s * (0.25f * LN2I);
        sc2sh[tid] = v;
        float m = warp_max(v);
        if (lane == 0) redA[warp] = m;
        __syncthreads();
        float M = redA[0];
#pragma unroll
        for (int w = 1; w < 8; w++) M = fmaxf(M, redA[w]);
        float x = ex2_ap(v - M);
#pragma unroll
        for (int off = 1; off < 32; off <<= 1) {
            float nv = __shfl_up_sync(0xffffffffu, x, off);
            x += (lane >= off) ? nv : 0.f;
        }
        if (lane == 31) redB[warp] = x;
        __syncthreads();
        float carry = 0.f;
#pragma unroll
        for (int w = 0; w < 7; w++) carry += (w < warp) ? redB[w] : 0.f;
        Csh[tid] = x + carry;
    }
    __syncthreads();

    const float g2 = -fabsf(gamma[h]) * LN2I;
    float sc2[8];
#pragma unroll
    for (int u = 0; u < 8; u++) sc2[u] = sc2sh[u * 32 + lane];

    const int jq = lane >> 3, dp = lane & 7;

    for (int gb = 0; gb < 16; ++gb) {
        const int i1 = warp + 8 * (2 * gb + 1);

        for (int k = 0; k < 2; ++k) {
            const int i = i1 - 8 + 8 * k;
            const float invC = (i > 0) ? rcp_ap(Csh[i - 1]) : 0.f;
            const float fi = (float)i;

            float e[8], sum = 0.f, emax = 0.f;
#pragma unroll
            for (int u = 0; u < 8; u++) {
                int j = u * 32 + lane;
                float t = fmaf(-Csh[j], invC, 1.0f);
                float pos = fabsf((float)j - fi);
                float dist = sqrt_ap(fmaxf(t * pos, 0.f));
                float eff = ex2_ap(g2 * dist);
                float ev = ex2_ap(sc2[u] * eff);
                ev = (j < i) ? ev : 0.f;
                e[u] = ev;
                sum += ev;
                emax = fmaxf(emax, ev);
            }
            sum = warp_sum(sum);
            emax = warp_max(emax);
            float mult = fminf(rcp_ap(fmaxf(emax, 1e-30f)),
                               5.f * rcp_ap(fmaxf(sum, 1e-30f)));
#pragma unroll
            for (int u = 0; u < 8; u++)
                Psh[warp][k][u * 32 + lane] = e[u] * mult;
            __syncwarp();

            const float4* P4 = (const float4*)Psh[warp][k];
            float4* ks4 = (float4*)(ks_out + ((((size_t)(b * Hx + h) * Sx + i) * NKx + n) << 8));
            ks4[lane] = P4[lane];
            ks4[32 + lane] = P4[32 + lane];
        }

        u64 a0 = 0ull, a1 = 0ull;
        const int njj = (i1 + 3) >> 2;
        const float* Pr0 = Psh[warp][0];
        const float* Pr1 = Psh[warp][1];
        for (int jj = 0; jj < njj; jj++) {
            int j = jj * 4 + jq;
            u64 v2 = *(const u64*)(Vsh + j * DKx + dp * 2);
            u64 p0 = pk2(Pr0[j]);
            u64 p1 = pk2(Pr1[j]);
            ffma2(a0, p0, v2);
            ffma2(a1, p1, v2);
        }
        a0 = addf2(a0, __shfl_xor_sync(0xffffffffu, a0, 8));
        a0 = addf2(a0, __shfl_xor_sync(0xffffffffu, a0, 16));
        a1 = addf2(a1, __shfl_xor_sync(0xffffffffu, a1, 8));
        a1 = addf2(a1, __shfl_xor_sync(0xffffffffu, a1, 16));
        if (lane < 8) {
            int i0 = i1 - 8;
            float2 r0 = up2(a0), r1 = up2(a1);
            *(float2*)(cat4 + ((size_t)bn * Sx + i0) * Dx + h * DKx + dp * 2) = r0;
            *(float2*)(cat4 + ((size_t)bn * Sx + i1) * Dx + h * DKx + dp * 2) = r1;
        }
        __syncwarp();
    }
}

// ---------------- launch ----------------
extern "C" void kernel_launch(void* const* d_in, const int* in_sizes, int n_in,
                              void* d_out, int out_size) {
    (void)in_sizes; (void)n_in; (void)out_size;
    const float* q_emb  = (const float*)d_in[0];
    const float* s_emb  = (const float*)d_in[1];
    const float* b1_Wq  = (const float*)d_in[3];
    const float* b1_bq  = (const float*)d_in[4];
    const float* b1_Wv  = (const float*)d_in[5];
    const float* b1_bv  = (const float*)d_in[6];
    const float* b1_Wo  = (const float*)d_in[7];
    const float* b1_bo  = (const float*)d_in[8];
    const float* b1_gam = (const float*)d_in[9];
    const float* b1_lng = (const float*)d_in[10];
    const float* b1_lnb = (const float*)d_in[11];
    const float* b4_Wq  = (const float*)d_in[12];
    const float* b4_bq  = (const float*)d_in[13];
    const float* b4_Wk  = (const float*)d_in[14];
    const float* b4_bk  = (const float*)d_in[15];
    const float* b4_Wv  = (const float*)d_in[16];
    const float* b4_bv  = (const float*)d_in[17];
    const float* b4_Wo  = (const float*)d_in[18];
    const float* b4_bo  = (const float*)d_in[19];
    const float* b4_gam = (const float*)d_in[20];
    const float* b4_lng = (const float*)d_in[21];
    const float* b4_lnb = (const float*)d_in[22];
    const float* know   = (const float*)d_in[23];

    float* z_out  = (float*)d_out;
    float* qs_out = z_out + (size_t)BSx * Sx * NKx * Dx;
    float* ks_out = qs_out + (size_t)BSx * Hx * Sx * Sx;

    float *Q1, *V1, *cat1, *q4, *k4, *v4, *cat4, *WT;
    cudaGetSymbolAddress((void**)&Q1,   d_Q1);
    cudaGetSymbolAddress((void**)&V1,   d_V1);
    cudaGetSymbolAddress((void**)&cat1, d_cat1);
    cudaGetSymbolAddress((void**)&q4,   d_q4);
    cudaGetSymbolAddress((void**)&k4,   d_k4);
    cudaGetSymbolAddress((void**)&v4,   d_v4);
    cudaGetSymbolAddress((void**)&cat4, d_cat4);
    cudaGetSymbolAddress((void**)&WT,   d_WT);

    transpose_all<<<dim3(8, 8, 7), dim3(16, 16)>>>(b1_Wq, b1_Wv, b1_Wo, b4_Wq, b4_Wk, b4_Wv, b4_Wo, WT);

    proj_batch<<<dim3(64, 4), 512>>>(q_emb, s_emb, know, WT,
                                     b1_bq, b1_bv, b4_bk, b4_bq,
                                     Q1, V1, k4, q4);

    attn1_kernel<<<dim3(Sx / 8, Hx, BSx), 256>>>(Q1, V1, b1_gam, qs_out, cat1);

    oproj_ln1_v4<<<64, 512>>>(cat1, WT + 2 * 16384, b1_bo, q_emb, b1_lng, b1_lnb,
                              WT + 5 * 16384, b4_bv, v4);

    attn4_kernel<<<dim3(BSx * NKx, Hx), 256>>>(q4, k4, v4, b4_gam, ks_out, cat4);

    oproj_ln4_k<<<1024, 256>>>(cat4, WT + 6 * 16384, b4_bo, know, b4_lng, b4_lnb, z_out);
}

// round 9
// speedup vs baseline: 2.1041x; 1.0382x over previous
#include <cuda_runtime.h>
#include <math.h>
#include <stdint.h>

#define Sx   256
#define Dx   128
#define Hx   8
#define DKx  16
#define NKx  16
#define BSx  4

typedef unsigned long long u64;

// ---------------- scratch ----------------
__device__ float d_Q1[BSx * Sx * Dx];
__device__ float d_V1[BSx * Sx * Dx];
__device__ float d_cat1[BSx * Sx * Dx];
__device__ float d_q4[NKx * Dx];
__device__ float d_k4[BSx * Sx * Dx];
__device__ float d_v4[BSx * Sx * Dx];
__device__ float d_cat4[BSx * NKx * Sx * Dx];
__device__ float d_WT[7][Dx * Dx];

// ---------------- helpers ----------------
__device__ __forceinline__ float warp_max(float v) {
#pragma unroll
    for (int o = 16; o; o >>= 1) v = fmaxf(v, __shfl_xor_sync(0xffffffffu, v, o));
    return v;
}
__device__ __forceinline__ float warp_sum(float v) {
#pragma unroll
    for (int o = 16; o; o >>= 1) v += __shfl_xor_sync(0xffffffffu, v, o);
    return v;
}
__device__ __forceinline__ float rcp_ap(float x) {
    float r; asm("rcp.approx.f32 %0, %1;" : "=f"(r) : "f"(x)); return r;
}
__device__ __forceinline__ float sqrt_ap(float x) {
    float r; asm("sqrt.approx.f32 %0, %1;" : "=f"(r) : "f"(x)); return r;
}
__device__ __forceinline__ float ex2_ap(float x) {
    float r; asm("ex2.approx.f32 %0, %1;" : "=f"(r) : "f"(x)); return r;
}
__device__ __forceinline__ u64 pk2(float x) {
    u64 r; asm("mov.b64 %0, {%1, %1};" : "=l"(r) : "f"(x)); return r;
}
__device__ __forceinline__ void ffma2(u64& d, u64 a, u64 b) {
    asm("fma.rn.f32x2 %0, %1, %2, %0;" : "+l"(d) : "l"(a), "l"(b));
}
__device__ __forceinline__ u64 addf2(u64 a, u64 b) {
    u64 r; asm("add.rn.f32x2 %0, %1, %2;" : "=l"(r) : "l"(a), "l"(b)); return r;
}
__device__ __forceinline__ u64 mulf2(u64 a, u64 b) {
    u64 r; asm("mul.rn.f32x2 %0, %1, %2;" : "=l"(r) : "l"(a), "l"(b)); return r;
}
__device__ __forceinline__ float2 up2(u64 v) {
    float2 f; asm("mov.b64 {%0, %1}, %2;" : "=f"(f.x), "=f"(f.y) : "l"(v)); return f;
}
__device__ __forceinline__ float4 unpack_acc(u64 lo, u64 hi) {
    float2 a = up2(lo), b = up2(hi);
    return make_float4(a.x, a.y, b.x, b.y);
}
__device__ __forceinline__ float4 add4(float4 a, float4 b) {
    return make_float4(a.x + b.x, a.y + b.y, a.z + b.z, a.w + b.w);
}

#define LN2I 1.442695041f

// ---------------- transpose all 7 weights ----------------
__global__ void transpose_all(const float* __restrict__ s0, const float* __restrict__ s1,
                              const float* __restrict__ s2, const float* __restrict__ s3,
                              const float* __restrict__ s4, const float* __restrict__ s5,
                              const float* __restrict__ s6, float* __restrict__ dst) {
    const float* srcs[7] = {s0, s1, s2, s3, s4, s5, s6};
    __shared__ float t[16][17];
    const float* W = srcs[blockIdx.z];
    float* Wt = dst + (size_t)blockIdx.z * Dx * Dx;
    int bx = blockIdx.x * 16, by = blockIdx.y * 16;
    int x = threadIdx.x, y = threadIdx.y;
    t[y][x] = W[(by + y) * Dx + bx + x];
    __syncthreads();
    Wt[(bx + y) * Dx + by + x] = t[x][y];
}

// ---------------- K-chunk partial, R rows, NKP chunks of 128/NKP K-values ----------------
template<int R, int NKP>
__device__ __forceinline__ void gemm_partT(const float4* __restrict__ X4,
                                           const float* __restrict__ Wt,
                                           int kp, int lane, float4* out) {
    constexpr int CI = 32 / NKP;   // float4 iters per chunk
    u64 aL[R], aH[R];
#pragma unroll
    for (int r = 0; r < R; r++) { aL[r] = 0ull; aH[r] = 0ull; }
    const ulonglong2* W2 = (const ulonglong2*)(Wt + kp * (Dx / NKP) * Dx);
#pragma unroll
    for (int c = 0; c < CI; c++) {
        ulonglong2 w0 = W2[(4 * c + 0) * 32 + lane];
        ulonglong2 w1 = W2[(4 * c + 1) * 32 + lane];
        ulonglong2 w2 = W2[(4 * c + 2) * 32 + lane];
        ulonglong2 w3 = W2[(4 * c + 3) * 32 + lane];
#pragma unroll
        for (int r = 0; r < R; r++) {
            float4 xv = X4[r * 32 + kp * CI + c];
            u64 p0 = pk2(xv.x), p1 = pk2(xv.y), p2 = pk2(xv.z), p3 = pk2(xv.w);
            ffma2(aL[r], p0, w0.x); ffma2(aH[r], p0, w0.y);
            ffma2(aL[r], p1, w1.x); ffma2(aH[r], p1, w1.y);
            ffma2(aL[r], p2, w2.x); ffma2(aH[r], p2, w2.y);
            ffma2(aL[r], p3, w3.x); ffma2(aH[r], p3, w3.y);
        }
    }
#pragma unroll
    for (int r = 0; r < R; r++) out[r] = unpack_acc(aL[r], aH[r]);
}

// ---------------- LN over a float4-per-lane row (warp-collective) ----------------
__device__ __forceinline__ float4 ln_row(float4 hv, const float4& g4, const float4& b4) {
    float s = hv.x + hv.y + hv.z + hv.w;
    s = warp_sum(s);
    float mean = s * 0.0078125f;
    float4 dv = {hv.x - mean, hv.y - mean, hv.z - mean, hv.w - mean};
    float vs = dv.x * dv.x + dv.y * dv.y + dv.z * dv.z + dv.w * dv.w;
    vs = warp_sum(vs);
    float rstd = rsqrtf(vs * 0.0078125f + 1e-5f);
    float4 o = {dv.x * rstd * g4.x + b4.x, dv.y * rstd * g4.y + b4.y,
                dv.z * rstd * g4.z + b4.z, dv.w * rstd * g4.w + b4.w};
    return o;
}

// ---------------- projections: Q1, V1, K4, Q4 — 16 rows/block, 512 thr ----------------
__global__ void proj_batch(const float* __restrict__ q_emb, const float* __restrict__ s_emb,
                           const float* __restrict__ know, const float* __restrict__ WT,
                           const float* __restrict__ bq1, const float* __restrict__ bv1,
                           const float* __restrict__ bk4, const float* __restrict__ bq4,
                           float* __restrict__ Q1, float* __restrict__ V1,
                           float* __restrict__ K4, float* __restrict__ Q4) {
    const float* A; const float* Wt; const float* bias; float* C; int M;
    switch (blockIdx.y) {
        case 0:  A = q_emb; Wt = WT + 0 * 16384; bias = bq1; C = Q1; M = 1024; break;
        case 1:  A = s_emb; Wt = WT + 1 * 16384; bias = bv1; C = V1; M = 1024; break;
        case 2:  A = q_emb; Wt = WT + 4 * 16384; bias = bk4; C = K4; M = 1024; break;
        default: A = know;  Wt = WT + 3 * 16384; bias = bq4; C = Q4; M = 16;   break;
    }
    int row0 = blockIdx.x * 16;
    if (row0 >= M) return;
    __shared__ float4 Ps[16][4][32];
    int lane = threadIdx.x & 31, warp = threadIdx.x >> 5;
    int rg = warp >> 2, kp = warp & 3;
    float4 out[4];
    gemm_partT<4, 4>((const float4*)A + (size_t)(row0 + rg * 4) * 32, Wt, kp, lane, out);
#pragma unroll
    for (int r = 0; r < 4; r++) Ps[rg * 4 + r][kp][lane] = out[r];
    __syncthreads();
    float4 s = add4(add4(Ps[warp][0][lane], Ps[warp][1][lane]),
                    add4(Ps[warp][2][lane], Ps[warp][3][lane]));
    float4 b4 = ((const float4*)bias)[lane];
    ((float4*)C)[(size_t)(row0 + warp) * 32 + lane] = add4(s, b4);
}

// ---------------- block1 O-proj + residual + LN fused with V4 projection ----------------
// 4 rows/block, 8 K-chunk warps, 256 thr, grid 256
__global__ void __launch_bounds__(256) oproj_ln1_v4(
        const float* __restrict__ X, const float* __restrict__ WoT,
        const float* __restrict__ bo, const float* __restrict__ res,
        const float* __restrict__ lng, const float* __restrict__ lnb,
        const float* __restrict__ WvT, const float* __restrict__ bv,
        float* __restrict__ v4) {
    __shared__ float4 Ps[4][8][32];
    __shared__ float4 p_sm[4][32];
    int lane = threadIdx.x & 31, warp = threadIdx.x >> 5;   // warp = kp (0..7)
    int row0 = blockIdx.x * 4;
    {
        float4 out[4];
        gemm_partT<4, 8>((const float4*)X + (size_t)row0 * 32, WoT, warp, lane, out);
#pragma unroll
        for (int r = 0; r < 4; r++) Ps[r][warp][lane] = out[r];
    }
    __syncthreads();
    if (warp < 4) {
        float4 s = Ps[warp][0][lane];
#pragma unroll
        for (int k = 1; k < 8; k++) s = add4(s, Ps[warp][k][lane]);
        float4 bb = ((const float4*)bo)[lane];
        float4 rv = ((const float4*)res)[(size_t)(row0 + warp) * 32 + lane];
        float4 hv = {s.x + bb.x + rv.x, s.y + bb.y + rv.y,
                     s.z + bb.z + rv.z, s.w + bb.w + rv.w};
        float4 g4 = ((const float4*)lng)[lane];
        float4 b4 = ((const float4*)lnb)[lane];
        p_sm[warp][lane] = ln_row(hv, g4, b4);
    }
    __syncthreads();
    {
        float4 out[4];
        gemm_partT<4, 8>((const float4*)p_sm[0], WvT, warp, lane, out);
#pragma unroll
        for (int r = 0; r < 4; r++) Ps[r][warp][lane] = out[r];
    }
    __syncthreads();
    if (warp < 4) {
        float4 s = Ps[warp][0][lane];
#pragma unroll
        for (int k = 1; k < 8; k++) s = add4(s, Ps[warp][k][lane]);
        float4 b4 = ((const float4*)bv)[lane];
        ((float4*)v4)[(size_t)(row0 + warp) * 32 + lane] = add4(s, b4);
    }
}

// ---------------- block4 O-proj + residual(know) + LN + scatter: 16 rows/warp ----------------
__global__ void __launch_bounds__(128) oproj_ln4_k(
        const float* __restrict__ X, const float* __restrict__ WoT,
        const float* __restrict__ bo, const float* __restrict__ know,
        const float* __restrict__ lng, const float* __restrict__ lnb,
        float* __restrict__ z) {
    __shared__ float4 Ps[16][4][32];     // 32KB
    int lane = threadIdx.x & 31, warp = threadIdx.x >> 5;   // 4 warps, warp = kp
    int row0 = blockIdx.x * 16;
    {
        float4 out[16];
        gemm_partT<16, 4>((const float4*)X + (size_t)row0 * 32, WoT, warp, lane, out);
#pragma unroll
        for (int r = 0; r < 16; r++) Ps[r][warp][lane] = out[r];
    }
    __syncthreads();
#pragma unroll
    for (int rr = 0; rr < 4; rr++) {
        int lrow = warp * 4 + rr;
        int row = row0 + lrow;                   // (b*NK+n)*S + s
        int bn = row >> 8, s = row & 255;
        int b = bn >> 4, n = bn & 15;
        float4 sm = add4(add4(Ps[lrow][0][lane], Ps[lrow][1][lane]),
                         add4(Ps[lrow][2][lane], Ps[lrow][3][lane]));
        float4 bb = ((const float4*)bo)[lane];
        float4 rv = ((const float4*)know)[n * 32 + lane];
        float4 hv = {sm.x + bb.x + rv.x, sm.y + bb.y + rv.y,
                     sm.z + bb.z + rv.z, sm.w + bb.w + rv.w};
        float4 g4 = ((const float4*)lng)[lane];
        float4 b4 = ((const float4*)lnb)[lane];
        ((float4*)z)[(((size_t)(b * Sx + s) * NKx) + n) * 32 + lane] = ln_row(hv, g4, b4);
    }
}

// ---------------- block1 attention: warp-per-row, packed PV ----------------
__global__ void attn1_kernel(const float* __restrict__ QK, const float* __restrict__ Vg,
                             const float* __restrict__ gamma,
                             float* __restrict__ q_scores, float* __restrict__ cat1) {
    __shared__ float Kd[DKx * Sx];   // [d][j]
    __shared__ float Vsh[Sx * DKx];  // [j][d]
    __shared__ float Psh[8][Sx];
    const int b = blockIdx.z, h = blockIdx.y;
    const int tid = threadIdx.x, lane = tid & 31, warp = tid >> 5;

    {
        const float* base = QK + ((size_t)b * Sx) * Dx + h * DKx;
        const float4* r = (const float4*)(base + (size_t)tid * Dx);
        float4 a0 = r[0], a1 = r[1], a2 = r[2], a3 = r[3];
        Kd[0*Sx+tid]=a0.x; Kd[1*Sx+tid]=a0.y; Kd[2*Sx+tid]=a0.z; Kd[3*Sx+tid]=a0.w;
        Kd[4*Sx+tid]=a1.x; Kd[5*Sx+tid]=a1.y; Kd[6*Sx+tid]=a1.z; Kd[7*Sx+tid]=a1.w;
        Kd[8*Sx+tid]=a2.x; Kd[9*Sx+tid]=a2.y; Kd[10*Sx+tid]=a2.z; Kd[11*Sx+tid]=a2.w;
        Kd[12*Sx+tid]=a3.x; Kd[13*Sx+tid]=a3.y; Kd[14*Sx+tid]=a3.z; Kd[15*Sx+tid]=a3.w;
    }
    {
        const float* base = Vg + ((size_t)b * Sx) * Dx + h * DKx;
        for (int idx = tid; idx < Sx * DKx; idx += 256) {
            int j = idx >> 4, d = idx & 15;
            Vsh[idx] = base[(size_t)j * Dx + d];
        }
    }
    __syncthreads();

    const float g2 = -fabsf(gamma[h]) * LN2I;
    const int i = blockIdx.x * 8 + warp;

    float q[16];
#pragma unroll
    for (int d = 0; d < 16; d++) q[d] = Kd[d * Sx + i];

    float sc2[8], ex[8];
    float sum = 0.f;
#pragma unroll
    for (int u = 0; u < 8; u++) {
        int j = u * 32 + lane;
        float s = 0.f;
#pragma unroll
        for (int d = 0; d < 16; d++) s = fmaf(q[d], Kd[d * Sx + j], s);
        sc2[u] = s * (0.25f * LN2I);
        float e = (j <= i) ? ex2_ap(sc2[u]) : 0.f;
        ex[u] = e;
        sum += e;
    }
    sum = warp_sum(sum);
    float inv = rcp_ap(sum);

    float cum[8]; float carry = 0.f;
#pragma unroll
    for (int u = 0; u < 8; u++) {
        float x = ex[u] * inv;
#pragma unroll
        for (int off = 1; off < 32; off <<= 1) {
            float nv = __shfl_up_sync(0xffffffffu, x, off);
            x += (lane >= off) ? nv : 0.f;
        }
        float seg = __shfl_sync(0xffffffffu, x, 31);
        cum[u] = x + carry;
        carry += seg;
    }
    const float total = carry;
    const float fi = (float)i;

    float sum2 = 0.f;
#pragma unroll
    for (int u = 0; u < 8; u++) {
        int j = u * 32 + lane;
        float pos = fabsf((float)j - fi);
        float dist = sqrt_ap(fmaxf((total - cum[u]) * pos, 0.f));
        float eff = ex2_ap(g2 * dist);
        float e2 = (j <= i) ? ex2_ap(sc2[u] * eff) : 0.f;
        ex[u] = e2;
        sum2 += e2;
    }
    sum2 = warp_sum(sum2);
    float inv2 = rcp_ap(sum2);

#pragma unroll
    for (int u = 0; u < 8; u++)
        Psh[warp][u * 32 + lane] = ex[u] * inv2;
    __syncwarp();

    {
        const float4* P4 = (const float4*)Psh[warp];
        float4* qs4 = (float4*)(q_scores + (((size_t)(b * Hx + h)) * Sx + i) * Sx);
        qs4[lane] = P4[lane];
        qs4[32 + lane] = P4[32 + lane];
    }

    const int jq = lane >> 3, dp = lane & 7;
    u64 acc = 0ull;
    const int njj = (i + 4) >> 2;
    const float* Pr = Psh[warp];
    for (int jj = 0; jj < njj; jj++) {
        int j = jj * 4 + jq;
        u64 v2 = *(const u64*)(Vsh + j * DKx + dp * 2);
        u64 p = pk2(Pr[j]);
        ffma2(acc, p, v2);
    }
    acc = addf2(acc, __shfl_xor_sync(0xffffffffu, acc, 8));
    acc = addf2(acc, __shfl_xor_sync(0xffffffffu, acc, 16));
    if (lane < 8) {
        float2 r = up2(acc);
        *(float2*)(cat1 + (((size_t)b * Sx) + i) * Dx + h * DKx + dp * 2) = r;
    }
}

// ---------------- block4 attention: scan-free, dyn-triangular, deferred maxout ----------------
// grid (64 bn, 8 h, 2 iz); each block handles 128 rows
__global__ void attn4_kernel(const float* __restrict__ q4g, const float* __restrict__ k4g,
                             const float* __restrict__ v4g, const float* __restrict__ gamma,
                             float* __restrict__ ks_out, float* __restrict__ cat4) {
    __shared__ float Vsh[Sx * DKx];
    __shared__ float sc2sh[Sx];
    __shared__ float Csh[Sx];
    __shared__ float Psh[8][2][Sx];
    __shared__ float redA[8], redB[8];

    const int bn = blockIdx.x, h = blockIdx.y, iz = blockIdx.z;
    const int b = bn >> 4, n = bn & 15;
    const int tid = threadIdx.x, lane = tid & 31, warp = tid >> 5;

    {
        const float* vb = v4g + ((size_t)b * Sx) * Dx + h * DKx;
        const int vlim = (iz ? Sx : 128) * DKx;
        for (int idx = tid; idx < vlim; idx += 256) {
            int j = idx >> 4, d = idx & 15;
            Vsh[idx] = vb[(size_t)j * Dx + d];
        }
    }
    {
        const float* qp = q4g + n * Dx + h * DKx;
        const float* kp = k4g + ((size_t)b * Sx + tid) * Dx + h * DKx;
        float s = 0.f;
#pragma unroll
        for (int d = 0; d < 16; d++) s = fmaf(qp[d], kp[d], s);
        float v = s * (0.25f * LN2I);
        sc2sh[tid] = v;
        float m = warp_max(v);
        if (lane == 0) redA[warp] = m;
        __syncthreads();
        float M = redA[0];
#pragma unroll
        for (int w = 1; w < 8; w++) M = fmaxf(M, redA[w]);
        float x = ex2_ap(v - M);
#pragma unroll
        for (int off = 1; off < 32; off <<= 1) {
            float nv = __shfl_up_sync(0xffffffffu, x, off);
            x += (lane >= off) ? nv : 0.f;
        }
        if (lane == 31) redB[warp] = x;
        __syncthreads();
        float carry = 0.f;
#pragma unroll
        for (int w = 0; w < 7; w++) carry += (w < warp) ? redB[w] : 0.f;
        Csh[tid] = x + carry;
    }
    __syncthreads();

    const float g2 = -fabsf(gamma[h]) * LN2I;
    const int jq = lane >> 3, dp = lane & 7;

    for (int gb = 0; gb < 8; ++gb) {
        const int i1 = iz * 128 + warp + 8 * (2 * gb + 1);
        float mlt[2];

#pragma unroll
        for (int k = 0; k < 2; ++k) {
            const int i = i1 - 8 + 8 * k;
            const int uMax = (i - 1) >> 5;
            const float invC = (i > 0) ? rcp_ap(Csh[i - 1]) : 0.f;
            const float fi = (float)i;

            float sum = 0.f, emax = 0.f;
            for (int u = 0; u <= uMax; u++) {
                int j = u * 32 + lane;
                float t = fmaf(-Csh[j], invC, 1.0f);
                float pos = fabsf((float)j - fi);
                float dist = sqrt_ap(fmaxf(t * pos, 0.f));
                float eff = ex2_ap(g2 * dist);
                float ev = ex2_ap(sc2sh[j] * eff);
                ev = (j < i) ? ev : 0.f;
                sum += ev;
                emax = fmaxf(emax, ev);
                Psh[warp][k][j] = ev;
            }
            for (int u = uMax + 1; u < 8; u++)
                Psh[warp][k][u * 32 + lane] = 0.f;
            sum = warp_sum(sum);
            emax = warp_max(emax);
            mlt[k] = fminf(rcp_ap(fmaxf(emax, 1e-30f)),
                           5.f * rcp_ap(fmaxf(sum, 1e-30f)));
        }
        __syncwarp();

        // ks writes (scaled on the fly; Psh keeps raw e for PV)
#pragma unroll
        for (int k = 0; k < 2; ++k) {
            const int i = i1 - 8 + 8 * k;
            const float m = mlt[k];
            const float4* P4 = (const float4*)Psh[warp][k];
            float4 v0 = P4[lane], v1 = P4[32 + lane];
            v0.x *= m; v0.y *= m; v0.z *= m; v0.w *= m;
            v1.x *= m; v1.y *= m; v1.z *= m; v1.w *= m;
            float4* ks4 = (float4*)(ks_out + ((((size_t)(b * Hx + h) * Sx + i) * NKx + n) << 8));
            ks4[lane] = v0;
            ks4[32 + lane] = v1;
        }

        // PV on raw e, deferred mult
        u64 a0 = 0ull, a1 = 0ull;
        const int njj = (i1 + 3) >> 2;
        const float* Pr0 = Psh[warp][0];
        const float* Pr1 = Psh[warp][1];
        for (int jj = 0; jj < njj; jj++) {
            int j = jj * 4 + jq;
            u64 v2 = *(const u64*)(Vsh + j * DKx + dp * 2);
            ffma2(a0, pk2(Pr0[j]), v2);
            ffma2(a1, pk2(Pr1[j]), v2);
        }
        a0 = addf2(a0, __shfl_xor_sync(0xffffffffu, a0, 8));
        a0 = addf2(a0, __shfl_xor_sync(0xffffffffu, a0, 16));
        a1 = addf2(a1, __shfl_xor_sync(0xffffffffu, a1, 8));
        a1 = addf2(a1, __shfl_xor_sync(0xffffffffu, a1, 16));
        a0 = mulf2(a0, pk2(mlt[0]));
        a1 = mulf2(a1, pk2(mlt[1]));
        if (lane < 8) {
            int i0 = i1 - 8;
            float2 r0 = up2(a0), r1 = up2(a1);
            *(float2*)(cat4 + ((size_t)bn * Sx + i0) * Dx + h * DKx + dp * 2) = r0;
            *(float2*)(cat4 + ((size_t)bn * Sx + i1) * Dx + h * DKx + dp * 2) = r1;
        }
        __syncwarp();
    }
}

// ---------------- launch ----------------
extern "C" void kernel_launch(void* const* d_in, const int* in_sizes, int n_in,
                              void* d_out, int out_size) {
    (void)in_sizes; (void)n_in; (void)out_size;
    const float* q_emb  = (const float*)d_in[0];
    const float* s_emb  = (const float*)d_in[1];
    const float* b1_Wq  = (const float*)d_in[3];
    const float* b1_bq  = (const float*)d_in[4];
    const float* b1_Wv  = (const float*)d_in[5];
    const float* b1_bv  = (const float*)d_in[6];
    const float* b1_Wo  = (const float*)d_in[7];
    const float* b1_bo  = (const float*)d_in[8];
    const float* b1_gam = (const float*)d_in[9];
    const float* b1_lng = (const float*)d_in[10];
    const float* b1_lnb = (const float*)d_in[11];
    const float* b4_Wq  = (const float*)d_in[12];
    const float* b4_bq  = (const float*)d_in[13];
    const float* b4_Wk  = (const float*)d_in[14];
    const float* b4_bk  = (const float*)d_in[15];
    const float* b4_Wv  = (const float*)d_in[16];
    const float* b4_bv  = (const float*)d_in[17];
    const float* b4_Wo  = (const float*)d_in[18];
    const float* b4_bo  = (const float*)d_in[19];
    const float* b4_gam = (const float*)d_in[20];
    const float* b4_lng = (const float*)d_in[21];
    const float* b4_lnb = (const float*)d_in[22];
    const float* know   = (const float*)d_in[23];

    float* z_out  = (float*)d_out;
    float* qs_out = z_out + (size_t)BSx * Sx * NKx * Dx;
    float* ks_out = qs_out + (size_t)BSx * Hx * Sx * Sx;

    float *Q1, *V1, *cat1, *q4, *k4, *v4, *cat4, *WT;
    cudaGetSymbolAddress((void**)&Q1,   d_Q1);
    cudaGetSymbolAddress((void**)&V1,   d_V1);
    cudaGetSymbolAddress((void**)&cat1, d_cat1);
    cudaGetSymbolAddress((void**)&q4,   d_q4);
    cudaGetSymbolAddress((void**)&k4,   d_k4);
    cudaGetSymbolAddress((void**)&v4,   d_v4);
    cudaGetSymbolAddress((void**)&cat4, d_cat4);
    cudaGetSymbolAddress((void**)&WT,   d_WT);

    transpose_all<<<dim3(8, 8, 7), dim3(16, 16)>>>(b1_Wq, b1_Wv, b1_Wo, b4_Wq, b4_Wk, b4_Wv, b4_Wo, WT);

    proj_batch<<<dim3(64, 4), 512>>>(q_emb, s_emb, know, WT,
                                     b1_bq, b1_bv, b4_bk, b4_bq,
                                     Q1, V1, k4, q4);

    attn1_kernel<<<dim3(Sx / 8, Hx, BSx), 256>>>(Q1, V1, b1_gam, qs_out, cat1);

    oproj_ln1_v4<<<256, 256>>>(cat1, WT + 2 * 16384, b1_bo, q_emb, b1_lng, b1_lnb,
                               WT + 5 * 16384, b4_bv, v4);

    attn4_kernel<<<dim3(BSx * NKx, Hx, 2), 256>>>(q4, k4, v4, b4_gam, ks_out, cat4);

    oproj_ln4_k<<<1024, 128>>>(cat4, WT + 6 * 16384, b4_bo, know, b4_lng, b4_lnb, z_out);
}